// round 7
// baseline (speedup 1.0000x reference)
#include <cuda_runtime.h>
#include <math.h>

#define N_ATOM  50000
#define M_NBR   12
#define N_ROW   600000
#define OFD     92
#define FDIM    64
#define EDIMM   41
#define NC_L    210
#define NC_H    256
#define UVS_L   420
#define UVS_H   512

// ---------------- scratch (device globals; no runtime allocation) ----------------
__device__ __align__(16) float  g_Y[(size_t)N_ROW * NC_H];
__device__ __align__(16) float  g_G[(size_t)N_ROW * EDIMM];
__device__ __align__(16) float  g_EDGE[(size_t)N_ROW * EDIMM];
__device__ __align__(16) float  g_NODE[N_ATOM * FDIM];
__device__ __align__(16) float  g_AGGR[N_ATOM * FDIM];
__device__ __align__(16) float  g_UV[(size_t)N_ATOM * UVS_H];
__device__ __align__(16) float  g_WP[FDIM * UVS_H];
__device__ __align__(16) float  g_BP[UVS_H];
__device__ __align__(16) float  g_EW[EDIMM * NC_H];
__device__ __align__(16) float  g_DIST[N_ROW];
__device__ double g_S[2 * NC_H];
__device__ double g_SA[2 * FDIM];
__device__ double g_SG[2 * EDIMM];
__device__ float  g_MEAN[NC_H], g_ISTD[NC_H];
__device__ float  g_MEANA[FDIM], g_ISTDA[FDIM];
__device__ float  g_MEANG[EDIMM], g_ISTDG[EDIMM];

__device__ __forceinline__ float lrelu(float x){ return x > 0.f ? x : 0.01f*x; }
__device__ __forceinline__ float sigm(float x){ return 1.f/(1.f + __expf(-x)); }
__device__ __forceinline__ float softplus(float x){ return fmaxf(x,0.f) + log1pf(__expf(-fabsf(x))); }

// ---------------- packed f32x2 helpers (sm_103a FFMA2 via PTX) ----------------
__device__ __forceinline__ unsigned long long pack_dup(float x){
    unsigned long long r; unsigned int xi = __float_as_uint(x);
    asm("mov.b64 %0, {%1, %1};" : "=l"(r) : "r"(xi));
    return r;
}
__device__ __forceinline__ unsigned long long pack2(float lo, float hi){
    unsigned long long r;
    asm("mov.b64 %0, {%1, %2};" : "=l"(r) : "r"(__float_as_uint(lo)), "r"(__float_as_uint(hi)));
    return r;
}
__device__ __forceinline__ void fma2(unsigned long long &d, unsigned long long a, unsigned long long b){
    asm("fma.rn.f32x2 %0, %1, %2, %0;" : "+l"(d) : "l"(a), "l"(b));
}
__device__ __forceinline__ float2 unpack2(unsigned long long v){
    unsigned int lo, hi;
    asm("mov.b64 {%0, %1}, %2;" : "=r"(lo), "=r"(hi) : "l"(v));
    float2 f; f.x = __uint_as_float(lo); f.y = __uint_as_float(hi); return f;
}

// ---------------- distance ----------------
__global__ void k_dist(const float* __restrict__ nbr, const float* __restrict__ pos,
                       const float* __restrict__ cells, const int* __restrict__ eidx)
{
    int r = blockIdx.x*blockDim.x + threadIdx.x;
    if (r >= N_ROW) return;
    int n = r / M_NBR;
    float o0=nbr[r*3], o1=nbr[r*3+1], o2=nbr[r*3+2];
    const float* c = cells + (size_t)n*9;
    int g = eidx[r];
    float dd = 1e-12f;
    #pragma unroll
    for (int j=0;j<3;j++){
        float off = o0*c[j] + o1*c[3+j] + o2*c[6+j];
        float d = pos[g*3+j] + off - pos[n*3+j];
        dd += d*d;
    }
    g_DIST[r] = sqrtf(dd);
}

// ---------------- embedding GEMM: g_NODE = node_fea @ W_emb + b_emb ----------------
__global__ void __launch_bounds__(256) k_gemm_emb(const float* __restrict__ A,
                                                  const float* __restrict__ B,
                                                  const float* __restrict__ bias,
                                                  int Nrows, int K, int Ncols)
{
    __shared__ float As[64*32];
    __shared__ float Bs[32*128];
    int tid = threadIdx.x;
    int colT = tid & 31, rowT = tid >> 5;
    int r0 = blockIdx.x*64;
    float acc[8][4];
    #pragma unroll
    for (int ri=0;ri<8;ri++)
        #pragma unroll
        for (int ci=0;ci<4;ci++) acc[ri][ci]=0.f;

    for (int k0=0;k0<K;k0+=32){
        for (int i=tid;i<64*32;i+=256){
            int rr=i>>5, kk=i&31; int gr=r0+rr, gk=k0+kk;
            As[i] = (gr<Nrows && gk<K)? A[(size_t)gr*K+gk] : 0.f;
        }
        for (int i=tid;i<32*128;i+=256){
            int kk=i>>7, jj=i&127; int gk=k0+kk;
            Bs[i] = (gk<K && jj<Ncols)? B[(size_t)gk*Ncols+jj] : 0.f;
        }
        __syncthreads();
        #pragma unroll 4
        for (int kk=0;kk<32;kk++){
            float a[8];
            #pragma unroll
            for (int ri=0;ri<8;ri++) a[ri]=As[(rowT+8*ri)*32+kk];
            #pragma unroll
            for (int ci=0;ci<4;ci++){
                float b=Bs[kk*128 + colT + 32*ci];
                #pragma unroll
                for (int ri=0;ri<8;ri++) acc[ri][ci] = fmaf(a[ri], b, acc[ri][ci]);
            }
        }
        __syncthreads();
    }
    #pragma unroll
    for (int ri=0;ri<8;ri++){
        int gr=r0+rowT+8*ri;
        if (gr >= Nrows) continue;
        #pragma unroll
        for (int ci=0;ci<4;ci++){
            int gj=colT+32*ci;
            if (gj < Ncols) g_NODE[(size_t)gr*Ncols+gj] = acc[ri][ci] + bias[gj];
        }
    }
}

// ---------------- UV GEMM (f32x2): g_UV = g_NODE(50000x64) @ g_WP + g_BP ----------------
__global__ void __launch_bounds__(256) k_gemm_uv(int Ncols)
{
    __shared__ __align__(16) float As[16][128];   // [k][m]
    __shared__ __align__(16) float Bs[16][128];   // [k][n]
    int tid = threadIdx.x;
    int tx = tid & 15, ty = tid >> 4;
    int r0 = blockIdx.x*128, c0 = blockIdx.y*128;
    unsigned long long acc2[8][4];
    #pragma unroll
    for (int i=0;i<8;i++)
        #pragma unroll
        for (int p=0;p<4;p++) acc2[i][p]=0ull;

    for (int k0=0;k0<FDIM;k0+=16){
        #pragma unroll
        for (int h=0;h<2;h++){
            int arow = (tid>>2) + h*64;
            int acol = (tid&3)*4;
            float4 v = make_float4(0.f,0.f,0.f,0.f);
            int gr = r0 + arow;
            if (gr < N_ATOM) v = *(const float4*)&g_NODE[(size_t)gr*FDIM + k0 + acol];
            As[acol+0][arow]=v.x; As[acol+1][arow]=v.y; As[acol+2][arow]=v.z; As[acol+3][arow]=v.w;
        }
        #pragma unroll
        for (int h=0;h<2;h++){
            int brow = (tid>>5) + h*8;
            int bcol = (tid&31)*4;
            float4 v = make_float4(0.f,0.f,0.f,0.f);
            if (c0 + bcol < Ncols) v = *(const float4*)&g_WP[(size_t)(k0+brow)*Ncols + c0 + bcol];
            *(float4*)&Bs[brow][bcol] = v;
        }
        __syncthreads();
        #pragma unroll
        for (int kk=0;kk<16;kk++){
            float a[8];
            *(float4*)&a[0] = *(const float4*)&As[kk][ty*8];
            *(float4*)&a[4] = *(const float4*)&As[kk][ty*8+4];
            unsigned long long bp[4];
            #pragma unroll
            for (int p=0;p<4;p++) bp[p] = *(const unsigned long long*)&Bs[kk][tx*8 + 2*p];
            #pragma unroll
            for (int i=0;i<8;i++){
                unsigned long long ap = pack_dup(a[i]);
                #pragma unroll
                for (int p=0;p<4;p++) fma2(acc2[i][p], ap, bp[p]);
            }
        }
        __syncthreads();
    }
    #pragma unroll
    for (int ri=0;ri<8;ri++){
        int gr = r0 + ty*8 + ri;
        if (gr >= N_ATOM) continue;
        #pragma unroll
        for (int cj=0;cj<2;cj++){
            int gj = c0 + tx*8 + cj*4;
            if (gj < Ncols){
                float4 bv = *(const float4*)&g_BP[gj];
                float2 v0 = unpack2(acc2[ri][cj*2+0]);
                float2 v1 = unpack2(acc2[ri][cj*2+1]);
                float4 o;
                o.x = v0.x + bv.x;
                o.y = v0.y + bv.y;
                o.z = v1.x + bv.z;
                o.w = v1.y + bv.w;
                *(float4*)&g_UV[(size_t)gr*Ncols + gj] = o;
            }
        }
    }
}

// ---------------- weight packing (+ stat zeroing) ----------------
__global__ void k_pack_layer(const float* __restrict__ Wn, const float* __restrict__ bn,
                             const float* __restrict__ We, const float* __restrict__ be)
{
    int stride = gridDim.x*blockDim.x;
    int t0 = blockIdx.x*blockDim.x + threadIdx.x;
    for (int idx=t0; idx<FDIM*UVS_L; idx+=stride){
        int k = idx / UVS_L, j = idx % UVS_L;
        float v;
        if (j<128)       v = Wn[k*128 + j];
        else if (j<256)  v = Wn[(64+k)*128 + (j-128)];
        else if (j<338)  v = We[k*82 + (j-256)];
        else             v = We[(64+k)*82 + (j-338)];
        g_WP[idx] = v;
    }
    for (int j=t0;j<UVS_L;j+=stride){
        float v = 0.f;
        if (j<128) v = bn[j];
        else if (j>=256 && j<338) v = be[j-256];
        g_BP[j]=v;
    }
    for (int idx=t0;idx<EDIMM*NC_L;idx+=stride){
        int k=idx/NC_L, j=idx%NC_L;
        g_EW[idx] = (j<128)? Wn[(128+k)*128 + j] : We[(128+k)*82 + (j-128)];
    }
    if (t0 < 2*NC_H)  g_S[t0]=0.0;
    if (t0 < 2*FDIM)  g_SA[t0]=0.0;
    if (t0 < 2*EDIMM) g_SG[t0]=0.0;
}

__global__ void k_pack_head(const float* __restrict__ Wd, const float* __restrict__ bd,
                            const float* __restrict__ Wc, const float* __restrict__ bc)
{
    int stride = gridDim.x*blockDim.x;
    int t0 = blockIdx.x*blockDim.x + threadIdx.x;
    for (int idx=t0; idx<FDIM*UVS_H; idx+=stride){
        int k = idx / UVS_H, j = idx % UVS_H;
        float v;
        if (j<128)       v = Wd[k*128 + j];
        else if (j<256)  v = Wd[(64+k)*128 + (j-128)];
        else if (j<384)  v = Wc[k*128 + (j-256)];
        else             v = Wc[(64+k)*128 + (j-384)];
        g_WP[idx] = v;
    }
    for (int j=t0;j<UVS_H;j+=stride){
        float v = 0.f;
        if (j<128) v = bd[j];
        else if (j>=256 && j<384) v = bc[j-256];
        g_BP[j]=v;
    }
    for (int idx=t0;idx<EDIMM*NC_H;idx+=stride){
        int k=idx/NC_H, j=idx%NC_H;
        g_EW[idx] = (j<128)? Wd[(128+k)*128 + j] : Wc[(128+k)*128 + (j-128)];
    }
    if (t0 < 2*NC_H) g_S[t0]=0.0;
}

// ---------------- pass1 v3 (f32x2, pair-packed, dup-E): Y = edge@EW + U[n] + V[g] ----------------
// Columns processed as adjacent pairs (2q, 2q+1), q = colT + 32*p, p in [0,4).
// TAILN>0: group p=3 valid only for colT < TAILN (NC_L: 9 pairs -> cols 192..209).
// Dynamic smem: [ sWp: EDIMM*128 u64 pairs ][ sE2: 40*EDIMM dup'd u64 ].
#define P1_TR   40
#define P1_DSMB ((EDIMM*128 + P1_TR*EDIMM)*8)

template<int NC, int TAILN>
__global__ void __launch_bounds__(256,2) k_pass1_t(const float* __restrict__ Ein, int useG,
                                                   const int* __restrict__ eidx, int uvS)
{
    extern __shared__ unsigned long long dsm[];
    unsigned long long* sWp = dsm;                  // [EDIMM][128] column-pairs
    unsigned long long* sE2 = dsm + EDIMM*128;      // [P1_TR][EDIMM] duplicated e
    const float* E = useG ? (const float*)g_EDGE : Ein;
    const int tid = threadIdx.x;
    const int colT = tid & 31, rowT = tid >> 5;

    // pack weights as adjacent column pairs, zero-padded to 128 pairs
    for (int idx = tid; idx < EDIMM*128; idx += 256){
        int k = idx >> 7, q = idx & 127;
        int j0 = 2*q;
        float lo = (j0   < NC) ? g_EW[k*NC + j0]     : 0.f;
        float hi = (j0+1 < NC) ? g_EW[k*NC + j0 + 1] : 0.f;
        sWp[idx] = pack2(lo, hi);
    }

    float s1[8], s2[8];
    #pragma unroll
    for (int ci=0;ci<8;ci++){ s1[ci]=0.f; s2[ci]=0.f; }

    const int nTiles = N_ROW / P1_TR;
    for (int t = blockIdx.x; t < nTiles; t += gridDim.x){
        int r0 = t*P1_TR;
        size_t base = (size_t)r0*EDIMM;
        __syncthreads();
        for (int i=tid; i<P1_TR*EDIMM; i+=256){
            float e = E[base + i];
            sE2[i] = pack_dup(e);
        }
        __syncthreads();

        unsigned long long acc2[5][4];
        #pragma unroll
        for (int ri=0;ri<5;ri++)
            #pragma unroll
            for (int p=0;p<4;p++) acc2[ri][p]=0ull;

        const unsigned long long* pE = sE2 + rowT*5*EDIMM;
        const unsigned long long* pW = sWp + colT;
        #pragma unroll 2
        for (int k=0;k<EDIMM;k++){
            unsigned long long evp[5];
            #pragma unroll
            for (int ri=0;ri<5;ri++) evp[ri] = pE[ri*EDIMM + k];
            unsigned long long wp[4];
            #pragma unroll
            for (int p=0;p<3;p++) wp[p] = pW[k*128 + 32*p];
            if (TAILN==0 || colT < TAILN) wp[3] = pW[k*128 + 96];
            #pragma unroll
            for (int p=0;p<3;p++)
                #pragma unroll
                for (int ri=0;ri<5;ri++) fma2(acc2[ri][p], evp[ri], wp[p]);
            if (TAILN==0 || colT < TAILN){
                #pragma unroll
                for (int ri=0;ri<5;ri++) fma2(acc2[ri][3], evp[ri], wp[3]);
            }
        }
        #pragma unroll
        for (int ri=0;ri<5;ri++){
            int row = r0 + rowT*5 + ri;
            int n  = row / M_NBR;
            int gg = __ldg(&eidx[row]);
            const float* Un = g_UV + (size_t)n*uvS;
            const float* Vg = g_UV + (size_t)gg*uvS;
            float* yp = g_Y + (size_t)row*NC;
            #pragma unroll
            for (int p=0;p<4;p++){
                if (TAILN==0 || p<3 || colT < TAILN){
                    int j0 = 2*(colT + 32*p);
                    float2 y2 = unpack2(acc2[ri][p]);
                    int uc = (j0<128)? j0        : j0+128;
                    int vc = (j0<128)? (j0+128)  : j0+NC;
                    float2 u2 = *(const float2*)&Un[uc];
                    float2 v2 = *(const float2*)&Vg[vc];
                    float y0 = y2.x + u2.x + v2.x;
                    float y1 = y2.y + u2.y + v2.y;
                    float2 yo; yo.x=y0; yo.y=y1;
                    *(float2*)&yp[j0] = yo;
                    s1[2*p]   += y0; s2[2*p]   += y0*y0;
                    s1[2*p+1] += y1; s2[2*p+1] += y1*y1;
                }
            }
        }
    }
    __syncthreads();
    float* red = (float*)sE2;
    #pragma unroll 1
    for (int ci=0;ci<8;ci++){
        red[tid] = s1[ci];
        red[256+tid] = s2[ci];
        __syncthreads();
        if (tid < 32){
            float a=0.f, b=0.f;
            #pragma unroll
            for (int w=0;w<8;w++){ a += red[w*32+tid]; b += red[256+w*32+tid]; }
            int j = 2*(tid + 32*(ci>>1)) + (ci&1);
            if (j < NC){
                atomicAdd(&g_S[j],    (double)a);
                atomicAdd(&g_S[NC+j], (double)b);
            }
        }
        __syncthreads();
    }
}

// ---------------- finalize stats ----------------
__global__ void k_finalize0(int C, double invCnt)
{
    int t = threadIdx.x + blockIdx.x*blockDim.x;
    if (t >= C) return;
    double m = g_S[t]*invCnt;
    double v = g_S[C+t]*invCnt - m*m;
    g_MEAN[t] = (float)m;
    g_ISTD[t] = rsqrtf((float)v + 1e-5f);
}

__global__ void k_finalize12()
{
    int t = threadIdx.x;
    if (t < FDIM){
        double m = g_SA[t] * (1.0/(double)N_ATOM);
        double v = g_SA[FDIM+t] * (1.0/(double)N_ATOM) - m*m;
        g_MEANA[t] = (float)m;
        g_ISTDA[t] = rsqrtf((float)v + 1e-5f);
    } else if (t >= 64 && t < 64+EDIMM){
        int c = t-64;
        double m = g_SG[c] * (1.0/(double)N_ROW);
        double v = g_SG[EDIMM+c] * (1.0/(double)N_ROW) - m*m;
        g_MEANG[c] = (float)m;
        g_ISTDG[c] = rsqrtf((float)v + 1e-5f);
    }
}

// ---------------- pass2 (layer) ----------------
__global__ void __launch_bounds__(128) k_pass2_layer()
{
    int t = threadIdx.x;
    bool isNode = t < 64;
    bool isEdge = (t >= 64 && t < 105);
    float m1=0.f,i1=0.f,m2=0.f,i2=0.f;
    int c = 0;
    if (isNode){ c=t;    m1=g_MEAN[c];     i1=g_ISTD[c];     m2=g_MEAN[64+c];  i2=g_ISTD[64+c]; }
    else if (isEdge){ c=t-64; m1=g_MEAN[128+c]; i1=g_ISTD[128+c]; m2=g_MEAN[169+c]; i2=g_ISTD[169+c]; }
    float st1=0.f, st2=0.f;
    for (int n = blockIdx.x; n < N_ATOM; n += gridDim.x){
        if (isNode){
            float a = 0.f;
            #pragma unroll
            for (int m=0;m<M_NBR;m++){
                size_t row = (size_t)(n*M_NBR+m);
                float y1 = (g_Y[row*NC_L + c]      - m1)*i1;
                float y2 = (g_Y[row*NC_L + 64 + c] - m2)*i2;
                a += sigm(y1)*lrelu(y2);
            }
            g_AGGR[n*64 + c] = a;
            st1 += a; st2 += a*a;
        } else if (isEdge){
            #pragma unroll
            for (int m=0;m<M_NBR;m++){
                size_t row = (size_t)(n*M_NBR+m);
                float y1 = (g_Y[row*NC_L + 128 + c] - m1)*i1;
                float y2 = (g_Y[row*NC_L + 169 + c] - m2)*i2;
                float gv = sigm(y1)*lrelu(y2);
                g_G[row*EDIMM + c] = gv;
                st1 += gv; st2 += gv*gv;
            }
        }
    }
    if (isNode){ atomicAdd(&g_SA[c], (double)st1); atomicAdd(&g_SA[64+c], (double)st2); }
    else if (isEdge){ atomicAdd(&g_SG[c], (double)st1); atomicAdd(&g_SG[41+c], (double)st2); }
}

__global__ void k_node_update()
{
    int idx = blockIdx.x*blockDim.x + threadIdx.x;
    if (idx >= N_ATOM*FDIM) return;
    int c = idx & 63;
    float v = g_NODE[idx] + (g_AGGR[idx] - g_MEANA[c]) * g_ISTDA[c];
    g_NODE[idx] = lrelu(v);
}

__global__ void k_edge_update(const float* __restrict__ Ein, int useG)
{
    size_t idx = (size_t)blockIdx.x*blockDim.x + threadIdx.x;
    if (idx >= (size_t)N_ROW*EDIMM) return;
    int c = (int)(idx % EDIMM);
    float e = useG ? g_EDGE[idx] : Ein[idx];
    float v = e + (g_G[idx] - g_MEANG[c]) * g_ISTDG[c];
    g_EDGE[idx] = lrelu(v);
}

// ---------------- pass2 (head) ----------------
__global__ void __launch_bounds__(256) k_pass2_head(float* __restrict__ out)
{
    int warp = threadIdx.x >> 5, lane = threadIdx.x & 31;
    size_t r = (size_t)blockIdx.x*8 + warp;
    if (r >= N_ROW) return;
    float dist = g_DIST[r];
    float bd = 0.f, bc = 0.f;
    const float* y = g_Y + r*NC_H;
    #pragma unroll
    for (int i=0;i<8;i++){
        int cidx = lane + 32*i;
        float v = (y[cidx] - g_MEAN[cidx]) * g_ISTD[cidx];
        if (i < 4) bd += softplus(v + dist);
        else       bc += softplus(v);
    }
    #pragma unroll
    for (int o=16;o>0;o>>=1){
        bd += __shfl_down_sync(0xffffffffu, bd, o);
        bc += __shfl_down_sync(0xffffffffu, bc, o);
    }
    if (lane==0){
        out[r*2]   = bd * (1.f/128.f);
        out[r*2+1] = bc * (1.f/128.f) * (1.f/(float)N_ATOM);
    }
}

// ---------------- host orchestration ----------------
extern "C" void kernel_launch(void* const* d_in, const int* in_sizes, int n_in,
                              void* d_out, int out_size)
{
    const float* node_fea = (const float*)d_in[0];
    const float* edge_fea = (const float*)d_in[1];
    const float* nbr_off  = (const float*)d_in[2];
    const float* atom_pos = (const float*)d_in[3];
    const float* cells    = (const float*)d_in[4];
    const int*   eidx     = (const int*)  d_in[5];
    const float* W_emb = (const float*)d_in[6];
    const float* b_emb = (const float*)d_in[7];
    const float* W_pn  = (const float*)d_in[8];
    const float* b_pn  = (const float*)d_in[9];
    const float* W_pe  = (const float*)d_in[10];
    const float* b_pe  = (const float*)d_in[11];
    const float* W_d   = (const float*)d_in[12];
    const float* b_d   = (const float*)d_in[13];
    const float* W_c   = (const float*)d_in[14];
    const float* b_c   = (const float*)d_in[15];
    float* out = (float*)d_out;

    // opt-in to >48KB dynamic shared memory for pass1 (idempotent, capture-legal)
    cudaFuncSetAttribute(k_pass1_t<NC_L,9>, cudaFuncAttributeMaxDynamicSharedMemorySize, P1_DSMB);
    cudaFuncSetAttribute(k_pass1_t<NC_H,0>, cudaFuncAttributeMaxDynamicSharedMemorySize, P1_DSMB);

    k_dist<<<(N_ROW+255)/256, 256>>>(nbr_off, atom_pos, cells, eidx);
    k_gemm_emb<<<(N_ATOM+63)/64, 256>>>(node_fea, W_emb, b_emb, N_ATOM, OFD, FDIM);

    for (int l=0;l<3;l++){
        int useG = (l>0) ? 1 : 0;
        k_pack_layer<<<64,256>>>(W_pn + (size_t)l*169*128, b_pn + l*128,
                                 W_pe + (size_t)l*169*82,  b_pe + l*82);
        k_gemm_uv<<<dim3((N_ATOM+127)/128, (UVS_L+127)/128), 256>>>(UVS_L);
        k_pass1_t<NC_L,9><<<1184,256,P1_DSMB>>>(edge_fea, useG, eidx, UVS_L);
        k_finalize0<<<1,256>>>(NC_L, 1.0/(double)N_ROW);
        k_pass2_layer<<<2368,128>>>();
        k_finalize12<<<1,128>>>();
        k_node_update<<<(N_ATOM*FDIM+255)/256,256>>>();
        k_edge_update<<<(int)(((size_t)N_ROW*EDIMM+255)/256),256>>>(edge_fea, useG);
    }

    k_pack_head<<<64,256>>>(W_d, b_d, W_c, b_c);
    k_gemm_uv<<<dim3((N_ATOM+127)/128, (UVS_H+127)/128), 256>>>(UVS_H);
    k_pass1_t<NC_H,0><<<1184,256,P1_DSMB>>>(edge_fea, 1, eidx, UVS_H);
    k_finalize0<<<1,256>>>(NC_H, 1.0/(double)N_ROW);
    k_pass2_head<<<(int)((N_ROW+7)/8), 256>>>(out);
}

// round 8
// speedup vs baseline: 1.0187x; 1.0187x over previous
#include <cuda_runtime.h>
#include <math.h>

#define N_ATOM  50000
#define M_NBR   12
#define N_ROW   600000
#define OFD     92
#define FDIM    64
#define EDIMM   41
#define NC_L    210
#define NC_H    256
#define UVS_L   420
#define UVS_H   512

// ---------------- scratch (device globals; no runtime allocation) ----------------
__device__ __align__(16) float  g_Y[(size_t)N_ROW * NC_H];
__device__ __align__(16) float  g_G[(size_t)N_ROW * EDIMM];
__device__ __align__(16) float  g_EDGE[(size_t)N_ROW * EDIMM];
__device__ __align__(16) float  g_NODE[N_ATOM * FDIM];
__device__ __align__(16) float  g_AGGR[N_ATOM * FDIM];
__device__ __align__(16) float  g_UV[(size_t)N_ATOM * UVS_H];
__device__ __align__(16) float  g_WP[FDIM * UVS_H];
__device__ __align__(16) float  g_BP[UVS_H];
__device__ __align__(16) float  g_EW[EDIMM * NC_H];
__device__ __align__(16) float  g_DIST[N_ROW];
__device__ double g_S[2 * NC_H];
__device__ double g_SA[2 * FDIM];
__device__ double g_SG[2 * EDIMM];
__device__ float  g_MEAN[NC_H], g_ISTD[NC_H];
__device__ float  g_MEANA[FDIM], g_ISTDA[FDIM];
__device__ float  g_MEANG[EDIMM], g_ISTDG[EDIMM];

__device__ __forceinline__ float lrelu(float x){ return x > 0.f ? x : 0.01f*x; }
__device__ __forceinline__ float sigm(float x){ return 1.f/(1.f + __expf(-x)); }
__device__ __forceinline__ float softplus(float x){ return fmaxf(x,0.f) + log1pf(__expf(-fabsf(x))); }

// ---------------- packed f32x2 helpers (sm_103a FFMA2 via PTX) ----------------
__device__ __forceinline__ unsigned long long pack_dup(float x){
    unsigned long long r; unsigned int xi = __float_as_uint(x);
    asm("mov.b64 %0, {%1, %1};" : "=l"(r) : "r"(xi));
    return r;
}
__device__ __forceinline__ unsigned long long pack2(float lo, float hi){
    unsigned long long r;
    asm("mov.b64 %0, {%1, %2};" : "=l"(r) : "r"(__float_as_uint(lo)), "r"(__float_as_uint(hi)));
    return r;
}
__device__ __forceinline__ void fma2(unsigned long long &d, unsigned long long a, unsigned long long b){
    asm("fma.rn.f32x2 %0, %1, %2, %0;" : "+l"(d) : "l"(a), "l"(b));
}
__device__ __forceinline__ float2 unpack2(unsigned long long v){
    unsigned int lo, hi;
    asm("mov.b64 {%0, %1}, %2;" : "=r"(lo), "=r"(hi) : "l"(v));
    float2 f; f.x = __uint_as_float(lo); f.y = __uint_as_float(hi); return f;
}

// ---------------- distance ----------------
__global__ void k_dist(const float* __restrict__ nbr, const float* __restrict__ pos,
                       const float* __restrict__ cells, const int* __restrict__ eidx)
{
    int r = blockIdx.x*blockDim.x + threadIdx.x;
    if (r >= N_ROW) return;
    int n = r / M_NBR;
    float o0=nbr[r*3], o1=nbr[r*3+1], o2=nbr[r*3+2];
    const float* c = cells + (size_t)n*9;
    int g = eidx[r];
    float dd = 1e-12f;
    #pragma unroll
    for (int j=0;j<3;j++){
        float off = o0*c[j] + o1*c[3+j] + o2*c[6+j];
        float d = pos[g*3+j] + off - pos[n*3+j];
        dd += d*d;
    }
    g_DIST[r] = sqrtf(dd);
}

// ---------------- embedding GEMM: g_NODE = node_fea @ W_emb + b_emb ----------------
__global__ void __launch_bounds__(256) k_gemm_emb(const float* __restrict__ A,
                                                  const float* __restrict__ B,
                                                  const float* __restrict__ bias,
                                                  int Nrows, int K, int Ncols)
{
    __shared__ float As[64*32];
    __shared__ float Bs[32*128];
    int tid = threadIdx.x;
    int colT = tid & 31, rowT = tid >> 5;
    int r0 = blockIdx.x*64;
    float acc[8][4];
    #pragma unroll
    for (int ri=0;ri<8;ri++)
        #pragma unroll
        for (int ci=0;ci<4;ci++) acc[ri][ci]=0.f;

    for (int k0=0;k0<K;k0+=32){
        for (int i=tid;i<64*32;i+=256){
            int rr=i>>5, kk=i&31; int gr=r0+rr, gk=k0+kk;
            As[i] = (gr<Nrows && gk<K)? A[(size_t)gr*K+gk] : 0.f;
        }
        for (int i=tid;i<32*128;i+=256){
            int kk=i>>7, jj=i&127; int gk=k0+kk;
            Bs[i] = (gk<K && jj<Ncols)? B[(size_t)gk*Ncols+jj] : 0.f;
        }
        __syncthreads();
        #pragma unroll 4
        for (int kk=0;kk<32;kk++){
            float a[8];
            #pragma unroll
            for (int ri=0;ri<8;ri++) a[ri]=As[(rowT+8*ri)*32+kk];
            #pragma unroll
            for (int ci=0;ci<4;ci++){
                float b=Bs[kk*128 + colT + 32*ci];
                #pragma unroll
                for (int ri=0;ri<8;ri++) acc[ri][ci] = fmaf(a[ri], b, acc[ri][ci]);
            }
        }
        __syncthreads();
    }
    #pragma unroll
    for (int ri=0;ri<8;ri++){
        int gr=r0+rowT+8*ri;
        if (gr >= Nrows) continue;
        #pragma unroll
        for (int ci=0;ci<4;ci++){
            int gj=colT+32*ci;
            if (gj < Ncols) g_NODE[(size_t)gr*Ncols+gj] = acc[ri][ci] + bias[gj];
        }
    }
}

// ---------------- UV GEMM (f32x2): g_UV = g_NODE(50000x64) @ g_WP + g_BP ----------------
__global__ void __launch_bounds__(256) k_gemm_uv(int Ncols)
{
    __shared__ __align__(16) float As[16][128];   // [k][m]
    __shared__ __align__(16) float Bs[16][128];   // [k][n]
    int tid = threadIdx.x;
    int tx = tid & 15, ty = tid >> 4;
    int r0 = blockIdx.x*128, c0 = blockIdx.y*128;
    unsigned long long acc2[8][4];
    #pragma unroll
    for (int i=0;i<8;i++)
        #pragma unroll
        for (int p=0;p<4;p++) acc2[i][p]=0ull;

    for (int k0=0;k0<FDIM;k0+=16){
        #pragma unroll
        for (int h=0;h<2;h++){
            int arow = (tid>>2) + h*64;
            int acol = (tid&3)*4;
            float4 v = make_float4(0.f,0.f,0.f,0.f);
            int gr = r0 + arow;
            if (gr < N_ATOM) v = *(const float4*)&g_NODE[(size_t)gr*FDIM + k0 + acol];
            As[acol+0][arow]=v.x; As[acol+1][arow]=v.y; As[acol+2][arow]=v.z; As[acol+3][arow]=v.w;
        }
        #pragma unroll
        for (int h=0;h<2;h++){
            int brow = (tid>>5) + h*8;
            int bcol = (tid&31)*4;
            float4 v = make_float4(0.f,0.f,0.f,0.f);
            if (c0 + bcol < Ncols) v = *(const float4*)&g_WP[(size_t)(k0+brow)*Ncols + c0 + bcol];
            *(float4*)&Bs[brow][bcol] = v;
        }
        __syncthreads();
        #pragma unroll
        for (int kk=0;kk<16;kk++){
            float a[8];
            *(float4*)&a[0] = *(const float4*)&As[kk][ty*8];
            *(float4*)&a[4] = *(const float4*)&As[kk][ty*8+4];
            unsigned long long bp[4];
            #pragma unroll
            for (int p=0;p<4;p++) bp[p] = *(const unsigned long long*)&Bs[kk][tx*8 + 2*p];
            #pragma unroll
            for (int i=0;i<8;i++){
                unsigned long long ap = pack_dup(a[i]);
                #pragma unroll
                for (int p=0;p<4;p++) fma2(acc2[i][p], ap, bp[p]);
            }
        }
        __syncthreads();
    }
    #pragma unroll
    for (int ri=0;ri<8;ri++){
        int gr = r0 + ty*8 + ri;
        if (gr >= N_ATOM) continue;
        #pragma unroll
        for (int cj=0;cj<2;cj++){
            int gj = c0 + tx*8 + cj*4;
            if (gj < Ncols){
                float4 bv = *(const float4*)&g_BP[gj];
                float2 v0 = unpack2(acc2[ri][cj*2+0]);
                float2 v1 = unpack2(acc2[ri][cj*2+1]);
                float4 o;
                o.x = v0.x + bv.x;
                o.y = v0.y + bv.y;
                o.z = v1.x + bv.z;
                o.w = v1.y + bv.w;
                *(float4*)&g_UV[(size_t)gr*Ncols + gj] = o;
            }
        }
    }
}

// ---------------- weight packing (+ stat zeroing) ----------------
__global__ void k_pack_layer(const float* __restrict__ Wn, const float* __restrict__ bn,
                             const float* __restrict__ We, const float* __restrict__ be)
{
    int stride = gridDim.x*blockDim.x;
    int t0 = blockIdx.x*blockDim.x + threadIdx.x;
    for (int idx=t0; idx<FDIM*UVS_L; idx+=stride){
        int k = idx / UVS_L, j = idx % UVS_L;
        float v;
        if (j<128)       v = Wn[k*128 + j];
        else if (j<256)  v = Wn[(64+k)*128 + (j-128)];
        else if (j<338)  v = We[k*82 + (j-256)];
        else             v = We[(64+k)*82 + (j-338)];
        g_WP[idx] = v;
    }
    for (int j=t0;j<UVS_L;j+=stride){
        float v = 0.f;
        if (j<128) v = bn[j];
        else if (j>=256 && j<338) v = be[j-256];
        g_BP[j]=v;
    }
    for (int idx=t0;idx<EDIMM*NC_L;idx+=stride){
        int k=idx/NC_L, j=idx%NC_L;
        g_EW[idx] = (j<128)? Wn[(128+k)*128 + j] : We[(128+k)*82 + (j-128)];
    }
    if (t0 < 2*NC_H)  g_S[t0]=0.0;
    if (t0 < 2*FDIM)  g_SA[t0]=0.0;
    if (t0 < 2*EDIMM) g_SG[t0]=0.0;
}

__global__ void k_pack_head(const float* __restrict__ Wd, const float* __restrict__ bd,
                            const float* __restrict__ Wc, const float* __restrict__ bc)
{
    int stride = gridDim.x*blockDim.x;
    int t0 = blockIdx.x*blockDim.x + threadIdx.x;
    for (int idx=t0; idx<FDIM*UVS_H; idx+=stride){
        int k = idx / UVS_H, j = idx % UVS_H;
        float v;
        if (j<128)       v = Wd[k*128 + j];
        else if (j<256)  v = Wd[(64+k)*128 + (j-128)];
        else if (j<384)  v = Wc[k*128 + (j-256)];
        else             v = Wc[(64+k)*128 + (j-384)];
        g_WP[idx] = v;
    }
    for (int j=t0;j<UVS_H;j+=stride){
        float v = 0.f;
        if (j<128) v = bd[j];
        else if (j>=256 && j<384) v = bc[j-256];
        g_BP[j]=v;
    }
    for (int idx=t0;idx<EDIMM*NC_H;idx+=stride){
        int k=idx/NC_H, j=idx%NC_H;
        g_EW[idx] = (j<128)? Wd[(128+k)*128 + j] : Wc[(128+k)*128 + (j-128)];
    }
    if (t0 < 2*NC_H) g_S[t0]=0.0;
}

// ---------------- pass1 v4 (f32x2, adjacent pairs, dup-E, BRANCH-FREE inner loop) ----------------
// Columns as adjacent pairs (2q, 2q+1), q = colT + 32*p, p in [0,4).
// Weights zero-padded to 128 pairs, so group p=3 runs unconditionally (zeros for
// invalid lanes); only the epilogue (C++ loads/stores, predicable) is guarded.
// Dynamic smem: [ sWp: EDIMM*128 u64 pairs ][ sE2: 40*EDIMM dup'd u64 ].
#define P1_TR   40
#define P1_DSMB ((EDIMM*128 + P1_TR*EDIMM)*8)

template<int NC, int TAILN>
__global__ void __launch_bounds__(256,2) k_pass1_t(const float* __restrict__ Ein, int useG,
                                                   const int* __restrict__ eidx, int uvS)
{
    extern __shared__ unsigned long long dsm[];
    unsigned long long* sWp = dsm;                  // [EDIMM][128] column-pairs
    unsigned long long* sE2 = dsm + EDIMM*128;      // [P1_TR][EDIMM] duplicated e
    const float* E = useG ? (const float*)g_EDGE : Ein;
    const int tid = threadIdx.x;
    const int colT = tid & 31, rowT = tid >> 5;

    // pack weights as adjacent column pairs, zero-padded to 128 pairs
    for (int idx = tid; idx < EDIMM*128; idx += 256){
        int k = idx >> 7, q = idx & 127;
        int j0 = 2*q;
        float lo = (j0   < NC) ? g_EW[k*NC + j0]     : 0.f;
        float hi = (j0+1 < NC) ? g_EW[k*NC + j0 + 1] : 0.f;
        sWp[idx] = pack2(lo, hi);
    }

    float s1[8], s2[8];
    #pragma unroll
    for (int ci=0;ci<8;ci++){ s1[ci]=0.f; s2[ci]=0.f; }

    const int nTiles = N_ROW / P1_TR;
    for (int t = blockIdx.x; t < nTiles; t += gridDim.x){
        int r0 = t*P1_TR;
        size_t base = (size_t)r0*EDIMM;
        __syncthreads();
        for (int i=tid; i<P1_TR*EDIMM; i+=256){
            float e = E[base + i];
            sE2[i] = pack_dup(e);
        }
        __syncthreads();

        unsigned long long acc2[5][4];
        #pragma unroll
        for (int ri=0;ri<5;ri++)
            #pragma unroll
            for (int p=0;p<4;p++) acc2[ri][p]=0ull;

        const unsigned long long* pE = sE2 + rowT*5*EDIMM;
        const unsigned long long* pW = sWp + colT;
        #pragma unroll 2
        for (int k=0;k<EDIMM;k++){
            unsigned long long evp[5];
            #pragma unroll
            for (int ri=0;ri<5;ri++) evp[ri] = pE[ri*EDIMM + k];
            unsigned long long wp[4];
            #pragma unroll
            for (int p=0;p<4;p++) wp[p] = pW[k*128 + 32*p];
            #pragma unroll
            for (int p=0;p<4;p++)
                #pragma unroll
                for (int ri=0;ri<5;ri++) fma2(acc2[ri][p], evp[ri], wp[p]);
        }
        #pragma unroll
        for (int ri=0;ri<5;ri++){
            int row = r0 + rowT*5 + ri;
            int n  = row / M_NBR;
            int gg = __ldg(&eidx[row]);
            const float* Un = g_UV + (size_t)n*uvS;
            const float* Vg = g_UV + (size_t)gg*uvS;
            float* yp = g_Y + (size_t)row*NC;
            #pragma unroll
            for (int p=0;p<4;p++){
                if (TAILN==0 || p<3 || colT < TAILN){
                    int j0 = 2*(colT + 32*p);
                    float2 y2 = unpack2(acc2[ri][p]);
                    int uc = (j0<128)? j0        : j0+128;
                    int vc = (j0<128)? (j0+128)  : j0+NC;
                    float2 u2 = *(const float2*)&Un[uc];
                    float2 v2 = *(const float2*)&Vg[vc];
                    float y0 = y2.x + u2.x + v2.x;
                    float y1 = y2.y + u2.y + v2.y;
                    float2 yo; yo.x=y0; yo.y=y1;
                    *(float2*)&yp[j0] = yo;
                    s1[2*p]   += y0; s2[2*p]   += y0*y0;
                    s1[2*p+1] += y1; s2[2*p+1] += y1*y1;
                }
            }
        }
    }
    __syncthreads();
    float* red = (float*)sE2;
    #pragma unroll 1
    for (int ci=0;ci<8;ci++){
        red[tid] = s1[ci];
        red[256+tid] = s2[ci];
        __syncthreads();
        if (tid < 32){
            float a=0.f, b=0.f;
            #pragma unroll
            for (int w=0;w<8;w++){ a += red[w*32+tid]; b += red[256+w*32+tid]; }
            int j = 2*(tid + 32*(ci>>1)) + (ci&1);
            if (j < NC){
                atomicAdd(&g_S[j],    (double)a);
                atomicAdd(&g_S[NC+j], (double)b);
            }
        }
        __syncthreads();
    }
}

// ---------------- finalize stats ----------------
__global__ void k_finalize0(int C, double invCnt)
{
    int t = threadIdx.x + blockIdx.x*blockDim.x;
    if (t >= C) return;
    double m = g_S[t]*invCnt;
    double v = g_S[C+t]*invCnt - m*m;
    g_MEAN[t] = (float)m;
    g_ISTD[t] = rsqrtf((float)v + 1e-5f);
}

__global__ void k_finalize12()
{
    int t = threadIdx.x;
    if (t < FDIM){
        double m = g_SA[t] * (1.0/(double)N_ATOM);
        double v = g_SA[FDIM+t] * (1.0/(double)N_ATOM) - m*m;
        g_MEANA[t] = (float)m;
        g_ISTDA[t] = rsqrtf((float)v + 1e-5f);
    } else if (t >= 64 && t < 64+EDIMM){
        int c = t-64;
        double m = g_SG[c] * (1.0/(double)N_ROW);
        double v = g_SG[EDIMM+c] * (1.0/(double)N_ROW) - m*m;
        g_MEANG[c] = (float)m;
        g_ISTDG[c] = rsqrtf((float)v + 1e-5f);
    }
}

// ---------------- pass2 (layer) ----------------
__global__ void __launch_bounds__(128) k_pass2_layer()
{
    int t = threadIdx.x;
    bool isNode = t < 64;
    bool isEdge = (t >= 64 && t < 105);
    float m1=0.f,i1=0.f,m2=0.f,i2=0.f;
    int c = 0;
    if (isNode){ c=t;    m1=g_MEAN[c];     i1=g_ISTD[c];     m2=g_MEAN[64+c];  i2=g_ISTD[64+c]; }
    else if (isEdge){ c=t-64; m1=g_MEAN[128+c]; i1=g_ISTD[128+c]; m2=g_MEAN[169+c]; i2=g_ISTD[169+c]; }
    float st1=0.f, st2=0.f;
    for (int n = blockIdx.x; n < N_ATOM; n += gridDim.x){
        if (isNode){
            float a = 0.f;
            #pragma unroll
            for (int m=0;m<M_NBR;m++){
                size_t row = (size_t)(n*M_NBR+m);
                float y1 = (g_Y[row*NC_L + c]      - m1)*i1;
                float y2 = (g_Y[row*NC_L + 64 + c] - m2)*i2;
                a += sigm(y1)*lrelu(y2);
            }
            g_AGGR[n*64 + c] = a;
            st1 += a; st2 += a*a;
        } else if (isEdge){
            #pragma unroll
            for (int m=0;m<M_NBR;m++){
                size_t row = (size_t)(n*M_NBR+m);
                float y1 = (g_Y[row*NC_L + 128 + c] - m1)*i1;
                float y2 = (g_Y[row*NC_L + 169 + c] - m2)*i2;
                float gv = sigm(y1)*lrelu(y2);
                g_G[row*EDIMM + c] = gv;
                st1 += gv; st2 += gv*gv;
            }
        }
    }
    if (isNode){ atomicAdd(&g_SA[c], (double)st1); atomicAdd(&g_SA[64+c], (double)st2); }
    else if (isEdge){ atomicAdd(&g_SG[c], (double)st1); atomicAdd(&g_SG[41+c], (double)st2); }
}

__global__ void k_node_update()
{
    int idx = blockIdx.x*blockDim.x + threadIdx.x;
    if (idx >= N_ATOM*FDIM) return;
    int c = idx & 63;
    float v = g_NODE[idx] + (g_AGGR[idx] - g_MEANA[c]) * g_ISTDA[c];
    g_NODE[idx] = lrelu(v);
}

__global__ void k_edge_update(const float* __restrict__ Ein, int useG)
{
    size_t idx = (size_t)blockIdx.x*blockDim.x + threadIdx.x;
    if (idx >= (size_t)N_ROW*EDIMM) return;
    int c = (int)(idx % EDIMM);
    float e = useG ? g_EDGE[idx] : Ein[idx];
    float v = e + (g_G[idx] - g_MEANG[c]) * g_ISTDG[c];
    g_EDGE[idx] = lrelu(v);
}

// ---------------- pass2 (head) ----------------
__global__ void __launch_bounds__(256) k_pass2_head(float* __restrict__ out)
{
    int warp = threadIdx.x >> 5, lane = threadIdx.x & 31;
    size_t r = (size_t)blockIdx.x*8 + warp;
    if (r >= N_ROW) return;
    float dist = g_DIST[r];
    float bd = 0.f, bc = 0.f;
    const float* y = g_Y + r*NC_H;
    #pragma unroll
    for (int i=0;i<8;i++){
        int cidx = lane + 32*i;
        float v = (y[cidx] - g_MEAN[cidx]) * g_ISTD[cidx];
        if (i < 4) bd += softplus(v + dist);
        else       bc += softplus(v);
    }
    #pragma unroll
    for (int o=16;o>0;o>>=1){
        bd += __shfl_down_sync(0xffffffffu, bd, o);
        bc += __shfl_down_sync(0xffffffffu, bc, o);
    }
    if (lane==0){
        out[r*2]   = bd * (1.f/128.f);
        out[r*2+1] = bc * (1.f/128.f) * (1.f/(float)N_ATOM);
    }
}

// ---------------- host orchestration ----------------
extern "C" void kernel_launch(void* const* d_in, const int* in_sizes, int n_in,
                              void* d_out, int out_size)
{
    const float* node_fea = (const float*)d_in[0];
    const float* edge_fea = (const float*)d_in[1];
    const float* nbr_off  = (const float*)d_in[2];
    const float* atom_pos = (const float*)d_in[3];
    const float* cells    = (const float*)d_in[4];
    const int*   eidx     = (const int*)  d_in[5];
    const float* W_emb = (const float*)d_in[6];
    const float* b_emb = (const float*)d_in[7];
    const float* W_pn  = (const float*)d_in[8];
    const float* b_pn  = (const float*)d_in[9];
    const float* W_pe  = (const float*)d_in[10];
    const float* b_pe  = (const float*)d_in[11];
    const float* W_d   = (const float*)d_in[12];
    const float* b_d   = (const float*)d_in[13];
    const float* W_c   = (const float*)d_in[14];
    const float* b_c   = (const float*)d_in[15];
    float* out = (float*)d_out;

    // opt-in to >48KB dynamic shared memory for pass1 (idempotent, capture-legal)
    cudaFuncSetAttribute(k_pass1_t<NC_L,9>, cudaFuncAttributeMaxDynamicSharedMemorySize, P1_DSMB);
    cudaFuncSetAttribute(k_pass1_t<NC_H,0>, cudaFuncAttributeMaxDynamicSharedMemorySize, P1_DSMB);

    k_dist<<<(N_ROW+255)/256, 256>>>(nbr_off, atom_pos, cells, eidx);
    k_gemm_emb<<<(N_ATOM+63)/64, 256>>>(node_fea, W_emb, b_emb, N_ATOM, OFD, FDIM);

    for (int l=0;l<3;l++){
        int useG = (l>0) ? 1 : 0;
        k_pack_layer<<<64,256>>>(W_pn + (size_t)l*169*128, b_pn + l*128,
                                 W_pe + (size_t)l*169*82,  b_pe + l*82);
        k_gemm_uv<<<dim3((N_ATOM+127)/128, (UVS_L+127)/128), 256>>>(UVS_L);
        k_pass1_t<NC_L,9><<<1184,256,P1_DSMB>>>(edge_fea, useG, eidx, UVS_L);
        k_finalize0<<<1,256>>>(NC_L, 1.0/(double)N_ROW);
        k_pass2_layer<<<2368,128>>>();
        k_finalize12<<<1,128>>>();
        k_node_update<<<(N_ATOM*FDIM+255)/256,256>>>();
        k_edge_update<<<(int)(((size_t)N_ROW*EDIMM+255)/256),256>>>(edge_fea, useG);
    }

    k_pack_head<<<64,256>>>(W_d, b_d, W_c, b_c);
    k_gemm_uv<<<dim3((N_ATOM+127)/128, (UVS_H+127)/128), 256>>>(UVS_H);
    k_pass1_t<NC_H,0><<<1184,256,P1_DSMB>>>(edge_fea, 1, eidx, UVS_H);
    k_finalize0<<<1,256>>>(NC_H, 1.0/(double)N_ROW);
    k_pass2_head<<<(int)((N_ROW+7)/8), 256>>>(out);
}

// round 9
// speedup vs baseline: 1.2438x; 1.2210x over previous
#include <cuda_runtime.h>
#include <cuda_fp16.h>
#include <math.h>

#define N_ATOM  50000
#define M_NBR   12
#define N_ROW   600000
#define OFD     92
#define FDIM    64
#define EDIMM   41
#define NC_L    210
#define NC_H    256
#define UVS_L   420
#define UVS_H   512

// ---------------- scratch (device globals; no runtime allocation) ----------------
__device__ __align__(16) __half  g_Yh[(size_t)N_ROW * NC_H];   // fp16 pre-activations
__device__ __align__(16) float  g_G[(size_t)N_ROW * EDIMM];
__device__ __align__(16) float  g_EDGE[(size_t)N_ROW * EDIMM];
__device__ __align__(16) float  g_NODE[N_ATOM * FDIM];
__device__ __align__(16) float  g_AGGR[N_ATOM * FDIM];
__device__ __align__(16) float  g_UV[(size_t)N_ATOM * UVS_H];
__device__ __align__(16) float  g_WP[FDIM * UVS_H];
__device__ __align__(16) float  g_BP[UVS_H];
__device__ __align__(16) float  g_EW[EDIMM * NC_H];
__device__ __align__(16) float  g_DIST[N_ROW];
__device__ double g_S[2 * NC_H];
__device__ double g_SA[2 * FDIM];
__device__ double g_SG[2 * EDIMM];
__device__ float  g_MEAN[NC_H], g_ISTD[NC_H];
__device__ float  g_MEANA[FDIM], g_ISTDA[FDIM];
__device__ float  g_MEANG[EDIMM], g_ISTDG[EDIMM];

__device__ __forceinline__ float lrelu(float x){ return x > 0.f ? x : 0.01f*x; }
__device__ __forceinline__ float sigm(float x){ return 1.f/(1.f + __expf(-x)); }
__device__ __forceinline__ float softplus(float x){ return fmaxf(x,0.f) + log1pf(__expf(-fabsf(x))); }

// ---------------- packed f32x2 helpers (sm_103a FFMA2 via PTX) ----------------
__device__ __forceinline__ unsigned long long pack_dup(float x){
    unsigned long long r; unsigned int xi = __float_as_uint(x);
    asm("mov.b64 %0, {%1, %1};" : "=l"(r) : "r"(xi));
    return r;
}
__device__ __forceinline__ void fma2(unsigned long long &d, unsigned long long a, unsigned long long b){
    asm("fma.rn.f32x2 %0, %1, %2, %0;" : "+l"(d) : "l"(a), "l"(b));
}
__device__ __forceinline__ float2 unpack2(unsigned long long v){
    unsigned int lo, hi;
    asm("mov.b64 {%0, %1}, %2;" : "=r"(lo), "=r"(hi) : "l"(v));
    float2 f; f.x = __uint_as_float(lo); f.y = __uint_as_float(hi); return f;
}

// ---------------- distance ----------------
__global__ void k_dist(const float* __restrict__ nbr, const float* __restrict__ pos,
                       const float* __restrict__ cells, const int* __restrict__ eidx)
{
    int r = blockIdx.x*blockDim.x + threadIdx.x;
    if (r >= N_ROW) return;
    int n = r / M_NBR;
    float o0=nbr[r*3], o1=nbr[r*3+1], o2=nbr[r*3+2];
    const float* c = cells + (size_t)n*9;
    int g = eidx[r];
    float dd = 1e-12f;
    #pragma unroll
    for (int j=0;j<3;j++){
        float off = o0*c[j] + o1*c[3+j] + o2*c[6+j];
        float d = pos[g*3+j] + off - pos[n*3+j];
        dd += d*d;
    }
    g_DIST[r] = sqrtf(dd);
}

// ---------------- embedding GEMM: g_NODE = node_fea @ W_emb + b_emb ----------------
__global__ void __launch_bounds__(256) k_gemm_emb(const float* __restrict__ A,
                                                  const float* __restrict__ B,
                                                  const float* __restrict__ bias,
                                                  int Nrows, int K, int Ncols)
{
    __shared__ float As[64*32];
    __shared__ float Bs[32*128];
    int tid = threadIdx.x;
    int colT = tid & 31, rowT = tid >> 5;
    int r0 = blockIdx.x*64;
    float acc[8][4];
    #pragma unroll
    for (int ri=0;ri<8;ri++)
        #pragma unroll
        for (int ci=0;ci<4;ci++) acc[ri][ci]=0.f;

    for (int k0=0;k0<K;k0+=32){
        for (int i=tid;i<64*32;i+=256){
            int rr=i>>5, kk=i&31; int gr=r0+rr, gk=k0+kk;
            As[i] = (gr<Nrows && gk<K)? A[(size_t)gr*K+gk] : 0.f;
        }
        for (int i=tid;i<32*128;i+=256){
            int kk=i>>7, jj=i&127; int gk=k0+kk;
            Bs[i] = (gk<K && jj<Ncols)? B[(size_t)gk*Ncols+jj] : 0.f;
        }
        __syncthreads();
        #pragma unroll 4
        for (int kk=0;kk<32;kk++){
            float a[8];
            #pragma unroll
            for (int ri=0;ri<8;ri++) a[ri]=As[(rowT+8*ri)*32+kk];
            #pragma unroll
            for (int ci=0;ci<4;ci++){
                float b=Bs[kk*128 + colT + 32*ci];
                #pragma unroll
                for (int ri=0;ri<8;ri++) acc[ri][ci] = fmaf(a[ri], b, acc[ri][ci]);
            }
        }
        __syncthreads();
    }
    #pragma unroll
    for (int ri=0;ri<8;ri++){
        int gr=r0+rowT+8*ri;
        if (gr >= Nrows) continue;
        #pragma unroll
        for (int ci=0;ci<4;ci++){
            int gj=colT+32*ci;
            if (gj < Ncols) g_NODE[(size_t)gr*Ncols+gj] = acc[ri][ci] + bias[gj];
        }
    }
}

// ---------------- UV GEMM (f32x2): g_UV = g_NODE(50000x64) @ g_WP + g_BP ----------------
__global__ void __launch_bounds__(256) k_gemm_uv(int Ncols)
{
    __shared__ __align__(16) float As[16][128];   // [k][m]
    __shared__ __align__(16) float Bs[16][128];   // [k][n]
    int tid = threadIdx.x;
    int tx = tid & 15, ty = tid >> 4;
    int r0 = blockIdx.x*128, c0 = blockIdx.y*128;
    unsigned long long acc2[8][4];
    #pragma unroll
    for (int i=0;i<8;i++)
        #pragma unroll
        for (int p=0;p<4;p++) acc2[i][p]=0ull;

    for (int k0=0;k0<FDIM;k0+=16){
        #pragma unroll
        for (int h=0;h<2;h++){
            int arow = (tid>>2) + h*64;
            int acol = (tid&3)*4;
            float4 v = make_float4(0.f,0.f,0.f,0.f);
            int gr = r0 + arow;
            if (gr < N_ATOM) v = *(const float4*)&g_NODE[(size_t)gr*FDIM + k0 + acol];
            As[acol+0][arow]=v.x; As[acol+1][arow]=v.y; As[acol+2][arow]=v.z; As[acol+3][arow]=v.w;
        }
        #pragma unroll
        for (int h=0;h<2;h++){
            int brow = (tid>>5) + h*8;
            int bcol = (tid&31)*4;
            float4 v = make_float4(0.f,0.f,0.f,0.f);
            if (c0 + bcol < Ncols) v = *(const float4*)&g_WP[(size_t)(k0+brow)*Ncols + c0 + bcol];
            *(float4*)&Bs[brow][bcol] = v;
        }
        __syncthreads();
        #pragma unroll
        for (int kk=0;kk<16;kk++){
            float a[8];
            *(float4*)&a[0] = *(const float4*)&As[kk][ty*8];
            *(float4*)&a[4] = *(const float4*)&As[kk][ty*8+4];
            unsigned long long bp[4];
            #pragma unroll
            for (int p=0;p<4;p++) bp[p] = *(const unsigned long long*)&Bs[kk][tx*8 + 2*p];
            #pragma unroll
            for (int i=0;i<8;i++){
                unsigned long long ap = pack_dup(a[i]);
                #pragma unroll
                for (int p=0;p<4;p++) fma2(acc2[i][p], ap, bp[p]);
            }
        }
        __syncthreads();
    }
    #pragma unroll
    for (int ri=0;ri<8;ri++){
        int gr = r0 + ty*8 + ri;
        if (gr >= N_ATOM) continue;
        #pragma unroll
        for (int cj=0;cj<2;cj++){
            int gj = c0 + tx*8 + cj*4;
            if (gj < Ncols){
                float4 bv = *(const float4*)&g_BP[gj];
                float2 v0 = unpack2(acc2[ri][cj*2+0]);
                float2 v1 = unpack2(acc2[ri][cj*2+1]);
                float4 o;
                o.x = v0.x + bv.x;
                o.y = v0.y + bv.y;
                o.z = v1.x + bv.z;
                o.w = v1.y + bv.w;
                *(float4*)&g_UV[(size_t)gr*Ncols + gj] = o;
            }
        }
    }
}

// ---------------- weight packing (+ stat zeroing) ----------------
__global__ void k_pack_layer(const float* __restrict__ Wn, const float* __restrict__ bn,
                             const float* __restrict__ We, const float* __restrict__ be)
{
    int stride = gridDim.x*blockDim.x;
    int t0 = blockIdx.x*blockDim.x + threadIdx.x;
    for (int idx=t0; idx<FDIM*UVS_L; idx+=stride){
        int k = idx / UVS_L, j = idx % UVS_L;
        float v;
        if (j<128)       v = Wn[k*128 + j];
        else if (j<256)  v = Wn[(64+k)*128 + (j-128)];
        else if (j<338)  v = We[k*82 + (j-256)];
        else             v = We[(64+k)*82 + (j-338)];
        g_WP[idx] = v;
    }
    for (int j=t0;j<UVS_L;j+=stride){
        float v = 0.f;
        if (j<128) v = bn[j];
        else if (j>=256 && j<338) v = be[j-256];
        g_BP[j]=v;
    }
    for (int idx=t0;idx<EDIMM*NC_L;idx+=stride){
        int k=idx/NC_L, j=idx%NC_L;
        g_EW[idx] = (j<128)? Wn[(128+k)*128 + j] : We[(128+k)*82 + (j-128)];
    }
    if (t0 < 2*NC_H)  g_S[t0]=0.0;
    if (t0 < 2*FDIM)  g_SA[t0]=0.0;
    if (t0 < 2*EDIMM) g_SG[t0]=0.0;
}

__global__ void k_pack_head(const float* __restrict__ Wd, const float* __restrict__ bd,
                            const float* __restrict__ Wc, const float* __restrict__ bc)
{
    int stride = gridDim.x*blockDim.x;
    int t0 = blockIdx.x*blockDim.x + threadIdx.x;
    for (int idx=t0; idx<FDIM*UVS_H; idx+=stride){
        int k = idx / UVS_H, j = idx % UVS_H;
        float v;
        if (j<128)       v = Wd[k*128 + j];
        else if (j<256)  v = Wd[(64+k)*128 + (j-128)];
        else if (j<384)  v = Wc[k*128 + (j-256)];
        else             v = Wc[(64+k)*128 + (j-384)];
        g_WP[idx] = v;
    }
    for (int j=t0;j<UVS_H;j+=stride){
        float v = 0.f;
        if (j<128) v = bd[j];
        else if (j>=256 && j<384) v = bc[j-256];
        g_BP[j]=v;
    }
    for (int idx=t0;idx<EDIMM*NC_H;idx+=stride){
        int k=idx/NC_H, j=idx%NC_H;
        g_EW[idx] = (j<128)? Wd[(128+k)*128 + j] : Wc[(128+k)*128 + (j-128)];
    }
    if (t0 < 2*NC_H) g_S[t0]=0.0;
}

// ---------------- pass1 (round-6 winner + double-buffered E + fp16 Y) ----------------
// Weights repacked in smem: per k, NPAIR pairs of columns (j, j+32) interleaved
// (one LDS.64 per pair), plus optional scalar tail (NC_L: 18 valid tail cols).
// E tile double-buffered: prefetch next tile into regs during compute.
#define P1_TR   40
#define P1_TE   (P1_TR*EDIMM)   // 1640 floats per tile

template<int NC, int NPAIR, int HAS_SCALAR>
__global__ void __launch_bounds__(256,2) k_pass1(const float* __restrict__ Ein, int useG,
                                                 const int* __restrict__ eidx, int uvS)
{
    const int KSTRIDE = NPAIR*64 + (HAS_SCALAR?32:0);
    const int CPT     = 2*NPAIR + HAS_SCALAR;
    extern __shared__ float dsmf[];
    float* sEW = dsmf;                       // EDIMM*KSTRIDE
    float* sE  = dsmf + EDIMM*KSTRIDE;       // 2 * P1_TE (double buffer)
    const float* E = useG ? (const float*)g_EDGE : Ein;
    const int tid = threadIdx.x;
    const int colT = tid & 31, rowT = tid >> 5;
    const int gs = gridDim.x;
    const int nTiles = N_ROW / P1_TR;

    for (int i=tid;i<EDIMM*KSTRIDE;i+=256) sEW[i]=0.f;
    __syncthreads();
    for (int i=tid;i<EDIMM*NC;i+=256){
        int k = i / NC, j = i - k*NC;
        float v = g_EW[i];
        int dest;
        if (HAS_SCALAR && j >= NPAIR*64)
            dest = k*KSTRIDE + NPAIR*64 + (j - NPAIR*64);
        else {
            int p = j>>6, c = j&63;
            dest = k*KSTRIDE + p*64 + ((c&31)<<1) + (c>>5);
        }
        sEW[dest] = v;
    }

    // prologue: load first tile into buffer 0
    {
        int t0i = blockIdx.x;
        if (t0i < nTiles){
            size_t base = (size_t)t0i*P1_TE;
            for (int i=tid;i<P1_TE;i+=256) sE[i] = E[base + i];
        }
    }
    __syncthreads();

    float s1[CPT], s2[CPT];
    #pragma unroll
    for (int ci=0;ci<CPT;ci++){ s1[ci]=0.f; s2[ci]=0.f; }

    int cur = 0;
    for (int t = blockIdx.x; t < nTiles; t += gs){
        // prefetch next tile into registers (latency overlapped with compute)
        float pf[7];
        int tn = t + gs;
        if (tn < nTiles){
            size_t nbase = (size_t)tn*P1_TE;
            #pragma unroll
            for (int i=0;i<7;i++){
                int idx = tid + i*256;
                if (idx < P1_TE) pf[i] = E[nbase + idx];
            }
        }

        int r0 = t*P1_TR;
        unsigned long long acc2[5][NPAIR];
        float acc1[5];
        #pragma unroll
        for (int ri=0;ri<5;ri++){
            acc1[ri]=0.f;
            #pragma unroll
            for (int p=0;p<NPAIR;p++) acc2[ri][p]=0ull;
        }
        const float* pE = sE + cur*P1_TE + rowT*5*EDIMM;
        #pragma unroll 2
        for (int k=0;k<EDIMM;k++){
            float ev[5];
            unsigned long long evp[5];
            #pragma unroll
            for (int ri=0;ri<5;ri++){ ev[ri] = pE[ri*EDIMM + k]; evp[ri] = pack_dup(ev[ri]); }
            const float* wrow = sEW + k*KSTRIDE;
            unsigned long long wp[NPAIR];
            #pragma unroll
            for (int p=0;p<NPAIR;p++) wp[p] = *(const unsigned long long*)&wrow[p*64 + colT*2];
            #pragma unroll
            for (int p=0;p<NPAIR;p++)
                #pragma unroll
                for (int ri=0;ri<5;ri++) fma2(acc2[ri][p], evp[ri], wp[p]);
            if (HAS_SCALAR){
                float ws = wrow[NPAIR*64 + colT];
                #pragma unroll
                for (int ri=0;ri<5;ri++) acc1[ri] = fmaf(ev[ri], ws, acc1[ri]);
            }
        }
        #pragma unroll
        for (int ri=0;ri<5;ri++){
            int row = r0 + rowT*5 + ri;
            int n  = row / M_NBR;
            int gg = __ldg(&eidx[row]);
            const float* Un = g_UV + (size_t)n*uvS;
            const float* Vg = g_UV + (size_t)gg*uvS;
            __half* yp = g_Yh + (size_t)row*NC;
            #pragma unroll
            for (int p=0;p<NPAIR;p++){
                float2 y = unpack2(acc2[ri][p]);
                int j0 = colT + p*64, j1 = j0 + 32;
                int uc0 = (j0<128)? j0       : j0+128;
                int vc0 = (j0<128)? (j0+128) : j0+NC;
                int uc1 = (j1<128)? j1       : j1+128;
                int vc1 = (j1<128)? (j1+128) : j1+NC;
                float y0 = y.x + Un[uc0] + Vg[vc0];
                float y1 = y.y + Un[uc1] + Vg[vc1];
                yp[j0] = __float2half_rn(y0);
                yp[j1] = __float2half_rn(y1);
                s1[2*p]   += y0; s2[2*p]   += y0*y0;
                s1[2*p+1] += y1; s2[2*p+1] += y1*y1;
            }
            if (HAS_SCALAR && colT < (NC - NPAIR*64)){
                int j = NPAIR*64 + colT;
                float y = acc1[ri] + Un[j+128] + Vg[j+NC];
                yp[j] = __float2half_rn(y);
                s1[CPT-1] += y; s2[CPT-1] += y*y;
            }
        }

        // store prefetched tile into alternate buffer, flip
        if (tn < nTiles){
            float* dst = sE + (cur^1)*P1_TE;
            #pragma unroll
            for (int i=0;i<7;i++){
                int idx = tid + i*256;
                if (idx < P1_TE) dst[idx] = pf[i];
            }
        }
        __syncthreads();
        cur ^= 1;
    }

    float* red = sE;
    #pragma unroll 1
    for (int ci=0;ci<CPT;ci++){
        red[tid] = s1[ci];
        red[256+tid] = s2[ci];
        __syncthreads();
        if (tid < 32){
            float a=0.f, b=0.f;
            #pragma unroll
            for (int w=0;w<8;w++){ a += red[w*32+tid]; b += red[256+w*32+tid]; }
            int j = tid + 32*ci;
            if (j < NC){
                atomicAdd(&g_S[j],    (double)a);
                atomicAdd(&g_S[NC+j], (double)b);
            }
        }
        __syncthreads();
    }
}

#define P1_DSMB_L ((EDIMM*224 + 2*P1_TE)*4)
#define P1_DSMB_H ((EDIMM*256 + 2*P1_TE)*4)

// ---------------- finalize stats ----------------
__global__ void k_finalize0(int C, double invCnt)
{
    int t = threadIdx.x + blockIdx.x*blockDim.x;
    if (t >= C) return;
    double m = g_S[t]*invCnt;
    double v = g_S[C+t]*invCnt - m*m;
    g_MEAN[t] = (float)m;
    g_ISTD[t] = rsqrtf((float)v + 1e-5f);
}

__global__ void k_finalize12()
{
    int t = threadIdx.x;
    if (t < FDIM){
        double m = g_SA[t] * (1.0/(double)N_ATOM);
        double v = g_SA[FDIM+t] * (1.0/(double)N_ATOM) - m*m;
        g_MEANA[t] = (float)m;
        g_ISTDA[t] = rsqrtf((float)v + 1e-5f);
    } else if (t >= 64 && t < 64+EDIMM){
        int c = t-64;
        double m = g_SG[c] * (1.0/(double)N_ROW);
        double v = g_SG[EDIMM+c] * (1.0/(double)N_ROW) - m*m;
        g_MEANG[c] = (float)m;
        g_ISTDG[c] = rsqrtf((float)v + 1e-5f);
    }
}

// ---------------- pass2 (layer) ----------------
__global__ void __launch_bounds__(128) k_pass2_layer()
{
    int t = threadIdx.x;
    bool isNode = t < 64;
    bool isEdge = (t >= 64 && t < 105);
    float m1=0.f,i1=0.f,m2=0.f,i2=0.f;
    int c = 0;
    if (isNode){ c=t;    m1=g_MEAN[c];     i1=g_ISTD[c];     m2=g_MEAN[64+c];  i2=g_ISTD[64+c]; }
    else if (isEdge){ c=t-64; m1=g_MEAN[128+c]; i1=g_ISTD[128+c]; m2=g_MEAN[169+c]; i2=g_ISTD[169+c]; }
    float st1=0.f, st2=0.f;
    for (int n = blockIdx.x; n < N_ATOM; n += gridDim.x){
        if (isNode){
            float a = 0.f;
            #pragma unroll
            for (int m=0;m<M_NBR;m++){
                size_t row = (size_t)(n*M_NBR+m);
                float y1 = (__half2float(g_Yh[row*NC_L + c])      - m1)*i1;
                float y2 = (__half2float(g_Yh[row*NC_L + 64 + c]) - m2)*i2;
                a += sigm(y1)*lrelu(y2);
            }
            g_AGGR[n*64 + c] = a;
            st1 += a; st2 += a*a;
        } else if (isEdge){
            #pragma unroll
            for (int m=0;m<M_NBR;m++){
                size_t row = (size_t)(n*M_NBR+m);
                float y1 = (__half2float(g_Yh[row*NC_L + 128 + c]) - m1)*i1;
                float y2 = (__half2float(g_Yh[row*NC_L + 169 + c]) - m2)*i2;
                float gv = sigm(y1)*lrelu(y2);
                g_G[row*EDIMM + c] = gv;
                st1 += gv; st2 += gv*gv;
            }
        }
    }
    if (isNode){ atomicAdd(&g_SA[c], (double)st1); atomicAdd(&g_SA[64+c], (double)st2); }
    else if (isEdge){ atomicAdd(&g_SG[c], (double)st1); atomicAdd(&g_SG[41+c], (double)st2); }
}

__global__ void k_node_update()
{
    int idx = blockIdx.x*blockDim.x + threadIdx.x;
    if (idx >= N_ATOM*FDIM) return;
    int c = idx & 63;
    float v = g_NODE[idx] + (g_AGGR[idx] - g_MEANA[c]) * g_ISTDA[c];
    g_NODE[idx] = lrelu(v);
}

__global__ void k_edge_update(const float* __restrict__ Ein, int useG)
{
    size_t idx = (size_t)blockIdx.x*blockDim.x + threadIdx.x;
    if (idx >= (size_t)N_ROW*EDIMM) return;
    int c = (int)(idx % EDIMM);
    float e = useG ? g_EDGE[idx] : Ein[idx];
    float v = e + (g_G[idx] - g_MEANG[c]) * g_ISTDG[c];
    g_EDGE[idx] = lrelu(v);
}

// ---------------- pass2 (head) ----------------
__global__ void __launch_bounds__(256) k_pass2_head(float* __restrict__ out)
{
    int warp = threadIdx.x >> 5, lane = threadIdx.x & 31;
    size_t r = (size_t)blockIdx.x*8 + warp;
    if (r >= N_ROW) return;
    float dist = g_DIST[r];
    float bd = 0.f, bc = 0.f;
    const __half* y = g_Yh + r*NC_H;
    #pragma unroll
    for (int i=0;i<8;i++){
        int cidx = lane + 32*i;
        float v = (__half2float(y[cidx]) - g_MEAN[cidx]) * g_ISTD[cidx];
        if (i < 4) bd += softplus(v + dist);
        else       bc += softplus(v);
    }
    #pragma unroll
    for (int o=16;o>0;o>>=1){
        bd += __shfl_down_sync(0xffffffffu, bd, o);
        bc += __shfl_down_sync(0xffffffffu, bc, o);
    }
    if (lane==0){
        out[r*2]   = bd * (1.f/128.f);
        out[r*2+1] = bc * (1.f/128.f) * (1.f/(float)N_ATOM);
    }
}

// ---------------- host orchestration ----------------
extern "C" void kernel_launch(void* const* d_in, const int* in_sizes, int n_in,
                              void* d_out, int out_size)
{
    const float* node_fea = (const float*)d_in[0];
    const float* edge_fea = (const float*)d_in[1];
    const float* nbr_off  = (const float*)d_in[2];
    const float* atom_pos = (const float*)d_in[3];
    const float* cells    = (const float*)d_in[4];
    const int*   eidx     = (const int*)  d_in[5];
    const float* W_emb = (const float*)d_in[6];
    const float* b_emb = (const float*)d_in[7];
    const float* W_pn  = (const float*)d_in[8];
    const float* b_pn  = (const float*)d_in[9];
    const float* W_pe  = (const float*)d_in[10];
    const float* b_pe  = (const float*)d_in[11];
    const float* W_d   = (const float*)d_in[12];
    const float* b_d   = (const float*)d_in[13];
    const float* W_c   = (const float*)d_in[14];
    const float* b_c   = (const float*)d_in[15];
    float* out = (float*)d_out;

    // opt-in to >48KB dynamic shared memory for pass1 (idempotent, capture-legal)
    cudaFuncSetAttribute(k_pass1<NC_L,3,1>, cudaFuncAttributeMaxDynamicSharedMemorySize, P1_DSMB_L);
    cudaFuncSetAttribute(k_pass1<NC_H,4,0>, cudaFuncAttributeMaxDynamicSharedMemorySize, P1_DSMB_H);

    k_dist<<<(N_ROW+255)/256, 256>>>(nbr_off, atom_pos, cells, eidx);
    k_gemm_emb<<<(N_ATOM+63)/64, 256>>>(node_fea, W_emb, b_emb, N_ATOM, OFD, FDIM);

    for (int l=0;l<3;l++){
        int useG = (l>0) ? 1 : 0;
        k_pack_layer<<<64,256>>>(W_pn + (size_t)l*169*128, b_pn + l*128,
                                 W_pe + (size_t)l*169*82,  b_pe + l*82);
        k_gemm_uv<<<dim3((N_ATOM+127)/128, (UVS_L+127)/128), 256>>>(UVS_L);
        k_pass1<NC_L,3,1><<<1184,256,P1_DSMB_L>>>(edge_fea, useG, eidx, UVS_L);
        k_finalize0<<<1,256>>>(NC_L, 1.0/(double)N_ROW);
        k_pass2_layer<<<2368,128>>>();
        k_finalize12<<<1,128>>>();
        k_node_update<<<(N_ATOM*FDIM+255)/256,256>>>();
        k_edge_update<<<(int)(((size_t)N_ROW*EDIMM+255)/256),256>>>(edge_fea, useG);
    }

    k_pack_head<<<64,256>>>(W_d, b_d, W_c, b_c);
    k_gemm_uv<<<dim3((N_ATOM+127)/128, (UVS_H+127)/128), 256>>>(UVS_H);
    k_pass1<NC_H,4,0><<<1184,256,P1_DSMB_H>>>(edge_fea, 1, eidx, UVS_H);
    k_finalize0<<<1,256>>>(NC_H, 1.0/(double)N_ROW);
    k_pass2_head<<<(int)((N_ROW+7)/8), 256>>>(out);
}

// round 11
// speedup vs baseline: 1.2735x; 1.0239x over previous
#include <cuda_runtime.h>
#include <cuda_fp16.h>
#include <math.h>

#define N_ATOM  50000
#define M_NBR   12
#define N_ROW   600000
#define OFD     92
#define FDIM    64
#define EDIMM   41
#define NC_L    210
#define NC_H    256
#define UVS_L   420
#define UVS_H   512

// ---------------- scratch (device globals; no runtime allocation) ----------------
__device__ __align__(16) __half g_Yh[(size_t)N_ROW * NC_H];   // fp16 pre-activations
__device__ __align__(16) float  g_G[(size_t)N_ROW * EDIMM];
__device__ __align__(16) float  g_EDGE[(size_t)N_ROW * EDIMM];
__device__ __align__(16) float  g_NODE[N_ATOM * FDIM];
__device__ __align__(16) float  g_AGGR[N_ATOM * FDIM];
__device__ __align__(16) __half g_UVh[(size_t)N_ATOM * UVS_H]; // fp16 UV table
__device__ __align__(16) float  g_WP[FDIM * UVS_H];
__device__ __align__(16) float  g_BP[UVS_H];
__device__ __align__(16) float  g_EW[EDIMM * NC_H];
__device__ __align__(16) float  g_DIST[N_ROW];
__device__ double g_S[2 * NC_H];
__device__ double g_SA[2 * FDIM];
__device__ double g_SG[2 * EDIMM];
__device__ float  g_MEAN[NC_H], g_ISTD[NC_H];
__device__ float  g_MEANA[FDIM], g_ISTDA[FDIM];
__device__ float  g_MEANG[EDIMM], g_ISTDG[EDIMM];

__device__ __forceinline__ float lrelu(float x){ return x > 0.f ? x : 0.01f*x; }
__device__ __forceinline__ float sigm(float x){ return 1.f/(1.f + __expf(-x)); }
__device__ __forceinline__ float softplus(float x){ return fmaxf(x,0.f) + log1pf(__expf(-fabsf(x))); }

// ---------------- packed f32x2 helpers (sm_103a FFMA2 via PTX) ----------------
__device__ __forceinline__ unsigned long long pack_dup(float x){
    unsigned long long r; unsigned int xi = __float_as_uint(x);
    asm("mov.b64 %0, {%1, %1};" : "=l"(r) : "r"(xi));
    return r;
}
__device__ __forceinline__ unsigned long long pack2(float lo, float hi){
    unsigned long long r;
    asm("mov.b64 %0, {%1, %2};" : "=l"(r) : "r"(__float_as_uint(lo)), "r"(__float_as_uint(hi)));
    return r;
}
__device__ __forceinline__ void fma2(unsigned long long &d, unsigned long long a, unsigned long long b){
    asm("fma.rn.f32x2 %0, %1, %2, %0;" : "+l"(d) : "l"(a), "l"(b));
}
__device__ __forceinline__ float2 unpack2(unsigned long long v){
    unsigned int lo, hi;
    asm("mov.b64 {%0, %1}, %2;" : "=r"(lo), "=r"(hi) : "l"(v));
    float2 f; f.x = __uint_as_float(lo); f.y = __uint_as_float(hi); return f;
}

// ---------------- distance ----------------
__global__ void k_dist(const float* __restrict__ nbr, const float* __restrict__ pos,
                       const float* __restrict__ cells, const int* __restrict__ eidx)
{
    int r = blockIdx.x*blockDim.x + threadIdx.x;
    if (r >= N_ROW) return;
    int n = r / M_NBR;
    float o0=nbr[r*3], o1=nbr[r*3+1], o2=nbr[r*3+2];
    const float* c = cells + (size_t)n*9;
    int g = eidx[r];
    float dd = 1e-12f;
    #pragma unroll
    for (int j=0;j<3;j++){
        float off = o0*c[j] + o1*c[3+j] + o2*c[6+j];
        float d = pos[g*3+j] + off - pos[n*3+j];
        dd += d*d;
    }
    g_DIST[r] = sqrtf(dd);
}

// ---------------- embedding GEMM: g_NODE = node_fea @ W_emb + b_emb ----------------
__global__ void __launch_bounds__(256) k_gemm_emb(const float* __restrict__ A,
                                                  const float* __restrict__ B,
                                                  const float* __restrict__ bias,
                                                  int Nrows, int K, int Ncols)
{
    __shared__ float As[64*32];
    __shared__ float Bs[32*128];
    int tid = threadIdx.x;
    int colT = tid & 31, rowT = tid >> 5;
    int r0 = blockIdx.x*64;
    float acc[8][4];
    #pragma unroll
    for (int ri=0;ri<8;ri++)
        #pragma unroll
        for (int ci=0;ci<4;ci++) acc[ri][ci]=0.f;

    for (int k0=0;k0<K;k0+=32){
        for (int i=tid;i<64*32;i+=256){
            int rr=i>>5, kk=i&31; int gr=r0+rr, gk=k0+kk;
            As[i] = (gr<Nrows && gk<K)? A[(size_t)gr*K+gk] : 0.f;
        }
        for (int i=tid;i<32*128;i+=256){
            int kk=i>>7, jj=i&127; int gk=k0+kk;
            Bs[i] = (gk<K && jj<Ncols)? B[(size_t)gk*Ncols+jj] : 0.f;
        }
        __syncthreads();
        #pragma unroll 4
        for (int kk=0;kk<32;kk++){
            float a[8];
            #pragma unroll
            for (int ri=0;ri<8;ri++) a[ri]=As[(rowT+8*ri)*32+kk];
            #pragma unroll
            for (int ci=0;ci<4;ci++){
                float b=Bs[kk*128 + colT + 32*ci];
                #pragma unroll
                for (int ri=0;ri<8;ri++) acc[ri][ci] = fmaf(a[ri], b, acc[ri][ci]);
            }
        }
        __syncthreads();
    }
    #pragma unroll
    for (int ri=0;ri<8;ri++){
        int gr=r0+rowT+8*ri;
        if (gr >= Nrows) continue;
        #pragma unroll
        for (int ci=0;ci<4;ci++){
            int gj=colT+32*ci;
            if (gj < Ncols) g_NODE[(size_t)gr*Ncols+gj] = acc[ri][ci] + bias[gj];
        }
    }
}

// ---------------- UV GEMM (f32x2): g_UVh = fp16( g_NODE @ g_WP + g_BP ) ----------------
__global__ void __launch_bounds__(256) k_gemm_uv(int Ncols)
{
    __shared__ __align__(16) float As[16][128];
    __shared__ __align__(16) float Bs[16][128];
    int tid = threadIdx.x;
    int tx = tid & 15, ty = tid >> 4;
    int r0 = blockIdx.x*128, c0 = blockIdx.y*128;
    unsigned long long acc2[8][4];
    #pragma unroll
    for (int i=0;i<8;i++)
        #pragma unroll
        for (int p=0;p<4;p++) acc2[i][p]=0ull;

    for (int k0=0;k0<FDIM;k0+=16){
        #pragma unroll
        for (int h=0;h<2;h++){
            int arow = (tid>>2) + h*64;
            int acol = (tid&3)*4;
            float4 v = make_float4(0.f,0.f,0.f,0.f);
            int gr = r0 + arow;
            if (gr < N_ATOM) v = *(const float4*)&g_NODE[(size_t)gr*FDIM + k0 + acol];
            As[acol+0][arow]=v.x; As[acol+1][arow]=v.y; As[acol+2][arow]=v.z; As[acol+3][arow]=v.w;
        }
        #pragma unroll
        for (int h=0;h<2;h++){
            int brow = (tid>>5) + h*8;
            int bcol = (tid&31)*4;
            float4 v = make_float4(0.f,0.f,0.f,0.f);
            if (c0 + bcol < Ncols) v = *(const float4*)&g_WP[(size_t)(k0+brow)*Ncols + c0 + bcol];
            *(float4*)&Bs[brow][bcol] = v;
        }
        __syncthreads();
        #pragma unroll
        for (int kk=0;kk<16;kk++){
            float a[8];
            *(float4*)&a[0] = *(const float4*)&As[kk][ty*8];
            *(float4*)&a[4] = *(const float4*)&As[kk][ty*8+4];
            unsigned long long bp[4];
            #pragma unroll
            for (int p=0;p<4;p++) bp[p] = *(const unsigned long long*)&Bs[kk][tx*8 + 2*p];
            #pragma unroll
            for (int i=0;i<8;i++){
                unsigned long long ap = pack_dup(a[i]);
                #pragma unroll
                for (int p=0;p<4;p++) fma2(acc2[i][p], ap, bp[p]);
            }
        }
        __syncthreads();
    }
    #pragma unroll
    for (int ri=0;ri<8;ri++){
        int gr = r0 + ty*8 + ri;
        if (gr >= N_ATOM) continue;
        #pragma unroll
        for (int cj=0;cj<2;cj++){
            int gj = c0 + tx*8 + cj*4;
            if (gj < Ncols){
                float4 bv = *(const float4*)&g_BP[gj];
                float2 v0 = unpack2(acc2[ri][cj*2+0]);
                float2 v1 = unpack2(acc2[ri][cj*2+1]);
                __half2 h0 = __floats2half2_rn(v0.x + bv.x, v0.y + bv.y);
                __half2 h1 = __floats2half2_rn(v1.x + bv.z, v1.y + bv.w);
                uint2 st;
                st.x = *reinterpret_cast<unsigned int*>(&h0);
                st.y = *reinterpret_cast<unsigned int*>(&h1);
                *(uint2*)&g_UVh[(size_t)gr*Ncols + gj] = st;
            }
        }
    }
}

// ---------------- weight packing (+ stat zeroing) ----------------
__global__ void k_pack_layer(const float* __restrict__ Wn, const float* __restrict__ bn,
                             const float* __restrict__ We, const float* __restrict__ be)
{
    int stride = gridDim.x*blockDim.x;
    int t0 = blockIdx.x*blockDim.x + threadIdx.x;
    for (int idx=t0; idx<FDIM*UVS_L; idx+=stride){
        int k = idx / UVS_L, j = idx % UVS_L;
        float v;
        if (j<128)       v = Wn[k*128 + j];
        else if (j<256)  v = Wn[(64+k)*128 + (j-128)];
        else if (j<338)  v = We[k*82 + (j-256)];
        else             v = We[(64+k)*82 + (j-338)];
        g_WP[idx] = v;
    }
    for (int j=t0;j<UVS_L;j+=stride){
        float v = 0.f;
        if (j<128) v = bn[j];
        else if (j>=256 && j<338) v = be[j-256];
        g_BP[j]=v;
    }
    for (int idx=t0;idx<EDIMM*NC_L;idx+=stride){
        int k=idx/NC_L, j=idx%NC_L;
        g_EW[idx] = (j<128)? Wn[(128+k)*128 + j] : We[(128+k)*82 + (j-128)];
    }
    if (t0 < 2*NC_H)  g_S[t0]=0.0;
    if (t0 < 2*FDIM)  g_SA[t0]=0.0;
    if (t0 < 2*EDIMM) g_SG[t0]=0.0;
}

__global__ void k_pack_head(const float* __restrict__ Wd, const float* __restrict__ bd,
                            const float* __restrict__ Wc, const float* __restrict__ bc)
{
    int stride = gridDim.x*blockDim.x;
    int t0 = blockIdx.x*blockDim.x + threadIdx.x;
    for (int idx=t0; idx<FDIM*UVS_H; idx+=stride){
        int k = idx / UVS_H, j = idx % UVS_H;
        float v;
        if (j<128)       v = Wd[k*128 + j];
        else if (j<256)  v = Wd[(64+k)*128 + (j-128)];
        else if (j<384)  v = Wc[k*128 + (j-256)];
        else             v = Wc[(64+k)*128 + (j-384)];
        g_WP[idx] = v;
    }
    for (int j=t0;j<UVS_H;j+=stride){
        float v = 0.f;
        if (j<128) v = bd[j];
        else if (j>=256 && j<384) v = bc[j-256];
        g_BP[j]=v;
    }
    for (int idx=t0;idx<EDIMM*NC_H;idx+=stride){
        int k=idx/NC_H, j=idx%NC_H;
        g_EW[idx] = (j<128)? Wd[(128+k)*128 + j] : Wc[(128+k)*128 + (j-128)];
    }
    if (t0 < 2*NC_H) g_S[t0]=0.0;
}

// ---------------- pass1 v5: f32x2, adjacent pairs, dup-E smem, double-buffered, fp16 UV/Y ----
// Columns as adjacent pairs (2q, 2q+1), q = colT + 32*p, p in [0,4).
// Weights zero-padded to 128 pairs -> branch-free inner loop; epilogue guarded (C++).
// Dynamic smem: [ sWp: EDIMM*128 u64 pairs ][ sE: 2 * P1_TE dup'd u64 (double buffer) ].
#define P1_TR   40
#define P1_TE   (P1_TR*EDIMM)   // 1640
#define P1_DSMB ((EDIMM*128 + 2*P1_TE)*8)

template<int NC, int TAILN>
__global__ void __launch_bounds__(256,2) k_pass1(const float* __restrict__ Ein, int useG,
                                                 const int* __restrict__ eidx, int uvS)
{
    extern __shared__ unsigned long long dsm[];
    unsigned long long* sWp = dsm;                 // [EDIMM][128] adjacent column-pairs
    unsigned long long* sE  = dsm + EDIMM*128;     // 2 x [P1_TR][EDIMM] duplicated e
    const float* E = useG ? (const float*)g_EDGE : Ein;
    const int tid = threadIdx.x;
    const int colT = tid & 31, rowT = tid >> 5;
    const int gs = gridDim.x;
    const int nTiles = N_ROW / P1_TR;

    // pack weights as adjacent column pairs, zero-padded to 128 pairs
    for (int idx = tid; idx < EDIMM*128; idx += 256){
        int k = idx >> 7, q = idx & 127;
        int j0 = 2*q;
        float lo = 0.f, hi = 0.f;
        if (j0 < NC){ lo = g_EW[k*NC + j0]; hi = g_EW[k*NC + j0 + 1]; }
        sWp[idx] = pack2(lo, hi);
    }

    // prologue: first tile into buffer 0 (dup'd)
    {
        int t0i = blockIdx.x;
        if (t0i < nTiles){
            size_t base = (size_t)t0i*P1_TE;
            for (int i=tid;i<P1_TE;i+=256) sE[i] = pack_dup(E[base + i]);
        }
    }
    __syncthreads();

    float s1[8], s2[8];
    #pragma unroll
    for (int ci=0;ci<8;ci++){ s1[ci]=0.f; s2[ci]=0.f; }

    int cur = 0;
    for (int t = blockIdx.x; t < nTiles; t += gs){
        // prefetch next tile into registers
        float pf[7];
        int tn = t + gs;
        if (tn < nTiles){
            size_t nbase = (size_t)tn*P1_TE;
            #pragma unroll
            for (int i=0;i<7;i++){
                int idx = tid + i*256;
                if (idx < P1_TE) pf[i] = E[nbase + idx];
            }
        }

        int r0 = t*P1_TR;
        unsigned long long acc2[5][4];
        #pragma unroll
        for (int ri=0;ri<5;ri++)
            #pragma unroll
            for (int p=0;p<4;p++) acc2[ri][p]=0ull;

        const unsigned long long* pE = sE + cur*P1_TE + rowT*5*EDIMM;
        const unsigned long long* pW = sWp + colT;
        #pragma unroll 2
        for (int k=0;k<EDIMM;k++){
            unsigned long long evp[5];
            #pragma unroll
            for (int ri=0;ri<5;ri++) evp[ri] = pE[ri*EDIMM + k];
            unsigned long long wp[4];
            #pragma unroll
            for (int p=0;p<4;p++) wp[p] = pW[k*128 + 32*p];
            #pragma unroll
            for (int p=0;p<4;p++)
                #pragma unroll
                for (int ri=0;ri<5;ri++) fma2(acc2[ri][p], evp[ri], wp[p]);
        }
        #pragma unroll
        for (int ri=0;ri<5;ri++){
            int row = r0 + rowT*5 + ri;
            int n  = row / M_NBR;
            int gg = __ldg(&eidx[row]);
            const __half* Un = g_UVh + (size_t)n*uvS;
            const __half* Vg = g_UVh + (size_t)gg*uvS;
            __half* yp = g_Yh + (size_t)row*NC;
            #pragma unroll
            for (int p=0;p<4;p++){
                if (NC == 256 || p < 3 || colT < TAILN){
                    int j0 = 2*(colT + 32*p);
                    float2 y2 = unpack2(acc2[ri][p]);
                    int uc = (j0<128)? j0        : j0+128;
                    int vc = (j0<128)? (j0+128)  : j0+NC;
                    float2 uf = __half22float2(*(const __half2*)&Un[uc]);
                    float2 vf = __half22float2(*(const __half2*)&Vg[vc]);
                    float y0 = y2.x + uf.x + vf.x;
                    float y1 = y2.y + uf.y + vf.y;
                    *(__half2*)&yp[j0] = __floats2half2_rn(y0, y1);
                    s1[2*p]   += y0; s2[2*p]   += y0*y0;
                    s1[2*p+1] += y1; s2[2*p+1] += y1*y1;
                }
            }
        }

        // store prefetched tile (dup'd) into alternate buffer, flip
        if (tn < nTiles){
            unsigned long long* dst = sE + (cur^1)*P1_TE;
            #pragma unroll
            for (int i=0;i<7;i++){
                int idx = tid + i*256;
                if (idx < P1_TE) dst[idx] = pack_dup(pf[i]);
            }
        }
        __syncthreads();
        cur ^= 1;
    }

    float* red = (float*)sE;
    #pragma unroll 1
    for (int ci=0;ci<8;ci++){
        red[tid] = s1[ci];
        red[256+tid] = s2[ci];
        __syncthreads();
        if (tid < 32){
            float a=0.f, b=0.f;
            #pragma unroll
            for (int w=0;w<8;w++){ a += red[w*32+tid]; b += red[256+w*32+tid]; }
            int j = 2*(tid + 32*(ci>>1)) + (ci&1);
            if (j < NC){
                atomicAdd(&g_S[j],    (double)a);
                atomicAdd(&g_S[NC+j], (double)b);
            }
        }
        __syncthreads();
    }
}

// ---------------- finalize stats ----------------
__global__ void k_finalize0(int C, double invCnt)
{
    int t = threadIdx.x + blockIdx.x*blockDim.x;
    if (t >= C) return;
    double m = g_S[t]*invCnt;
    double v = g_S[C+t]*invCnt - m*m;
    g_MEAN[t] = (float)m;
    g_ISTD[t] = rsqrtf((float)v + 1e-5f);
}

__global__ void k_finalize12()
{
    int t = threadIdx.x;
    if (t < FDIM){
        double m = g_SA[t] * (1.0/(double)N_ATOM);
        double v = g_SA[FDIM+t] * (1.0/(double)N_ATOM) - m*m;
        g_MEANA[t] = (float)m;
        g_ISTDA[t] = rsqrtf((float)v + 1e-5f);
    } else if (t >= 64 && t < 64+EDIMM){
        int c = t-64;
        double m = g_SG[c] * (1.0/(double)N_ROW);
        double v = g_SG[EDIMM+c] * (1.0/(double)N_ROW) - m*m;
        g_MEANG[c] = (float)m;
        g_ISTDG[c] = rsqrtf((float)v + 1e-5f);
    }
}

// ---------------- pass2 (layer) ----------------
__global__ void __launch_bounds__(128) k_pass2_layer()
{
    int t = threadIdx.x;
    bool isNode = t < 64;
    bool isEdge = (t >= 64 && t < 105);
    float m1=0.f,i1=0.f,m2=0.f,i2=0.f;
    int c = 0;
    if (isNode){ c=t;    m1=g_MEAN[c];     i1=g_ISTD[c];     m2=g_MEAN[64+c];  i2=g_ISTD[64+c]; }
    else if (isEdge){ c=t-64; m1=g_MEAN[128+c]; i1=g_ISTD[128+c]; m2=g_MEAN[169+c]; i2=g_ISTD[169+c]; }
    float st1=0.f, st2=0.f;
    for (int n = blockIdx.x; n < N_ATOM; n += gridDim.x){
        if (isNode){
            float a = 0.f;
            #pragma unroll
            for (int m=0;m<M_NBR;m++){
                size_t row = (size_t)(n*M_NBR+m);
                float y1 = (__half2float(g_Yh[row*NC_L + c])      - m1)*i1;
                float y2 = (__half2float(g_Yh[row*NC_L + 64 + c]) - m2)*i2;
                a += sigm(y1)*lrelu(y2);
            }
            g_AGGR[n*64 + c] = a;
            st1 += a; st2 += a*a;
        } else if (isEdge){
            #pragma unroll
            for (int m=0;m<M_NBR;m++){
                size_t row = (size_t)(n*M_NBR+m);
                float y1 = (__half2float(g_Yh[row*NC_L + 128 + c]) - m1)*i1;
                float y2 = (__half2float(g_Yh[row*NC_L + 169 + c]) - m2)*i2;
                float gv = sigm(y1)*lrelu(y2);
                g_G[row*EDIMM + c] = gv;
                st1 += gv; st2 += gv*gv;
            }
        }
    }
    if (isNode){ atomicAdd(&g_SA[c], (double)st1); atomicAdd(&g_SA[64+c], (double)st2); }
    else if (isEdge){ atomicAdd(&g_SG[c], (double)st1); atomicAdd(&g_SG[41+c], (double)st2); }
}

__global__ void k_node_update()
{
    int idx = blockIdx.x*blockDim.x + threadIdx.x;
    if (idx >= N_ATOM*FDIM) return;
    int c = idx & 63;
    float v = g_NODE[idx] + (g_AGGR[idx] - g_MEANA[c]) * g_ISTDA[c];
    g_NODE[idx] = lrelu(v);
}

__global__ void k_edge_update(const float* __restrict__ Ein, int useG)
{
    size_t idx = (size_t)blockIdx.x*blockDim.x + threadIdx.x;
    if (idx >= (size_t)N_ROW*EDIMM) return;
    int c = (int)(idx % EDIMM);
    float e = useG ? g_EDGE[idx] : Ein[idx];
    float v = e + (g_G[idx] - g_MEANG[c]) * g_ISTDG[c];
    g_EDGE[idx] = lrelu(v);
}

// ---------------- pass2 (head) ----------------
__global__ void __launch_bounds__(256) k_pass2_head(float* __restrict__ out)
{
    int warp = threadIdx.x >> 5, lane = threadIdx.x & 31;
    size_t r = (size_t)blockIdx.x*8 + warp;
    if (r >= N_ROW) return;
    float dist = g_DIST[r];
    float bd = 0.f, bc = 0.f;
    const __half* y = g_Yh + r*NC_H;
    #pragma unroll
    for (int i=0;i<8;i++){
        int cidx = lane + 32*i;
        float v = (__half2float(y[cidx]) - g_MEAN[cidx]) * g_ISTD[cidx];
        if (i < 4) bd += softplus(v + dist);
        else       bc += softplus(v);
    }
    #pragma unroll
    for (int o=16;o>0;o>>=1){
        bd += __shfl_down_sync(0xffffffffu, bd, o);
        bc += __shfl_down_sync(0xffffffffu, bc, o);
    }
    if (lane==0){
        out[r*2]   = bd * (1.f/128.f);
        out[r*2+1] = bc * (1.f/128.f) * (1.f/(float)N_ATOM);
    }
}

// ---------------- host orchestration ----------------
extern "C" void kernel_launch(void* const* d_in, const int* in_sizes, int n_in,
                              void* d_out, int out_size)
{
    const float* node_fea = (const float*)d_in[0];
    const float* edge_fea = (const float*)d_in[1];
    const float* nbr_off  = (const float*)d_in[2];
    const float* atom_pos = (const float*)d_in[3];
    const float* cells    = (const float*)d_in[4];
    const int*   eidx     = (const int*)  d_in[5];
    const float* W_emb = (const float*)d_in[6];
    const float* b_emb = (const float*)d_in[7];
    const float* W_pn  = (const float*)d_in[8];
    const float* b_pn  = (const float*)d_in[9];
    const float* W_pe  = (const float*)d_in[10];
    const float* b_pe  = (const float*)d_in[11];
    const float* W_d   = (const float*)d_in[12];
    const float* b_d   = (const float*)d_in[13];
    const float* W_c   = (const float*)d_in[14];
    const float* b_c   = (const float*)d_in[15];
    float* out = (float*)d_out;

    // opt-in to >48KB dynamic shared memory for pass1 (idempotent, capture-legal)
    cudaFuncSetAttribute(k_pass1<NC_L,9>, cudaFuncAttributeMaxDynamicSharedMemorySize, P1_DSMB);
    cudaFuncSetAttribute(k_pass1<NC_H,0>, cudaFuncAttributeMaxDynamicSharedMemorySize, P1_DSMB);

    k_dist<<<(N_ROW+255)/256, 256>>>(nbr_off, atom_pos, cells, eidx);
    k_gemm_emb<<<(N_ATOM+63)/64, 256>>>(node_fea, W_emb, b_emb, N_ATOM, OFD, FDIM);

    for (int l=0;l<3;l++){
        int useG = (l>0) ? 1 : 0;
        k_pack_layer<<<64,256>>>(W_pn + (size_t)l*169*128, b_pn + l*128,
                                 W_pe + (size_t)l*169*82,  b_pe + l*82);
        k_gemm_uv<<<dim3((N_ATOM+127)/128, (UVS_L+127)/128), 256>>>(UVS_L);
        k_pass1<NC_L,9><<<1184,256,P1_DSMB>>>(edge_fea, useG, eidx, UVS_L);
        k_finalize0<<<1,256>>>(NC_L, 1.0/(double)N_ROW);
        k_pass2_layer<<<2368,128>>>();
        k_finalize12<<<1,128>>>();
        k_node_update<<<(N_ATOM*FDIM+255)/256,256>>>();
        k_edge_update<<<(int)(((size_t)N_ROW*EDIMM+255)/256),256>>>(edge_fea, useG);
    }

    k_pack_head<<<64,256>>>(W_d, b_d, W_c, b_c);
    k_gemm_uv<<<dim3((N_ATOM+127)/128, (UVS_H+127)/128), 256>>>(UVS_H);
    k_pass1<NC_H,0><<<1184,256,P1_DSMB>>>(edge_fea, 1, eidx, UVS_H);
    k_finalize0<<<1,256>>>(NC_H, 1.0/(double)N_ROW);
    k_pass2_head<<<(int)((N_ROW+7)/8), 256>>>(out);
}

// round 12
// speedup vs baseline: 1.3017x; 1.0221x over previous
#include <cuda_runtime.h>
#include <cuda_fp16.h>
#include <math.h>

#define N_ATOM  50000
#define M_NBR   12
#define N_ROW   600000
#define OFD     92
#define FDIM    64
#define EDIMM   41
#define NC_L    210
#define NC_H    256
#define UVS_L   420
#define UVS_H   512

// ---------------- scratch (device globals; no runtime allocation) ----------------
__device__ __align__(16) __half g_Yh[(size_t)N_ROW * NC_H];   // fp16 pre-activations
__device__ __align__(16) float  g_G[(size_t)N_ROW * EDIMM];
__device__ __align__(16) float  g_EDGE[(size_t)N_ROW * EDIMM];
__device__ __align__(16) float  g_NODE[N_ATOM * FDIM];
__device__ __align__(16) float  g_AGGR[N_ATOM * FDIM];
__device__ __align__(16) __half g_UVh[(size_t)N_ATOM * UVS_H]; // fp16 UV table
__device__ __align__(16) float  g_WP[FDIM * UVS_H];
__device__ __align__(16) float  g_BP[UVS_H];
__device__ __align__(16) float  g_EW[EDIMM * NC_H];
__device__ __align__(16) float  g_DIST[N_ROW];
__device__ double g_S[2 * NC_H];
__device__ double g_SA[2 * FDIM];
__device__ double g_SG[2 * EDIMM];
__device__ float  g_MEAN[NC_H], g_ISTD[NC_H];
__device__ float  g_MEANA[FDIM], g_ISTDA[FDIM];
__device__ float  g_MEANG[EDIMM], g_ISTDG[EDIMM];

__device__ __forceinline__ float lrelu(float x){ return x > 0.f ? x : 0.01f*x; }
__device__ __forceinline__ float sigm(float x){ return __fdividef(1.f, 1.f + __expf(-x)); }
__device__ __forceinline__ float softplus(float x){
    return fmaxf(x,0.f) + __logf(1.f + __expf(-fabsf(x)));
}

// ---------------- packed f32x2 helpers (sm_103a FFMA2 via PTX) ----------------
__device__ __forceinline__ unsigned long long pack_dup(float x){
    unsigned long long r; unsigned int xi = __float_as_uint(x);
    asm("mov.b64 %0, {%1, %1};" : "=l"(r) : "r"(xi));
    return r;
}
__device__ __forceinline__ unsigned long long pack2(float lo, float hi){
    unsigned long long r;
    asm("mov.b64 %0, {%1, %2};" : "=l"(r) : "r"(__float_as_uint(lo)), "r"(__float_as_uint(hi)));
    return r;
}
__device__ __forceinline__ void fma2(unsigned long long &d, unsigned long long a, unsigned long long b){
    asm("fma.rn.f32x2 %0, %1, %2, %0;" : "+l"(d) : "l"(a), "l"(b));
}
__device__ __forceinline__ float2 unpack2(unsigned long long v){
    unsigned int lo, hi;
    asm("mov.b64 {%0, %1}, %2;" : "=r"(lo), "=r"(hi) : "l"(v));
    float2 f; f.x = __uint_as_float(lo); f.y = __uint_as_float(hi); return f;
}

// ---------------- distance ----------------
__global__ void k_dist(const float* __restrict__ nbr, const float* __restrict__ pos,
                       const float* __restrict__ cells, const int* __restrict__ eidx)
{
    int r = blockIdx.x*blockDim.x + threadIdx.x;
    if (r >= N_ROW) return;
    int n = r / M_NBR;
    float o0=nbr[r*3], o1=nbr[r*3+1], o2=nbr[r*3+2];
    const float* c = cells + (size_t)n*9;
    int g = eidx[r];
    float dd = 1e-12f;
    #pragma unroll
    for (int j=0;j<3;j++){
        float off = o0*c[j] + o1*c[3+j] + o2*c[6+j];
        float d = pos[g*3+j] + off - pos[n*3+j];
        dd += d*d;
    }
    g_DIST[r] = sqrtf(dd);
}

// ---------------- embedding GEMM: g_NODE = node_fea @ W_emb + b_emb ----------------
__global__ void __launch_bounds__(256) k_gemm_emb(const float* __restrict__ A,
                                                  const float* __restrict__ B,
                                                  const float* __restrict__ bias,
                                                  int Nrows, int K, int Ncols)
{
    __shared__ float As[64*32];
    __shared__ float Bs[32*128];
    int tid = threadIdx.x;
    int colT = tid & 31, rowT = tid >> 5;
    int r0 = blockIdx.x*64;
    float acc[8][4];
    #pragma unroll
    for (int ri=0;ri<8;ri++)
        #pragma unroll
        for (int ci=0;ci<4;ci++) acc[ri][ci]=0.f;

    for (int k0=0;k0<K;k0+=32){
        for (int i=tid;i<64*32;i+=256){
            int rr=i>>5, kk=i&31; int gr=r0+rr, gk=k0+kk;
            As[i] = (gr<Nrows && gk<K)? A[(size_t)gr*K+gk] : 0.f;
        }
        for (int i=tid;i<32*128;i+=256){
            int kk=i>>7, jj=i&127; int gk=k0+kk;
            Bs[i] = (gk<K && jj<Ncols)? B[(size_t)gk*Ncols+jj] : 0.f;
        }
        __syncthreads();
        #pragma unroll 4
        for (int kk=0;kk<32;kk++){
            float a[8];
            #pragma unroll
            for (int ri=0;ri<8;ri++) a[ri]=As[(rowT+8*ri)*32+kk];
            #pragma unroll
            for (int ci=0;ci<4;ci++){
                float b=Bs[kk*128 + colT + 32*ci];
                #pragma unroll
                for (int ri=0;ri<8;ri++) acc[ri][ci] = fmaf(a[ri], b, acc[ri][ci]);
            }
        }
        __syncthreads();
    }
    #pragma unroll
    for (int ri=0;ri<8;ri++){
        int gr=r0+rowT+8*ri;
        if (gr >= Nrows) continue;
        #pragma unroll
        for (int ci=0;ci<4;ci++){
            int gj=colT+32*ci;
            if (gj < Ncols) g_NODE[(size_t)gr*Ncols+gj] = acc[ri][ci] + bias[gj];
        }
    }
}

// ---------------- UV GEMM (f32x2): g_UVh = fp16( g_NODE @ g_WP + g_BP ) ----------------
__global__ void __launch_bounds__(256) k_gemm_uv(int Ncols)
{
    __shared__ __align__(16) float As[16][128];
    __shared__ __align__(16) float Bs[16][128];
    int tid = threadIdx.x;
    int tx = tid & 15, ty = tid >> 4;
    int r0 = blockIdx.x*128, c0 = blockIdx.y*128;
    unsigned long long acc2[8][4];
    #pragma unroll
    for (int i=0;i<8;i++)
        #pragma unroll
        for (int p=0;p<4;p++) acc2[i][p]=0ull;

    for (int k0=0;k0<FDIM;k0+=16){
        #pragma unroll
        for (int h=0;h<2;h++){
            int arow = (tid>>2) + h*64;
            int acol = (tid&3)*4;
            float4 v = make_float4(0.f,0.f,0.f,0.f);
            int gr = r0 + arow;
            if (gr < N_ATOM) v = *(const float4*)&g_NODE[(size_t)gr*FDIM + k0 + acol];
            As[acol+0][arow]=v.x; As[acol+1][arow]=v.y; As[acol+2][arow]=v.z; As[acol+3][arow]=v.w;
        }
        #pragma unroll
        for (int h=0;h<2;h++){
            int brow = (tid>>5) + h*8;
            int bcol = (tid&31)*4;
            float4 v = make_float4(0.f,0.f,0.f,0.f);
            if (c0 + bcol < Ncols) v = *(const float4*)&g_WP[(size_t)(k0+brow)*Ncols + c0 + bcol];
            *(float4*)&Bs[brow][bcol] = v;
        }
        __syncthreads();
        #pragma unroll
        for (int kk=0;kk<16;kk++){
            float a[8];
            *(float4*)&a[0] = *(const float4*)&As[kk][ty*8];
            *(float4*)&a[4] = *(const float4*)&As[kk][ty*8+4];
            unsigned long long bp[4];
            #pragma unroll
            for (int p=0;p<4;p++) bp[p] = *(const unsigned long long*)&Bs[kk][tx*8 + 2*p];
            #pragma unroll
            for (int i=0;i<8;i++){
                unsigned long long ap = pack_dup(a[i]);
                #pragma unroll
                for (int p=0;p<4;p++) fma2(acc2[i][p], ap, bp[p]);
            }
        }
        __syncthreads();
    }
    #pragma unroll
    for (int ri=0;ri<8;ri++){
        int gr = r0 + ty*8 + ri;
        if (gr >= N_ATOM) continue;
        #pragma unroll
        for (int cj=0;cj<2;cj++){
            int gj = c0 + tx*8 + cj*4;
            if (gj < Ncols){
                float4 bv = *(const float4*)&g_BP[gj];
                float2 v0 = unpack2(acc2[ri][cj*2+0]);
                float2 v1 = unpack2(acc2[ri][cj*2+1]);
                __half2 h0 = __floats2half2_rn(v0.x + bv.x, v0.y + bv.y);
                __half2 h1 = __floats2half2_rn(v1.x + bv.z, v1.y + bv.w);
                uint2 st;
                st.x = *reinterpret_cast<unsigned int*>(&h0);
                st.y = *reinterpret_cast<unsigned int*>(&h1);
                *(uint2*)&g_UVh[(size_t)gr*Ncols + gj] = st;
            }
        }
    }
}

// ---------------- weight packing (+ stat zeroing) ----------------
__global__ void k_pack_layer(const float* __restrict__ Wn, const float* __restrict__ bn,
                             const float* __restrict__ We, const float* __restrict__ be)
{
    int stride = gridDim.x*blockDim.x;
    int t0 = blockIdx.x*blockDim.x + threadIdx.x;
    for (int idx=t0; idx<FDIM*UVS_L; idx+=stride){
        int k = idx / UVS_L, j = idx % UVS_L;
        float v;
        if (j<128)       v = Wn[k*128 + j];
        else if (j<256)  v = Wn[(64+k)*128 + (j-128)];
        else if (j<338)  v = We[k*82 + (j-256)];
        else             v = We[(64+k)*82 + (j-338)];
        g_WP[idx] = v;
    }
    for (int j=t0;j<UVS_L;j+=stride){
        float v = 0.f;
        if (j<128) v = bn[j];
        else if (j>=256 && j<338) v = be[j-256];
        g_BP[j]=v;
    }
    for (int idx=t0;idx<EDIMM*NC_L;idx+=stride){
        int k=idx/NC_L, j=idx%NC_L;
        g_EW[idx] = (j<128)? Wn[(128+k)*128 + j] : We[(128+k)*82 + (j-128)];
    }
    if (t0 < 2*NC_H)  g_S[t0]=0.0;
    if (t0 < 2*FDIM)  g_SA[t0]=0.0;
    if (t0 < 2*EDIMM) g_SG[t0]=0.0;
}

__global__ void k_pack_head(const float* __restrict__ Wd, const float* __restrict__ bd,
                            const float* __restrict__ Wc, const float* __restrict__ bc)
{
    int stride = gridDim.x*blockDim.x;
    int t0 = blockIdx.x*blockDim.x + threadIdx.x;
    for (int idx=t0; idx<FDIM*UVS_H; idx+=stride){
        int k = idx / UVS_H, j = idx % UVS_H;
        float v;
        if (j<128)       v = Wd[k*128 + j];
        else if (j<256)  v = Wd[(64+k)*128 + (j-128)];
        else if (j<384)  v = Wc[k*128 + (j-256)];
        else             v = Wc[(64+k)*128 + (j-384)];
        g_WP[idx] = v;
    }
    for (int j=t0;j<UVS_H;j+=stride){
        float v = 0.f;
        if (j<128) v = bd[j];
        else if (j>=256 && j<384) v = bc[j-256];
        g_BP[j]=v;
    }
    for (int idx=t0;idx<EDIMM*NC_H;idx+=stride){
        int k=idx/NC_H, j=idx%NC_H;
        g_EW[idx] = (j<128)? Wd[(128+k)*128 + j] : Wc[(128+k)*128 + (j-128)];
    }
    if (t0 < 2*NC_H) g_S[t0]=0.0;
}

// ---------------- pass1 v5: f32x2, adjacent pairs, dup-E smem, double-buffered, fp16 UV/Y ----
#define P1_TR   40
#define P1_TE   (P1_TR*EDIMM)   // 1640
#define P1_DSMB ((EDIMM*128 + 2*P1_TE)*8)

template<int NC, int TAILN>
__global__ void __launch_bounds__(256,2) k_pass1(const float* __restrict__ Ein, int useG,
                                                 const int* __restrict__ eidx, int uvS)
{
    extern __shared__ unsigned long long dsm[];
    unsigned long long* sWp = dsm;                 // [EDIMM][128] adjacent column-pairs
    unsigned long long* sE  = dsm + EDIMM*128;     // 2 x [P1_TR][EDIMM] duplicated e
    const float* E = useG ? (const float*)g_EDGE : Ein;
    const int tid = threadIdx.x;
    const int colT = tid & 31, rowT = tid >> 5;
    const int gs = gridDim.x;
    const int nTiles = N_ROW / P1_TR;

    for (int idx = tid; idx < EDIMM*128; idx += 256){
        int k = idx >> 7, q = idx & 127;
        int j0 = 2*q;
        float lo = 0.f, hi = 0.f;
        if (j0 < NC){ lo = g_EW[k*NC + j0]; hi = g_EW[k*NC + j0 + 1]; }
        sWp[idx] = pack2(lo, hi);
    }

    {
        int t0i = blockIdx.x;
        if (t0i < nTiles){
            size_t base = (size_t)t0i*P1_TE;
            for (int i=tid;i<P1_TE;i+=256) sE[i] = pack_dup(E[base + i]);
        }
    }
    __syncthreads();

    float s1[8], s2[8];
    #pragma unroll
    for (int ci=0;ci<8;ci++){ s1[ci]=0.f; s2[ci]=0.f; }

    int cur = 0;
    for (int t = blockIdx.x; t < nTiles; t += gs){
        float pf[7];
        int tn = t + gs;
        if (tn < nTiles){
            size_t nbase = (size_t)tn*P1_TE;
            #pragma unroll
            for (int i=0;i<7;i++){
                int idx = tid + i*256;
                if (idx < P1_TE) pf[i] = E[nbase + idx];
            }
        }

        int r0 = t*P1_TR;
        unsigned long long acc2[5][4];
        #pragma unroll
        for (int ri=0;ri<5;ri++)
            #pragma unroll
            for (int p=0;p<4;p++) acc2[ri][p]=0ull;

        const unsigned long long* pE = sE + cur*P1_TE + rowT*5*EDIMM;
        const unsigned long long* pW = sWp + colT;
        #pragma unroll 2
        for (int k=0;k<EDIMM;k++){
            unsigned long long evp[5];
            #pragma unroll
            for (int ri=0;ri<5;ri++) evp[ri] = pE[ri*EDIMM + k];
            unsigned long long wp[4];
            #pragma unroll
            for (int p=0;p<4;p++) wp[p] = pW[k*128 + 32*p];
            #pragma unroll
            for (int p=0;p<4;p++)
                #pragma unroll
                for (int ri=0;ri<5;ri++) fma2(acc2[ri][p], evp[ri], wp[p]);
        }
        #pragma unroll
        for (int ri=0;ri<5;ri++){
            int row = r0 + rowT*5 + ri;
            int n  = row / M_NBR;
            int gg = __ldg(&eidx[row]);
            const __half* Un = g_UVh + (size_t)n*uvS;
            const __half* Vg = g_UVh + (size_t)gg*uvS;
            __half* yp = g_Yh + (size_t)row*NC;
            #pragma unroll
            for (int p=0;p<4;p++){
                if (NC == 256 || p < 3 || colT < TAILN){
                    int j0 = 2*(colT + 32*p);
                    float2 y2 = unpack2(acc2[ri][p]);
                    int uc = (j0<128)? j0        : j0+128;
                    int vc = (j0<128)? (j0+128)  : j0+NC;
                    float2 uf = __half22float2(*(const __half2*)&Un[uc]);
                    float2 vf = __half22float2(*(const __half2*)&Vg[vc]);
                    float y0 = y2.x + uf.x + vf.x;
                    float y1 = y2.y + uf.y + vf.y;
                    *(__half2*)&yp[j0] = __floats2half2_rn(y0, y1);
                    s1[2*p]   += y0; s2[2*p]   += y0*y0;
                    s1[2*p+1] += y1; s2[2*p+1] += y1*y1;
                }
            }
        }

        if (tn < nTiles){
            unsigned long long* dst = sE + (cur^1)*P1_TE;
            #pragma unroll
            for (int i=0;i<7;i++){
                int idx = tid + i*256;
                if (idx < P1_TE) dst[idx] = pack_dup(pf[i]);
            }
        }
        __syncthreads();
        cur ^= 1;
    }

    float* red = (float*)sE;
    #pragma unroll 1
    for (int ci=0;ci<8;ci++){
        red[tid] = s1[ci];
        red[256+tid] = s2[ci];
        __syncthreads();
        if (tid < 32){
            float a=0.f, b=0.f;
            #pragma unroll
            for (int w=0;w<8;w++){ a += red[w*32+tid]; b += red[256+w*32+tid]; }
            int j = 2*(tid + 32*(ci>>1)) + (ci&1);
            if (j < NC){
                atomicAdd(&g_S[j],    (double)a);
                atomicAdd(&g_S[NC+j], (double)b);
            }
        }
        __syncthreads();
    }
}

// ---------------- finalize stats ----------------
__global__ void k_finalize0(int C, double invCnt)
{
    int t = threadIdx.x + blockIdx.x*blockDim.x;
    if (t >= C) return;
    double m = g_S[t]*invCnt;
    double v = g_S[C+t]*invCnt - m*m;
    g_MEAN[t] = (float)m;
    g_ISTD[t] = rsqrtf((float)v + 1e-5f);
}

__global__ void k_finalize12()
{
    int t = threadIdx.x;
    if (t < FDIM){
        double m = g_SA[t] * (1.0/(double)N_ATOM);
        double v = g_SA[FDIM+t] * (1.0/(double)N_ATOM) - m*m;
        g_MEANA[t] = (float)m;
        g_ISTDA[t] = rsqrtf((float)v + 1e-5f);
    } else if (t >= 64 && t < 64+EDIMM){
        int c = t-64;
        double m = g_SG[c] * (1.0/(double)N_ROW);
        double v = g_SG[EDIMM+c] * (1.0/(double)N_ROW) - m*m;
        g_MEANG[c] = (float)m;
        g_ISTDG[c] = rsqrtf((float)v + 1e-5f);
    }
}

// ---------------- pass2 (layer) ----------------
__global__ void __launch_bounds__(128) k_pass2_layer()
{
    int t = threadIdx.x;
    bool isNode = t < 64;
    bool isEdge = (t >= 64 && t < 105);
    float m1=0.f,i1=0.f,m2=0.f,i2=0.f;
    int c = 0;
    if (isNode){ c=t;    m1=g_MEAN[c];     i1=g_ISTD[c];     m2=g_MEAN[64+c];  i2=g_ISTD[64+c]; }
    else if (isEdge){ c=t-64; m1=g_MEAN[128+c]; i1=g_ISTD[128+c]; m2=g_MEAN[169+c]; i2=g_ISTD[169+c]; }
    float st1=0.f, st2=0.f;
    for (int n = blockIdx.x; n < N_ATOM; n += gridDim.x){
        if (isNode){
            float a = 0.f;
            #pragma unroll
            for (int m=0;m<M_NBR;m++){
                size_t row = (size_t)(n*M_NBR+m);
                float y1 = (__half2float(g_Yh[row*NC_L + c])      - m1)*i1;
                float y2 = (__half2float(g_Yh[row*NC_L + 64 + c]) - m2)*i2;
                a += sigm(y1)*lrelu(y2);
            }
            g_AGGR[n*64 + c] = a;
            st1 += a; st2 += a*a;
        } else if (isEdge){
            #pragma unroll
            for (int m=0;m<M_NBR;m++){
                size_t row = (size_t)(n*M_NBR+m);
                float y1 = (__half2float(g_Yh[row*NC_L + 128 + c]) - m1)*i1;
                float y2 = (__half2float(g_Yh[row*NC_L + 169 + c]) - m2)*i2;
                float gv = sigm(y1)*lrelu(y2);
                g_G[row*EDIMM + c] = gv;
                st1 += gv; st2 += gv*gv;
            }
        }
    }
    if (isNode){ atomicAdd(&g_SA[c], (double)st1); atomicAdd(&g_SA[64+c], (double)st2); }
    else if (isEdge){ atomicAdd(&g_SG[c], (double)st1); atomicAdd(&g_SG[41+c], (double)st2); }
}

__global__ void k_node_update()
{
    int idx = blockIdx.x*blockDim.x + threadIdx.x;
    if (idx >= N_ATOM*FDIM) return;
    int c = idx & 63;
    float v = g_NODE[idx] + (g_AGGR[idx] - g_MEANA[c]) * g_ISTDA[c];
    g_NODE[idx] = lrelu(v);
}

__global__ void k_edge_update(const float* __restrict__ Ein, int useG)
{
    size_t idx = (size_t)blockIdx.x*blockDim.x + threadIdx.x;
    if (idx >= (size_t)N_ROW*EDIMM) return;
    int c = (int)(idx % EDIMM);
    float e = useG ? g_EDGE[idx] : Ein[idx];
    float v = e + (g_G[idx] - g_MEANG[c]) * g_ISTDG[c];
    g_EDGE[idx] = lrelu(v);
}

// ---------------- pass2 (head): half2 loads, fast softplus ----------------
__global__ void __launch_bounds__(256) k_pass2_head(float* __restrict__ out)
{
    int warp = threadIdx.x >> 5, lane = threadIdx.x & 31;
    size_t r = (size_t)blockIdx.x*8 + warp;
    if (r >= N_ROW) return;
    float dist = g_DIST[r];
    float bd = 0.f, bc = 0.f;
    const __half* y = g_Yh + r*NC_H;
    #pragma unroll
    for (int i=0;i<4;i++){
        int c2 = 2*lane + 64*i;
        float2 f = __half22float2(*(const __half2*)&y[c2]);
        float v0 = (f.x - g_MEAN[c2])   * g_ISTD[c2];
        float v1 = (f.y - g_MEAN[c2+1]) * g_ISTD[c2+1];
        if (i < 2){ bd += softplus(v0 + dist) + softplus(v1 + dist); }
        else      { bc += softplus(v0) + softplus(v1); }
    }
    #pragma unroll
    for (int o=16;o>0;o>>=1){
        bd += __shfl_down_sync(0xffffffffu, bd, o);
        bc += __shfl_down_sync(0xffffffffu, bc, o);
    }
    if (lane==0){
        out[r*2]   = bd * (1.f/128.f);
        out[r*2+1] = bc * (1.f/128.f) * (1.f/(float)N_ATOM);
    }
}

// ---------------- host orchestration ----------------
extern "C" void kernel_launch(void* const* d_in, const int* in_sizes, int n_in,
                              void* d_out, int out_size)
{
    const float* node_fea = (const float*)d_in[0];
    const float* edge_fea = (const float*)d_in[1];
    const float* nbr_off  = (const float*)d_in[2];
    const float* atom_pos = (const float*)d_in[3];
    const float* cells    = (const float*)d_in[4];
    const int*   eidx     = (const int*)  d_in[5];
    const float* W_emb = (const float*)d_in[6];
    const float* b_emb = (const float*)d_in[7];
    const float* W_pn  = (const float*)d_in[8];
    const float* b_pn  = (const float*)d_in[9];
    const float* W_pe  = (const float*)d_in[10];
    const float* b_pe  = (const float*)d_in[11];
    const float* W_d   = (const float*)d_in[12];
    const float* b_d   = (const float*)d_in[13];
    const float* W_c   = (const float*)d_in[14];
    const float* b_c   = (const float*)d_in[15];
    float* out = (float*)d_out;

    // opt-in to >48KB dynamic shared memory for pass1 (idempotent, capture-legal)
    cudaFuncSetAttribute(k_pass1<NC_L,9>, cudaFuncAttributeMaxDynamicSharedMemorySize, P1_DSMB);
    cudaFuncSetAttribute(k_pass1<NC_H,0>, cudaFuncAttributeMaxDynamicSharedMemorySize, P1_DSMB);

    k_dist<<<(N_ROW+255)/256, 256>>>(nbr_off, atom_pos, cells, eidx);
    k_gemm_emb<<<(N_ATOM+63)/64, 256>>>(node_fea, W_emb, b_emb, N_ATOM, OFD, FDIM);

    for (int l=0;l<3;l++){
        int useG = (l>0) ? 1 : 0;
        k_pack_layer<<<64,256>>>(W_pn + (size_t)l*169*128, b_pn + l*128,
                                 W_pe + (size_t)l*169*82,  b_pe + l*82);
        k_gemm_uv<<<dim3((N_ATOM+127)/128, (UVS_L+127)/128), 256>>>(UVS_L);
        k_pass1<NC_L,9><<<1184,256,P1_DSMB>>>(edge_fea, useG, eidx, UVS_L);
        k_finalize0<<<1,256>>>(NC_L, 1.0/(double)N_ROW);
        k_pass2_layer<<<2368,128>>>();
        k_finalize12<<<1,128>>>();
        k_node_update<<<(N_ATOM*FDIM+255)/256,256>>>();
        k_edge_update<<<(int)(((size_t)N_ROW*EDIMM+255)/256),256>>>(edge_fea, useG);
    }

    k_pack_head<<<64,256>>>(W_d, b_d, W_c, b_c);
    k_gemm_uv<<<dim3((N_ATOM+127)/128, (UVS_H+127)/128), 256>>>(UVS_H);
    k_pass1<NC_H,0><<<1184,256,P1_DSMB>>>(edge_fea, 1, eidx, UVS_H);
    k_finalize0<<<1,256>>>(NC_H, 1.0/(double)N_ROW);
    k_pass2_head<<<(int)((N_ROW+7)/8), 256>>>(out);
}

// round 13
// speedup vs baseline: 1.3140x; 1.0095x over previous
#include <cuda_runtime.h>
#include <cuda_fp16.h>
#include <math.h>

#define N_ATOM  50000
#define M_NBR   12
#define N_ROW   600000
#define OFD     92
#define FDIM    64
#define EDIMM   41
#define NC_L    210
#define NC_H    256
#define UVS_L   420
#define UVS_H   512

// ---------------- scratch (device globals; no runtime allocation) ----------------
__device__ __align__(16) __half g_Yh[(size_t)N_ROW * NC_H];    // fp16 pre-activations
__device__ __align__(16) __half g_Gh[(size_t)N_ROW * EDIMM];   // fp16 edge gate values
__device__ __align__(16) __half g_EDGEh[(size_t)N_ROW * EDIMM];// fp16 current edge features
__device__ __align__(16) float  g_NODE[N_ATOM * FDIM];
__device__ __align__(16) float  g_AGGR[N_ATOM * FDIM];
__device__ __align__(16) __half g_UVh[(size_t)N_ATOM * UVS_H]; // fp16 UV table
__device__ __align__(16) float  g_WP[FDIM * UVS_H];
__device__ __align__(16) float  g_BP[UVS_H];
__device__ __align__(16) float  g_EW[EDIMM * NC_H];
__device__ __align__(16) float  g_DIST[N_ROW];
__device__ double g_S[2 * NC_H];
__device__ double g_SA[2 * FDIM];
__device__ double g_SG[2 * EDIMM];
__device__ float  g_MEAN[NC_H], g_ISTD[NC_H];
__device__ float  g_MEANA[FDIM], g_ISTDA[FDIM];
__device__ float  g_MEANG[EDIMM], g_ISTDG[EDIMM];

__device__ __forceinline__ float lrelu(float x){ return x > 0.f ? x : 0.01f*x; }
__device__ __forceinline__ float sigm(float x){ return __fdividef(1.f, 1.f + __expf(-x)); }
__device__ __forceinline__ float softplus(float x){
    return fmaxf(x,0.f) + __logf(1.f + __expf(-fabsf(x)));
}

// ---------------- packed f32x2 helpers (sm_103a FFMA2 via PTX) ----------------
__device__ __forceinline__ unsigned long long pack_dup(float x){
    unsigned long long r; unsigned int xi = __float_as_uint(x);
    asm("mov.b64 %0, {%1, %1};" : "=l"(r) : "r"(xi));
    return r;
}
__device__ __forceinline__ unsigned long long pack2(float lo, float hi){
    unsigned long long r;
    asm("mov.b64 %0, {%1, %2};" : "=l"(r) : "r"(__float_as_uint(lo)), "r"(__float_as_uint(hi)));
    return r;
}
__device__ __forceinline__ void fma2(unsigned long long &d, unsigned long long a, unsigned long long b){
    asm("fma.rn.f32x2 %0, %1, %2, %0;" : "+l"(d) : "l"(a), "l"(b));
}
__device__ __forceinline__ float2 unpack2(unsigned long long v){
    unsigned int lo, hi;
    asm("mov.b64 {%0, %1}, %2;" : "=r"(lo), "=r"(hi) : "l"(v));
    float2 f; f.x = __uint_as_float(lo); f.y = __uint_as_float(hi); return f;
}

// ---------------- distance ----------------
__global__ void k_dist(const float* __restrict__ nbr, const float* __restrict__ pos,
                       const float* __restrict__ cells, const int* __restrict__ eidx)
{
    int r = blockIdx.x*blockDim.x + threadIdx.x;
    if (r >= N_ROW) return;
    int n = r / M_NBR;
    float o0=nbr[r*3], o1=nbr[r*3+1], o2=nbr[r*3+2];
    const float* c = cells + (size_t)n*9;
    int g = eidx[r];
    float dd = 1e-12f;
    #pragma unroll
    for (int j=0;j<3;j++){
        float off = o0*c[j] + o1*c[3+j] + o2*c[6+j];
        float d = pos[g*3+j] + off - pos[n*3+j];
        dd += d*d;
    }
    g_DIST[r] = sqrtf(dd);
}

// ---------------- embedding GEMM: g_NODE = node_fea @ W_emb + b_emb ----------------
__global__ void __launch_bounds__(256) k_gemm_emb(const float* __restrict__ A,
                                                  const float* __restrict__ B,
                                                  const float* __restrict__ bias,
                                                  int Nrows, int K, int Ncols)
{
    __shared__ float As[64*32];
    __shared__ float Bs[32*128];
    int tid = threadIdx.x;
    int colT = tid & 31, rowT = tid >> 5;
    int r0 = blockIdx.x*64;
    float acc[8][4];
    #pragma unroll
    for (int ri=0;ri<8;ri++)
        #pragma unroll
        for (int ci=0;ci<4;ci++) acc[ri][ci]=0.f;

    for (int k0=0;k0<K;k0+=32){
        for (int i=tid;i<64*32;i+=256){
            int rr=i>>5, kk=i&31; int gr=r0+rr, gk=k0+kk;
            As[i] = (gr<Nrows && gk<K)? A[(size_t)gr*K+gk] : 0.f;
        }
        for (int i=tid;i<32*128;i+=256){
            int kk=i>>7, jj=i&127; int gk=k0+kk;
            Bs[i] = (gk<K && jj<Ncols)? B[(size_t)gk*Ncols+jj] : 0.f;
        }
        __syncthreads();
        #pragma unroll 4
        for (int kk=0;kk<32;kk++){
            float a[8];
            #pragma unroll
            for (int ri=0;ri<8;ri++) a[ri]=As[(rowT+8*ri)*32+kk];
            #pragma unroll
            for (int ci=0;ci<4;ci++){
                float b=Bs[kk*128 + colT + 32*ci];
                #pragma unroll
                for (int ri=0;ri<8;ri++) acc[ri][ci] = fmaf(a[ri], b, acc[ri][ci]);
            }
        }
        __syncthreads();
    }
    #pragma unroll
    for (int ri=0;ri<8;ri++){
        int gr=r0+rowT+8*ri;
        if (gr >= Nrows) continue;
        #pragma unroll
        for (int ci=0;ci<4;ci++){
            int gj=colT+32*ci;
            if (gj < Ncols) g_NODE[(size_t)gr*Ncols+gj] = acc[ri][ci] + bias[gj];
        }
    }
}

// ---------------- UV GEMM (f32x2): g_UVh = fp16( g_NODE @ g_WP + g_BP ) ----------------
__global__ void __launch_bounds__(256) k_gemm_uv(int Ncols)
{
    __shared__ __align__(16) float As[16][128];
    __shared__ __align__(16) float Bs[16][128];
    int tid = threadIdx.x;
    int tx = tid & 15, ty = tid >> 4;
    int r0 = blockIdx.x*128, c0 = blockIdx.y*128;
    unsigned long long acc2[8][4];
    #pragma unroll
    for (int i=0;i<8;i++)
        #pragma unroll
        for (int p=0;p<4;p++) acc2[i][p]=0ull;

    for (int k0=0;k0<FDIM;k0+=16){
        #pragma unroll
        for (int h=0;h<2;h++){
            int arow = (tid>>2) + h*64;
            int acol = (tid&3)*4;
            float4 v = make_float4(0.f,0.f,0.f,0.f);
            int gr = r0 + arow;
            if (gr < N_ATOM) v = *(const float4*)&g_NODE[(size_t)gr*FDIM + k0 + acol];
            As[acol+0][arow]=v.x; As[acol+1][arow]=v.y; As[acol+2][arow]=v.z; As[acol+3][arow]=v.w;
        }
        #pragma unroll
        for (int h=0;h<2;h++){
            int brow = (tid>>5) + h*8;
            int bcol = (tid&31)*4;
            float4 v = make_float4(0.f,0.f,0.f,0.f);
            if (c0 + bcol < Ncols) v = *(const float4*)&g_WP[(size_t)(k0+brow)*Ncols + c0 + bcol];
            *(float4*)&Bs[brow][bcol] = v;
        }
        __syncthreads();
        #pragma unroll
        for (int kk=0;kk<16;kk++){
            float a[8];
            *(float4*)&a[0] = *(const float4*)&As[kk][ty*8];
            *(float4*)&a[4] = *(const float4*)&As[kk][ty*8+4];
            unsigned long long bp[4];
            #pragma unroll
            for (int p=0;p<4;p++) bp[p] = *(const unsigned long long*)&Bs[kk][tx*8 + 2*p];
            #pragma unroll
            for (int i=0;i<8;i++){
                unsigned long long ap = pack_dup(a[i]);
                #pragma unroll
                for (int p=0;p<4;p++) fma2(acc2[i][p], ap, bp[p]);
            }
        }
        __syncthreads();
    }
    #pragma unroll
    for (int ri=0;ri<8;ri++){
        int gr = r0 + ty*8 + ri;
        if (gr >= N_ATOM) continue;
        #pragma unroll
        for (int cj=0;cj<2;cj++){
            int gj = c0 + tx*8 + cj*4;
            if (gj < Ncols){
                float4 bv = *(const float4*)&g_BP[gj];
                float2 v0 = unpack2(acc2[ri][cj*2+0]);
                float2 v1 = unpack2(acc2[ri][cj*2+1]);
                __half2 h0 = __floats2half2_rn(v0.x + bv.x, v0.y + bv.y);
                __half2 h1 = __floats2half2_rn(v1.x + bv.z, v1.y + bv.w);
                uint2 st;
                st.x = *reinterpret_cast<unsigned int*>(&h0);
                st.y = *reinterpret_cast<unsigned int*>(&h1);
                *(uint2*)&g_UVh[(size_t)gr*Ncols + gj] = st;
            }
        }
    }
}

// ---------------- weight packing (+ stat zeroing) ----------------
__global__ void k_pack_layer(const float* __restrict__ Wn, const float* __restrict__ bn,
                             const float* __restrict__ We, const float* __restrict__ be)
{
    int stride = gridDim.x*blockDim.x;
    int t0 = blockIdx.x*blockDim.x + threadIdx.x;
    for (int idx=t0; idx<FDIM*UVS_L; idx+=stride){
        int k = idx / UVS_L, j = idx % UVS_L;
        float v;
        if (j<128)       v = Wn[k*128 + j];
        else if (j<256)  v = Wn[(64+k)*128 + (j-128)];
        else if (j<338)  v = We[k*82 + (j-256)];
        else             v = We[(64+k)*82 + (j-338)];
        g_WP[idx] = v;
    }
    for (int j=t0;j<UVS_L;j+=stride){
        float v = 0.f;
        if (j<128) v = bn[j];
        else if (j>=256 && j<338) v = be[j-256];
        g_BP[j]=v;
    }
    for (int idx=t0;idx<EDIMM*NC_L;idx+=stride){
        int k=idx/NC_L, j=idx%NC_L;
        g_EW[idx] = (j<128)? Wn[(128+k)*128 + j] : We[(128+k)*82 + (j-128)];
    }
    if (t0 < 2*NC_H)  g_S[t0]=0.0;
    if (t0 < 2*FDIM)  g_SA[t0]=0.0;
    if (t0 < 2*EDIMM) g_SG[t0]=0.0;
}

__global__ void k_pack_head(const float* __restrict__ Wd, const float* __restrict__ bd,
                            const float* __restrict__ Wc, const float* __restrict__ bc)
{
    int stride = gridDim.x*blockDim.x;
    int t0 = blockIdx.x*blockDim.x + threadIdx.x;
    for (int idx=t0; idx<FDIM*UVS_H; idx+=stride){
        int k = idx / UVS_H, j = idx % UVS_H;
        float v;
        if (j<128)       v = Wd[k*128 + j];
        else if (j<256)  v = Wd[(64+k)*128 + (j-128)];
        else if (j<384)  v = Wc[k*128 + (j-256)];
        else             v = Wc[(64+k)*128 + (j-384)];
        g_WP[idx] = v;
    }
    for (int j=t0;j<UVS_H;j+=stride){
        float v = 0.f;
        if (j<128) v = bd[j];
        else if (j>=256 && j<384) v = bc[j-256];
        g_BP[j]=v;
    }
    for (int idx=t0;idx<EDIMM*NC_H;idx+=stride){
        int k=idx/NC_H, j=idx%NC_H;
        g_EW[idx] = (j<128)? Wd[(128+k)*128 + j] : Wc[(128+k)*128 + (j-128)];
    }
    if (t0 < 2*NC_H) g_S[t0]=0.0;
}

// ---------------- pass1 v6: f32x2, adjacent pairs, dup-E smem, double-buffered, fp16 E/UV/Y ----
#define P1_TR   40
#define P1_TE   (P1_TR*EDIMM)   // 1640
#define P1_DSMB ((EDIMM*128 + 2*P1_TE)*8)

template<int NC, int TAILN>
__global__ void __launch_bounds__(256,2) k_pass1(const float* __restrict__ Ein, int useG,
                                                 const int* __restrict__ eidx, int uvS)
{
    extern __shared__ unsigned long long dsm[];
    unsigned long long* sWp = dsm;                 // [EDIMM][128] adjacent column-pairs
    unsigned long long* sE  = dsm + EDIMM*128;     // 2 x [P1_TR][EDIMM] duplicated e
    const int tid = threadIdx.x;
    const int colT = tid & 31, rowT = tid >> 5;
    const int gs = gridDim.x;
    const int nTiles = N_ROW / P1_TR;

    for (int idx = tid; idx < EDIMM*128; idx += 256){
        int k = idx >> 7, q = idx & 127;
        int j0 = 2*q;
        float lo = 0.f, hi = 0.f;
        if (j0 < NC){ lo = g_EW[k*NC + j0]; hi = g_EW[k*NC + j0 + 1]; }
        sWp[idx] = pack2(lo, hi);
    }

    {
        int t0i = blockIdx.x;
        if (t0i < nTiles){
            size_t base = (size_t)t0i*P1_TE;
            for (int i=tid;i<P1_TE;i+=256){
                float e = useG ? __half2float(g_EDGEh[base + i]) : Ein[base + i];
                sE[i] = pack_dup(e);
            }
        }
    }
    __syncthreads();

    float s1[8], s2[8];
    #pragma unroll
    for (int ci=0;ci<8;ci++){ s1[ci]=0.f; s2[ci]=0.f; }

    int cur = 0;
    for (int t = blockIdx.x; t < nTiles; t += gs){
        float pf[7];
        int tn = t + gs;
        if (tn < nTiles){
            size_t nbase = (size_t)tn*P1_TE;
            #pragma unroll
            for (int i=0;i<7;i++){
                int idx = tid + i*256;
                if (idx < P1_TE)
                    pf[i] = useG ? __half2float(g_EDGEh[nbase + idx]) : Ein[nbase + idx];
            }
        }

        int r0 = t*P1_TR;
        unsigned long long acc2[5][4];
        #pragma unroll
        for (int ri=0;ri<5;ri++)
            #pragma unroll
            for (int p=0;p<4;p++) acc2[ri][p]=0ull;

        const unsigned long long* pE = sE + cur*P1_TE + rowT*5*EDIMM;
        const unsigned long long* pW = sWp + colT;
        #pragma unroll 2
        for (int k=0;k<EDIMM;k++){
            unsigned long long evp[5];
            #pragma unroll
            for (int ri=0;ri<5;ri++) evp[ri] = pE[ri*EDIMM + k];
            unsigned long long wp[4];
            #pragma unroll
            for (int p=0;p<4;p++) wp[p] = pW[k*128 + 32*p];
            #pragma unroll
            for (int p=0;p<4;p++)
                #pragma unroll
                for (int ri=0;ri<5;ri++) fma2(acc2[ri][p], evp[ri], wp[p]);
        }
        #pragma unroll
        for (int ri=0;ri<5;ri++){
            int row = r0 + rowT*5 + ri;
            int n  = row / M_NBR;
            int gg = __ldg(&eidx[row]);
            const __half* Un = g_UVh + (size_t)n*uvS;
            const __half* Vg = g_UVh + (size_t)gg*uvS;
            __half* yp = g_Yh + (size_t)row*NC;
            #pragma unroll
            for (int p=0;p<4;p++){
                if (NC == 256 || p < 3 || colT < TAILN){
                    int j0 = 2*(colT + 32*p);
                    float2 y2 = unpack2(acc2[ri][p]);
                    int uc = (j0<128)? j0        : j0+128;
                    int vc = (j0<128)? (j0+128)  : j0+NC;
                    float2 uf = __half22float2(*(const __half2*)&Un[uc]);
                    float2 vf = __half22float2(*(const __half2*)&Vg[vc]);
                    float y0 = y2.x + uf.x + vf.x;
                    float y1 = y2.y + uf.y + vf.y;
                    *(__half2*)&yp[j0] = __floats2half2_rn(y0, y1);
                    s1[2*p]   += y0; s2[2*p]   += y0*y0;
                    s1[2*p+1] += y1; s2[2*p+1] += y1*y1;
                }
            }
        }

        if (tn < nTiles){
            unsigned long long* dst = sE + (cur^1)*P1_TE;
            #pragma unroll
            for (int i=0;i<7;i++){
                int idx = tid + i*256;
                if (idx < P1_TE) dst[idx] = pack_dup(pf[i]);
            }
        }
        __syncthreads();
        cur ^= 1;
    }

    float* red = (float*)sE;
    #pragma unroll 1
    for (int ci=0;ci<8;ci++){
        red[tid] = s1[ci];
        red[256+tid] = s2[ci];
        __syncthreads();
        if (tid < 32){
            float a=0.f, b=0.f;
            #pragma unroll
            for (int w=0;w<8;w++){ a += red[w*32+tid]; b += red[256+w*32+tid]; }
            int j = 2*(tid + 32*(ci>>1)) + (ci&1);
            if (j < NC){
                atomicAdd(&g_S[j],    (double)a);
                atomicAdd(&g_S[NC+j], (double)b);
            }
        }
        __syncthreads();
    }
}

// ---------------- finalize stats ----------------
__global__ void k_finalize0(int C, double invCnt)
{
    int t = threadIdx.x + blockIdx.x*blockDim.x;
    if (t >= C) return;
    double m = g_S[t]*invCnt;
    double v = g_S[C+t]*invCnt - m*m;
    g_MEAN[t] = (float)m;
    g_ISTD[t] = rsqrtf((float)v + 1e-5f);
}

__global__ void k_finalize12()
{
    int t = threadIdx.x;
    if (t < FDIM){
        double m = g_SA[t] * (1.0/(double)N_ATOM);
        double v = g_SA[FDIM+t] * (1.0/(double)N_ATOM) - m*m;
        g_MEANA[t] = (float)m;
        g_ISTDA[t] = rsqrtf((float)v + 1e-5f);
    } else if (t >= 64 && t < 64+EDIMM){
        int c = t-64;
        double m = g_SG[c] * (1.0/(double)N_ROW);
        double v = g_SG[EDIMM+c] * (1.0/(double)N_ROW) - m*m;
        g_MEANG[c] = (float)m;
        g_ISTDG[c] = rsqrtf((float)v + 1e-5f);
    }
}

// ---------------- pass2 (layer) ----------------
__global__ void __launch_bounds__(128) k_pass2_layer()
{
    int t = threadIdx.x;
    bool isNode = t < 64;
    bool isEdge = (t >= 64 && t < 105);
    float m1=0.f,i1=0.f,m2=0.f,i2=0.f;
    int c = 0;
    if (isNode){ c=t;    m1=g_MEAN[c];     i1=g_ISTD[c];     m2=g_MEAN[64+c];  i2=g_ISTD[64+c]; }
    else if (isEdge){ c=t-64; m1=g_MEAN[128+c]; i1=g_ISTD[128+c]; m2=g_MEAN[169+c]; i2=g_ISTD[169+c]; }
    float st1=0.f, st2=0.f;
    for (int n = blockIdx.x; n < N_ATOM; n += gridDim.x){
        if (isNode){
            float a = 0.f;
            #pragma unroll
            for (int m=0;m<M_NBR;m++){
                size_t row = (size_t)(n*M_NBR+m);
                float y1 = (__half2float(g_Yh[row*NC_L + c])      - m1)*i1;
                float y2 = (__half2float(g_Yh[row*NC_L + 64 + c]) - m2)*i2;
                a += sigm(y1)*lrelu(y2);
            }
            g_AGGR[n*64 + c] = a;
            st1 += a; st2 += a*a;
        } else if (isEdge){
            #pragma unroll
            for (int m=0;m<M_NBR;m++){
                size_t row = (size_t)(n*M_NBR+m);
                float y1 = (__half2float(g_Yh[row*NC_L + 128 + c]) - m1)*i1;
                float y2 = (__half2float(g_Yh[row*NC_L + 169 + c]) - m2)*i2;
                float gv = sigm(y1)*lrelu(y2);
                g_Gh[row*EDIMM + c] = __float2half_rn(gv);
                st1 += gv; st2 += gv*gv;
            }
        }
    }
    if (isNode){ atomicAdd(&g_SA[c], (double)st1); atomicAdd(&g_SA[64+c], (double)st2); }
    else if (isEdge){ atomicAdd(&g_SG[c], (double)st1); atomicAdd(&g_SG[41+c], (double)st2); }
}

__global__ void k_node_update()
{
    int idx = blockIdx.x*blockDim.x + threadIdx.x;
    if (idx >= N_ATOM*FDIM) return;
    int c = idx & 63;
    float v = g_NODE[idx] + (g_AGGR[idx] - g_MEANA[c]) * g_ISTDA[c];
    g_NODE[idx] = lrelu(v);
}

// ---------------- edge update: half2-vectorized, 2 elems/thread ----------------
__global__ void k_edge_update(const float* __restrict__ Ein, int useG)
{
    size_t i2 = (size_t)blockIdx.x*blockDim.x + threadIdx.x;
    size_t idx = i2 * 2;
    if (idx >= (size_t)N_ROW*EDIMM) return;
    int c0 = (int)(idx % EDIMM);
    int c1 = c0 + 1 >= EDIMM ? 0 : c0 + 1;
    float2 g = __half22float2(*(const __half2*)&g_Gh[idx]);
    float e0, e1;
    if (useG){
        float2 e = __half22float2(*(const __half2*)&g_EDGEh[idx]);
        e0 = e.x; e1 = e.y;
    } else {
        float2 e = *(const float2*)&Ein[idx];
        e0 = e.x; e1 = e.y;
    }
    float v0 = lrelu(e0 + (g.x - g_MEANG[c0]) * g_ISTDG[c0]);
    float v1 = lrelu(e1 + (g.y - g_MEANG[c1]) * g_ISTDG[c1]);
    *(__half2*)&g_EDGEh[idx] = __floats2half2_rn(v0, v1);
}

// ---------------- pass2 (head): half2 loads, fast softplus ----------------
__global__ void __launch_bounds__(256) k_pass2_head(float* __restrict__ out)
{
    int warp = threadIdx.x >> 5, lane = threadIdx.x & 31;
    size_t r = (size_t)blockIdx.x*8 + warp;
    if (r >= N_ROW) return;
    float dist = g_DIST[r];
    float bd = 0.f, bc = 0.f;
    const __half* y = g_Yh + r*NC_H;
    #pragma unroll
    for (int i=0;i<4;i++){
        int c2 = 2*lane + 64*i;
        float2 f = __half22float2(*(const __half2*)&y[c2]);
        float v0 = (f.x - g_MEAN[c2])   * g_ISTD[c2];
        float v1 = (f.y - g_MEAN[c2+1]) * g_ISTD[c2+1];
        if (i < 2){ bd += softplus(v0 + dist) + softplus(v1 + dist); }
        else      { bc += softplus(v0) + softplus(v1); }
    }
    #pragma unroll
    for (int o=16;o>0;o>>=1){
        bd += __shfl_down_sync(0xffffffffu, bd, o);
        bc += __shfl_down_sync(0xffffffffu, bc, o);
    }
    if (lane==0){
        out[r*2]   = bd * (1.f/128.f);
        out[r*2+1] = bc * (1.f/128.f) * (1.f/(float)N_ATOM);
    }
}

// ---------------- host orchestration ----------------
extern "C" void kernel_launch(void* const* d_in, const int* in_sizes, int n_in,
                              void* d_out, int out_size)
{
    const float* node_fea = (const float*)d_in[0];
    const float* edge_fea = (const float*)d_in[1];
    const float* nbr_off  = (const float*)d_in[2];
    const float* atom_pos = (const float*)d_in[3];
    const float* cells    = (const float*)d_in[4];
    const int*   eidx     = (const int*)  d_in[5];
    const float* W_emb = (const float*)d_in[6];
    const float* b_emb = (const float*)d_in[7];
    const float* W_pn  = (const float*)d_in[8];
    const float* b_pn  = (const float*)d_in[9];
    const float* W_pe  = (const float*)d_in[10];
    const float* b_pe  = (const float*)d_in[11];
    const float* W_d   = (const float*)d_in[12];
    const float* b_d   = (const float*)d_in[13];
    const float* W_c   = (const float*)d_in[14];
    const float* b_c   = (const float*)d_in[15];
    float* out = (float*)d_out;

    // opt-in to >48KB dynamic shared memory for pass1 (idempotent, capture-legal)
    cudaFuncSetAttribute(k_pass1<NC_L,9>, cudaFuncAttributeMaxDynamicSharedMemorySize, P1_DSMB);
    cudaFuncSetAttribute(k_pass1<NC_H,0>, cudaFuncAttributeMaxDynamicSharedMemorySize, P1_DSMB);

    k_dist<<<(N_ROW+255)/256, 256>>>(nbr_off, atom_pos, cells, eidx);
    k_gemm_emb<<<(N_ATOM+63)/64, 256>>>(node_fea, W_emb, b_emb, N_ATOM, OFD, FDIM);

    const size_t nEl2 = ((size_t)N_ROW*EDIMM)/2;
    for (int l=0;l<3;l++){
        int useG = (l>0) ? 1 : 0;
        k_pack_layer<<<64,256>>>(W_pn + (size_t)l*169*128, b_pn + l*128,
                                 W_pe + (size_t)l*169*82,  b_pe + l*82);
        k_gemm_uv<<<dim3((N_ATOM+127)/128, (UVS_L+127)/128), 256>>>(UVS_L);
        k_pass1<NC_L,9><<<1184,256,P1_DSMB>>>(edge_fea, useG, eidx, UVS_L);
        k_finalize0<<<1,256>>>(NC_L, 1.0/(double)N_ROW);
        k_pass2_layer<<<2368,128>>>();
        k_finalize12<<<1,128>>>();
        k_node_update<<<(N_ATOM*FDIM+255)/256,256>>>();
        k_edge_update<<<(int)((nEl2+255)/256),256>>>(edge_fea, useG);
    }

    k_pack_head<<<64,256>>>(W_d, b_d, W_c, b_c);
    k_gemm_uv<<<dim3((N_ATOM+127)/128, (UVS_H+127)/128), 256>>>(UVS_H);
    k_pass1<NC_H,0><<<1184,256,P1_DSMB>>>(edge_fea, 1, eidx, UVS_H);
    k_finalize0<<<1,256>>>(NC_H, 1.0/(double)N_ROW);
    k_pass2_head<<<(int)((N_ROW+7)/8), 256>>>(out);
}

// round 14
// speedup vs baseline: 1.4005x; 1.0658x over previous
#include <cuda_runtime.h>
#include <cuda_fp16.h>
#include <math.h>

#define N_ATOM  50000
#define M_NBR   12
#define N_ROW   600000
#define OFD     92
#define FDIM    64
#define EDIMM   41
#define NC_L    210
#define NC_H    256
#define UVS_L   420
#define UVS_H   512

// ---------------- scratch (device globals; no runtime allocation) ----------------
__device__ __align__(16) __half g_Yh[(size_t)N_ROW * NC_H];    // fp16 pre-activations
__device__ __align__(16) __half g_Gh[(size_t)N_ROW * EDIMM];   // fp16 edge gate values
__device__ __align__(16) __half g_EDGEh[(size_t)N_ROW * EDIMM];// fp16 current edge features
__device__ __align__(16) float  g_NODE[N_ATOM * FDIM];
__device__ __align__(16) float  g_AGGR[N_ATOM * FDIM];
__device__ __align__(16) __half g_UVh[(size_t)N_ATOM * UVS_H]; // fp16 UV table
__device__ __align__(16) float  g_WP[FDIM * UVS_H];
__device__ __align__(16) float  g_BP[UVS_H];
__device__ __align__(16) float  g_EW[EDIMM * NC_H];
__device__ __align__(16) float  g_DIST[N_ROW];
__device__ double g_S[2 * NC_H];
__device__ double g_SA[2 * FDIM];
__device__ double g_SG[2 * EDIMM];
__device__ float  g_MEAN[NC_H], g_ISTD[NC_H];
__device__ float  g_MEANA[FDIM], g_ISTDA[FDIM];
__device__ float  g_MEANG[EDIMM], g_ISTDG[EDIMM];

__device__ __forceinline__ float lrelu(float x){ return x > 0.f ? x : 0.01f*x; }
__device__ __forceinline__ float sigm(float x){ return __fdividef(1.f, 1.f + __expf(-x)); }
__device__ __forceinline__ float softplus(float x){
    return fmaxf(x,0.f) + __logf(1.f + __expf(-fabsf(x)));
}

// ---------------- packed f32x2 helpers (sm_103a FFMA2 via PTX) ----------------
__device__ __forceinline__ unsigned long long pack_dup(float x){
    unsigned long long r; unsigned int xi = __float_as_uint(x);
    asm("mov.b64 %0, {%1, %1};" : "=l"(r) : "r"(xi));
    return r;
}
__device__ __forceinline__ unsigned long long pack2(float lo, float hi){
    unsigned long long r;
    asm("mov.b64 %0, {%1, %2};" : "=l"(r) : "r"(__float_as_uint(lo)), "r"(__float_as_uint(hi)));
    return r;
}
__device__ __forceinline__ void fma2(unsigned long long &d, unsigned long long a, unsigned long long b){
    asm("fma.rn.f32x2 %0, %1, %2, %0;" : "+l"(d) : "l"(a), "l"(b));
}
__device__ __forceinline__ float2 unpack2(unsigned long long v){
    unsigned int lo, hi;
    asm("mov.b64 {%0, %1}, %2;" : "=r"(lo), "=r"(hi) : "l"(v));
    float2 f; f.x = __uint_as_float(lo); f.y = __uint_as_float(hi); return f;
}

// ---------------- distance ----------------
__global__ void k_dist(const float* __restrict__ nbr, const float* __restrict__ pos,
                       const float* __restrict__ cells, const int* __restrict__ eidx)
{
    int r = blockIdx.x*blockDim.x + threadIdx.x;
    if (r >= N_ROW) return;
    int n = r / M_NBR;
    float o0=nbr[r*3], o1=nbr[r*3+1], o2=nbr[r*3+2];
    const float* c = cells + (size_t)n*9;
    int g = eidx[r];
    float dd = 1e-12f;
    #pragma unroll
    for (int j=0;j<3;j++){
        float off = o0*c[j] + o1*c[3+j] + o2*c[6+j];
        float d = pos[g*3+j] + off - pos[n*3+j];
        dd += d*d;
    }
    g_DIST[r] = sqrtf(dd);
}

// ---------------- embedding GEMM: g_NODE = node_fea @ W_emb + b_emb ----------------
__global__ void __launch_bounds__(256) k_gemm_emb(const float* __restrict__ A,
                                                  const float* __restrict__ B,
                                                  const float* __restrict__ bias,
                                                  int Nrows, int K, int Ncols)
{
    __shared__ float As[64*32];
    __shared__ float Bs[32*128];
    int tid = threadIdx.x;
    int colT = tid & 31, rowT = tid >> 5;
    int r0 = blockIdx.x*64;
    float acc[8][4];
    #pragma unroll
    for (int ri=0;ri<8;ri++)
        #pragma unroll
        for (int ci=0;ci<4;ci++) acc[ri][ci]=0.f;

    for (int k0=0;k0<K;k0+=32){
        for (int i=tid;i<64*32;i+=256){
            int rr=i>>5, kk=i&31; int gr=r0+rr, gk=k0+kk;
            As[i] = (gr<Nrows && gk<K)? A[(size_t)gr*K+gk] : 0.f;
        }
        for (int i=tid;i<32*128;i+=256){
            int kk=i>>7, jj=i&127; int gk=k0+kk;
            Bs[i] = (gk<K && jj<Ncols)? B[(size_t)gk*Ncols+jj] : 0.f;
        }
        __syncthreads();
        #pragma unroll 4
        for (int kk=0;kk<32;kk++){
            float a[8];
            #pragma unroll
            for (int ri=0;ri<8;ri++) a[ri]=As[(rowT+8*ri)*32+kk];
            #pragma unroll
            for (int ci=0;ci<4;ci++){
                float b=Bs[kk*128 + colT + 32*ci];
                #pragma unroll
                for (int ri=0;ri<8;ri++) acc[ri][ci] = fmaf(a[ri], b, acc[ri][ci]);
            }
        }
        __syncthreads();
    }
    #pragma unroll
    for (int ri=0;ri<8;ri++){
        int gr=r0+rowT+8*ri;
        if (gr >= Nrows) continue;
        #pragma unroll
        for (int ci=0;ci<4;ci++){
            int gj=colT+32*ci;
            if (gj < Ncols) g_NODE[(size_t)gr*Ncols+gj] = acc[ri][ci] + bias[gj];
        }
    }
}

// ---------------- UV GEMM (f32x2): g_UVh = fp16( g_NODE @ g_WP + g_BP ) ----------------
__global__ void __launch_bounds__(256) k_gemm_uv(int Ncols)
{
    __shared__ __align__(16) float As[16][128];
    __shared__ __align__(16) float Bs[16][128];
    int tid = threadIdx.x;
    int tx = tid & 15, ty = tid >> 4;
    int r0 = blockIdx.x*128, c0 = blockIdx.y*128;
    unsigned long long acc2[8][4];
    #pragma unroll
    for (int i=0;i<8;i++)
        #pragma unroll
        for (int p=0;p<4;p++) acc2[i][p]=0ull;

    for (int k0=0;k0<FDIM;k0+=16){
        #pragma unroll
        for (int h=0;h<2;h++){
            int arow = (tid>>2) + h*64;
            int acol = (tid&3)*4;
            float4 v = make_float4(0.f,0.f,0.f,0.f);
            int gr = r0 + arow;
            if (gr < N_ATOM) v = *(const float4*)&g_NODE[(size_t)gr*FDIM + k0 + acol];
            As[acol+0][arow]=v.x; As[acol+1][arow]=v.y; As[acol+2][arow]=v.z; As[acol+3][arow]=v.w;
        }
        #pragma unroll
        for (int h=0;h<2;h++){
            int brow = (tid>>5) + h*8;
            int bcol = (tid&31)*4;
            float4 v = make_float4(0.f,0.f,0.f,0.f);
            if (c0 + bcol < Ncols) v = *(const float4*)&g_WP[(size_t)(k0+brow)*Ncols + c0 + bcol];
            *(float4*)&Bs[brow][bcol] = v;
        }
        __syncthreads();
        #pragma unroll
        for (int kk=0;kk<16;kk++){
            float a[8];
            *(float4*)&a[0] = *(const float4*)&As[kk][ty*8];
            *(float4*)&a[4] = *(const float4*)&As[kk][ty*8+4];
            unsigned long long bp[4];
            #pragma unroll
            for (int p=0;p<4;p++) bp[p] = *(const unsigned long long*)&Bs[kk][tx*8 + 2*p];
            #pragma unroll
            for (int i=0;i<8;i++){
                unsigned long long ap = pack_dup(a[i]);
                #pragma unroll
                for (int p=0;p<4;p++) fma2(acc2[i][p], ap, bp[p]);
            }
        }
        __syncthreads();
    }
    #pragma unroll
    for (int ri=0;ri<8;ri++){
        int gr = r0 + ty*8 + ri;
        if (gr >= N_ATOM) continue;
        #pragma unroll
        for (int cj=0;cj<2;cj++){
            int gj = c0 + tx*8 + cj*4;
            if (gj < Ncols){
                float4 bv = *(const float4*)&g_BP[gj];
                float2 v0 = unpack2(acc2[ri][cj*2+0]);
                float2 v1 = unpack2(acc2[ri][cj*2+1]);
                __half2 h0 = __floats2half2_rn(v0.x + bv.x, v0.y + bv.y);
                __half2 h1 = __floats2half2_rn(v1.x + bv.z, v1.y + bv.w);
                uint2 st;
                st.x = *reinterpret_cast<unsigned int*>(&h0);
                st.y = *reinterpret_cast<unsigned int*>(&h1);
                *(uint2*)&g_UVh[(size_t)gr*Ncols + gj] = st;
            }
        }
    }
}

// ---------------- weight packing (+ stat zeroing) ----------------
__global__ void k_pack_layer(const float* __restrict__ Wn, const float* __restrict__ bn,
                             const float* __restrict__ We, const float* __restrict__ be)
{
    int stride = gridDim.x*blockDim.x;
    int t0 = blockIdx.x*blockDim.x + threadIdx.x;
    for (int idx=t0; idx<FDIM*UVS_L; idx+=stride){
        int k = idx / UVS_L, j = idx % UVS_L;
        float v;
        if (j<128)       v = Wn[k*128 + j];
        else if (j<256)  v = Wn[(64+k)*128 + (j-128)];
        else if (j<338)  v = We[k*82 + (j-256)];
        else             v = We[(64+k)*82 + (j-338)];
        g_WP[idx] = v;
    }
    for (int j=t0;j<UVS_L;j+=stride){
        float v = 0.f;
        if (j<128) v = bn[j];
        else if (j>=256 && j<338) v = be[j-256];
        g_BP[j]=v;
    }
    for (int idx=t0;idx<EDIMM*NC_L;idx+=stride){
        int k=idx/NC_L, j=idx%NC_L;
        g_EW[idx] = (j<128)? Wn[(128+k)*128 + j] : We[(128+k)*82 + (j-128)];
    }
    if (t0 < 2*NC_H)  g_S[t0]=0.0;
    if (t0 < 2*FDIM)  g_SA[t0]=0.0;
    if (t0 < 2*EDIMM) g_SG[t0]=0.0;
}

__global__ void k_pack_head(const float* __restrict__ Wd, const float* __restrict__ bd,
                            const float* __restrict__ Wc, const float* __restrict__ bc)
{
    int stride = gridDim.x*blockDim.x;
    int t0 = blockIdx.x*blockDim.x + threadIdx.x;
    for (int idx=t0; idx<FDIM*UVS_H; idx+=stride){
        int k = idx / UVS_H, j = idx % UVS_H;
        float v;
        if (j<128)       v = Wd[k*128 + j];
        else if (j<256)  v = Wd[(64+k)*128 + (j-128)];
        else if (j<384)  v = Wc[k*128 + (j-256)];
        else             v = Wc[(64+k)*128 + (j-384)];
        g_WP[idx] = v;
    }
    for (int j=t0;j<UVS_H;j+=stride){
        float v = 0.f;
        if (j<128) v = bd[j];
        else if (j>=256 && j<384) v = bc[j-256];
        g_BP[j]=v;
    }
    for (int idx=t0;idx<EDIMM*NC_H;idx+=stride){
        int k=idx/NC_H, j=idx%NC_H;
        g_EW[idx] = (j<128)? Wd[(128+k)*128 + j] : Wc[(128+k)*128 + (j-128)];
    }
    if (t0 < 2*NC_H) g_S[t0]=0.0;
}

// ---------------- pass1 v7: column-split (gridDim.y=2), 3 blocks/SM, f32x2 pairs ------------
// Each block handles 2 pair-groups: pair q = colT + 32*p + 64*by, p in {0,1}.
// smem: sWp [EDIMM][64] pairs (21KB) + dup-E double buffer (26.2KB) = 47.2KB -> 3 blocks/SM.
#define P1_TR   40
#define P1_TE   (P1_TR*EDIMM)   // 1640
#define P1_DSMB ((EDIMM*64 + 2*P1_TE)*8)

template<int NC, int TAILN>
__global__ void __launch_bounds__(256,3) k_pass1(const float* __restrict__ Ein, int useG,
                                                 const int* __restrict__ eidx, int uvS)
{
    extern __shared__ unsigned long long dsm[];
    unsigned long long* sWp = dsm;                 // [EDIMM][64] this block's column-pairs
    unsigned long long* sE  = dsm + EDIMM*64;      // 2 x [P1_TR][EDIMM] duplicated e
    const int tid = threadIdx.x;
    const int colT = tid & 31, rowT = tid >> 5;
    const int by = blockIdx.y;                     // 0 or 1: column half
    const int gs = gridDim.x;
    const int nTiles = N_ROW / P1_TR;

    // pack this half's weights as adjacent column pairs, zero-padded
    for (int idx = tid; idx < EDIMM*64; idx += 256){
        int k = idx >> 6, qq = idx & 63;
        int j0 = 2*(64*by + qq);
        float lo = 0.f, hi = 0.f;
        if (j0 < NC){ lo = g_EW[k*NC + j0]; hi = g_EW[k*NC + j0 + 1]; }
        sWp[idx] = pack2(lo, hi);
    }

    {
        int t0i = blockIdx.x;
        if (t0i < nTiles){
            size_t base = (size_t)t0i*P1_TE;
            for (int i=tid;i<P1_TE;i+=256){
                float e = useG ? __half2float(g_EDGEh[base + i]) : Ein[base + i];
                sE[i] = pack_dup(e);
            }
        }
    }
    __syncthreads();

    float s1[4], s2[4];
    #pragma unroll
    for (int ci=0;ci<4;ci++){ s1[ci]=0.f; s2[ci]=0.f; }

    int cur = 0;
    for (int t = blockIdx.x; t < nTiles; t += gs){
        float pf[7];
        int tn = t + gs;
        if (tn < nTiles){
            size_t nbase = (size_t)tn*P1_TE;
            #pragma unroll
            for (int i=0;i<7;i++){
                int idx = tid + i*256;
                if (idx < P1_TE)
                    pf[i] = useG ? __half2float(g_EDGEh[nbase + idx]) : Ein[nbase + idx];
            }
        }

        int r0 = t*P1_TR;
        unsigned long long acc2[5][2];
        #pragma unroll
        for (int ri=0;ri<5;ri++)
            #pragma unroll
            for (int p=0;p<2;p++) acc2[ri][p]=0ull;

        const unsigned long long* pE = sE + cur*P1_TE + rowT*5*EDIMM;
        const unsigned long long* pW = sWp + colT;
        #pragma unroll 2
        for (int k=0;k<EDIMM;k++){
            unsigned long long evp[5];
            #pragma unroll
            for (int ri=0;ri<5;ri++) evp[ri] = pE[ri*EDIMM + k];
            unsigned long long w0 = pW[k*64];
            unsigned long long w1 = pW[k*64 + 32];
            #pragma unroll
            for (int ri=0;ri<5;ri++) fma2(acc2[ri][0], evp[ri], w0);
            #pragma unroll
            for (int ri=0;ri<5;ri++) fma2(acc2[ri][1], evp[ri], w1);
        }
        #pragma unroll
        for (int ri=0;ri<5;ri++){
            int row = r0 + rowT*5 + ri;
            int n  = row / M_NBR;
            int gg = __ldg(&eidx[row]);
            const __half* Un = g_UVh + (size_t)n*uvS;
            const __half* Vg = g_UVh + (size_t)gg*uvS;
            __half* yp = g_Yh + (size_t)row*NC;
            #pragma unroll
            for (int p=0;p<2;p++){
                if (TAILN==0 || by==0 || p==0 || colT < TAILN){
                    int j0 = 2*(colT + 32*p + 64*by);
                    float2 y2 = unpack2(acc2[ri][p]);
                    int uc = (j0<128)? j0        : j0+128;
                    int vc = (j0<128)? (j0+128)  : j0+NC;
                    float2 uf = __half22float2(*(const __half2*)&Un[uc]);
                    float2 vf = __half22float2(*(const __half2*)&Vg[vc]);
                    float y0 = y2.x + uf.x + vf.x;
                    float y1 = y2.y + uf.y + vf.y;
                    *(__half2*)&yp[j0] = __floats2half2_rn(y0, y1);
                    s1[2*p]   += y0; s2[2*p]   += y0*y0;
                    s1[2*p+1] += y1; s2[2*p+1] += y1*y1;
                }
            }
        }

        if (tn < nTiles){
            unsigned long long* dst = sE + (cur^1)*P1_TE;
            #pragma unroll
            for (int i=0;i<7;i++){
                int idx = tid + i*256;
                if (idx < P1_TE) dst[idx] = pack_dup(pf[i]);
            }
        }
        __syncthreads();
        cur ^= 1;
    }

    float* red = (float*)sE;
    #pragma unroll 1
    for (int ci=0;ci<4;ci++){
        red[tid] = s1[ci];
        red[256+tid] = s2[ci];
        __syncthreads();
        if (tid < 32){
            float a=0.f, b=0.f;
            #pragma unroll
            for (int w=0;w<8;w++){ a += red[w*32+tid]; b += red[256+w*32+tid]; }
            int j = 2*(tid + 32*(ci>>1) + 64*by) + (ci&1);
            if (j < NC){
                atomicAdd(&g_S[j],    (double)a);
                atomicAdd(&g_S[NC+j], (double)b);
            }
        }
        __syncthreads();
    }
}

// ---------------- finalize stats ----------------
__global__ void k_finalize0(int C, double invCnt)
{
    int t = threadIdx.x + blockIdx.x*blockDim.x;
    if (t >= C) return;
    double m = g_S[t]*invCnt;
    double v = g_S[C+t]*invCnt - m*m;
    g_MEAN[t] = (float)m;
    g_ISTD[t] = rsqrtf((float)v + 1e-5f);
}

__global__ void k_finalize12()
{
    int t = threadIdx.x;
    if (t < FDIM){
        double m = g_SA[t] * (1.0/(double)N_ATOM);
        double v = g_SA[FDIM+t] * (1.0/(double)N_ATOM) - m*m;
        g_MEANA[t] = (float)m;
        g_ISTDA[t] = rsqrtf((float)v + 1e-5f);
    } else if (t >= 64 && t < 64+EDIMM){
        int c = t-64;
        double m = g_SG[c] * (1.0/(double)N_ROW);
        double v = g_SG[EDIMM+c] * (1.0/(double)N_ROW) - m*m;
        g_MEANG[c] = (float)m;
        g_ISTDG[c] = rsqrtf((float)v + 1e-5f);
    }
}

// ---------------- pass2 (layer) ----------------
__global__ void __launch_bounds__(128) k_pass2_layer()
{
    int t = threadIdx.x;
    bool isNode = t < 64;
    bool isEdge = (t >= 64 && t < 105);
    float m1=0.f,i1=0.f,m2=0.f,i2=0.f;
    int c = 0;
    if (isNode){ c=t;    m1=g_MEAN[c];     i1=g_ISTD[c];     m2=g_MEAN[64+c];  i2=g_ISTD[64+c]; }
    else if (isEdge){ c=t-64; m1=g_MEAN[128+c]; i1=g_ISTD[128+c]; m2=g_MEAN[169+c]; i2=g_ISTD[169+c]; }
    float st1=0.f, st2=0.f;
    for (int n = blockIdx.x; n < N_ATOM; n += gridDim.x){
        if (isNode){
            float a = 0.f;
            #pragma unroll
            for (int m=0;m<M_NBR;m++){
                size_t row = (size_t)(n*M_NBR+m);
                float y1 = (__half2float(g_Yh[row*NC_L + c])      - m1)*i1;
                float y2 = (__half2float(g_Yh[row*NC_L + 64 + c]) - m2)*i2;
                a += sigm(y1)*lrelu(y2);
            }
            g_AGGR[n*64 + c] = a;
            st1 += a; st2 += a*a;
        } else if (isEdge){
            #pragma unroll
            for (int m=0;m<M_NBR;m++){
                size_t row = (size_t)(n*M_NBR+m);
                float y1 = (__half2float(g_Yh[row*NC_L + 128 + c]) - m1)*i1;
                float y2 = (__half2float(g_Yh[row*NC_L + 169 + c]) - m2)*i2;
                float gv = sigm(y1)*lrelu(y2);
                g_Gh[row*EDIMM + c] = __float2half_rn(gv);
                st1 += gv; st2 += gv*gv;
            }
        }
    }
    if (isNode){ atomicAdd(&g_SA[c], (double)st1); atomicAdd(&g_SA[64+c], (double)st2); }
    else if (isEdge){ atomicAdd(&g_SG[c], (double)st1); atomicAdd(&g_SG[41+c], (double)st2); }
}

__global__ void k_node_update()
{
    int idx = blockIdx.x*blockDim.x + threadIdx.x;
    if (idx >= N_ATOM*FDIM) return;
    int c = idx & 63;
    float v = g_NODE[idx] + (g_AGGR[idx] - g_MEANA[c]) * g_ISTDA[c];
    g_NODE[idx] = lrelu(v);
}

// ---------------- edge update: half2-vectorized, 2 elems/thread ----------------
__global__ void k_edge_update(const float* __restrict__ Ein, int useG)
{
    size_t i2 = (size_t)blockIdx.x*blockDim.x + threadIdx.x;
    size_t idx = i2 * 2;
    if (idx >= (size_t)N_ROW*EDIMM) return;
    int c0 = (int)(idx % EDIMM);
    int c1 = c0 + 1 >= EDIMM ? 0 : c0 + 1;
    float2 g = __half22float2(*(const __half2*)&g_Gh[idx]);
    float e0, e1;
    if (useG){
        float2 e = __half22float2(*(const __half2*)&g_EDGEh[idx]);
        e0 = e.x; e1 = e.y;
    } else {
        float2 e = *(const float2*)&Ein[idx];
        e0 = e.x; e1 = e.y;
    }
    float v0 = lrelu(e0 + (g.x - g_MEANG[c0]) * g_ISTDG[c0]);
    float v1 = lrelu(e1 + (g.y - g_MEANG[c1]) * g_ISTDG[c1]);
    *(__half2*)&g_EDGEh[idx] = __floats2half2_rn(v0, v1);
}

// ---------------- pass2 (head): half2 loads, fast softplus ----------------
__global__ void __launch_bounds__(256) k_pass2_head(float* __restrict__ out)
{
    int warp = threadIdx.x >> 5, lane = threadIdx.x & 31;
    size_t r = (size_t)blockIdx.x*8 + warp;
    if (r >= N_ROW) return;
    float dist = g_DIST[r];
    float bd = 0.f, bc = 0.f;
    const __half* y = g_Yh + r*NC_H;
    #pragma unroll
    for (int i=0;i<4;i++){
        int c2 = 2*lane + 64*i;
        float2 f = __half22float2(*(const __half2*)&y[c2]);
        float v0 = (f.x - g_MEAN[c2])   * g_ISTD[c2];
        float v1 = (f.y - g_MEAN[c2+1]) * g_ISTD[c2+1];
        if (i < 2){ bd += softplus(v0 + dist) + softplus(v1 + dist); }
        else      { bc += softplus(v0) + softplus(v1); }
    }
    #pragma unroll
    for (int o=16;o>0;o>>=1){
        bd += __shfl_down_sync(0xffffffffu, bd, o);
        bc += __shfl_down_sync(0xffffffffu, bc, o);
    }
    if (lane==0){
        out[r*2]   = bd * (1.f/128.f);
        out[r*2+1] = bc * (1.f/128.f) * (1.f/(float)N_ATOM);
    }
}

// ---------------- host orchestration ----------------
extern "C" void kernel_launch(void* const* d_in, const int* in_sizes, int n_in,
                              void* d_out, int out_size)
{
    const float* node_fea = (const float*)d_in[0];
    const float* edge_fea = (const float*)d_in[1];
    const float* nbr_off  = (const float*)d_in[2];
    const float* atom_pos = (const float*)d_in[3];
    const float* cells    = (const float*)d_in[4];
    const int*   eidx     = (const int*)  d_in[5];
    const float* W_emb = (const float*)d_in[6];
    const float* b_emb = (const float*)d_in[7];
    const float* W_pn  = (const float*)d_in[8];
    const float* b_pn  = (const float*)d_in[9];
    const float* W_pe  = (const float*)d_in[10];
    const float* b_pe  = (const float*)d_in[11];
    const float* W_d   = (const float*)d_in[12];
    const float* b_d   = (const float*)d_in[13];
    const float* W_c   = (const float*)d_in[14];
    const float* b_c   = (const float*)d_in[15];
    float* out = (float*)d_out;

    cudaFuncSetAttribute(k_pass1<NC_L,9>, cudaFuncAttributeMaxDynamicSharedMemorySize, P1_DSMB);
    cudaFuncSetAttribute(k_pass1<NC_H,0>, cudaFuncAttributeMaxDynamicSharedMemorySize, P1_DSMB);

    k_dist<<<(N_ROW+255)/256, 256>>>(nbr_off, atom_pos, cells, eidx);
    k_gemm_emb<<<(N_ATOM+63)/64, 256>>>(node_fea, W_emb, b_emb, N_ATOM, OFD, FDIM);

    const size_t nEl2 = ((size_t)N_ROW*EDIMM)/2;
    for (int l=0;l<3;l++){
        int useG = (l>0) ? 1 : 0;
        k_pack_layer<<<64,256>>>(W_pn + (size_t)l*169*128, b_pn + l*128,
                                 W_pe + (size_t)l*169*82,  b_pe + l*82);
        k_gemm_uv<<<dim3((N_ATOM+127)/128, (UVS_L+127)/128), 256>>>(UVS_L);
        k_pass1<NC_L,9><<<dim3(1184,2),256,P1_DSMB>>>(edge_fea, useG, eidx, UVS_L);
        k_finalize0<<<1,256>>>(NC_L, 1.0/(double)N_ROW);
        k_pass2_layer<<<2368,128>>>();
        k_finalize12<<<1,128>>>();
        k_node_update<<<(N_ATOM*FDIM+255)/256,256>>>();
        k_edge_update<<<(int)((nEl2+255)/256),256>>>(edge_fea, useG);
    }

    k_pack_head<<<64,256>>>(W_d, b_d, W_c, b_c);
    k_gemm_uv<<<dim3((N_ATOM+127)/128, (UVS_H+127)/128), 256>>>(UVS_H);
    k_pass1<NC_H,0><<<dim3(1184,2),256,P1_DSMB>>>(edge_fea, 1, eidx, UVS_H);
    k_finalize0<<<1,256>>>(NC_H, 1.0/(double)N_ROW);
    k_pass2_head<<<(int)((N_ROW+7)/8), 256>>>(out);
}

// round 15
// speedup vs baseline: 1.5132x; 1.0804x over previous
#include <cuda_runtime.h>
#include <cuda_fp16.h>
#include <math.h>

#define N_ATOM  50000
#define M_NBR   12
#define N_ROW   600000
#define OFD     92
#define FDIM    64
#define EDIMM   41
#define NC_L    210
#define NC_H    256
#define UVS_L   420
#define UVS_H   512

// ---------------- scratch (device globals; no runtime allocation) ----------------
__device__ __align__(16) __half g_Yh[(size_t)N_ROW * NC_H];    // fp16 pre-activations
__device__ __align__(16) __half g_Gh[(size_t)N_ROW * EDIMM];   // fp16 edge gate values
__device__ __align__(16) __half g_EDGEh[(size_t)N_ROW * EDIMM];// fp16 current edge features
__device__ __align__(16) float  g_NODE[N_ATOM * FDIM];
__device__ __align__(16) float  g_AGGR[N_ATOM * FDIM];
__device__ __align__(16) __half g_UVh[(size_t)N_ATOM * UVS_H]; // fp16 UV table
__device__ __align__(16) float  g_WP[FDIM * UVS_H];
__device__ __align__(16) float  g_BP[UVS_H];
__device__ __align__(16) float  g_EW[EDIMM * NC_H];
__device__ __align__(16) float  g_DIST[N_ROW];
__device__ double g_S[2 * NC_H];
__device__ double g_SA[2 * FDIM];
__device__ double g_SG[2 * EDIMM];
__device__ float  g_MEAN[NC_H], g_ISTD[NC_H];
__device__ float  g_MEANA[FDIM], g_ISTDA[FDIM];
__device__ float  g_MEANG[EDIMM], g_ISTDG[EDIMM];

__device__ __forceinline__ float lrelu(float x){ return x > 0.f ? x : 0.01f*x; }
__device__ __forceinline__ float sigm(float x){ return __fdividef(1.f, 1.f + __expf(-x)); }
__device__ __forceinline__ float softplus(float x){
    return fmaxf(x,0.f) + __logf(1.f + __expf(-fabsf(x)));
}

// ---------------- packed f32x2 helpers (sm_103a FFMA2 via PTX) ----------------
__device__ __forceinline__ unsigned long long pack_dup(float x){
    unsigned long long r; unsigned int xi = __float_as_uint(x);
    asm("mov.b64 %0, {%1, %1};" : "=l"(r) : "r"(xi));
    return r;
}
__device__ __forceinline__ unsigned long long pack2(float lo, float hi){
    unsigned long long r;
    asm("mov.b64 %0, {%1, %2};" : "=l"(r) : "r"(__float_as_uint(lo)), "r"(__float_as_uint(hi)));
    return r;
}
__device__ __forceinline__ void fma2(unsigned long long &d, unsigned long long a, unsigned long long b){
    asm("fma.rn.f32x2 %0, %1, %2, %0;" : "+l"(d) : "l"(a), "l"(b));
}
__device__ __forceinline__ float2 unpack2(unsigned long long v){
    unsigned int lo, hi;
    asm("mov.b64 {%0, %1}, %2;" : "=r"(lo), "=r"(hi) : "l"(v));
    float2 f; f.x = __uint_as_float(lo); f.y = __uint_as_float(hi); return f;
}

// ---------------- distance ----------------
__global__ void k_dist(const float* __restrict__ nbr, const float* __restrict__ pos,
                       const float* __restrict__ cells, const int* __restrict__ eidx)
{
    int r = blockIdx.x*blockDim.x + threadIdx.x;
    if (r >= N_ROW) return;
    int n = r / M_NBR;
    float o0=nbr[r*3], o1=nbr[r*3+1], o2=nbr[r*3+2];
    const float* c = cells + (size_t)n*9;
    int g = eidx[r];
    float dd = 1e-12f;
    #pragma unroll
    for (int j=0;j<3;j++){
        float off = o0*c[j] + o1*c[3+j] + o2*c[6+j];
        float d = pos[g*3+j] + off - pos[n*3+j];
        dd += d*d;
    }
    g_DIST[r] = sqrtf(dd);
}

// ---------------- embedding GEMM: g_NODE = node_fea @ W_emb + b_emb ----------------
__global__ void __launch_bounds__(256) k_gemm_emb(const float* __restrict__ A,
                                                  const float* __restrict__ B,
                                                  const float* __restrict__ bias,
                                                  int Nrows, int K, int Ncols)
{
    __shared__ float As[64*32];
    __shared__ float Bs[32*128];
    int tid = threadIdx.x;
    int colT = tid & 31, rowT = tid >> 5;
    int r0 = blockIdx.x*64;
    float acc[8][4];
    #pragma unroll
    for (int ri=0;ri<8;ri++)
        #pragma unroll
        for (int ci=0;ci<4;ci++) acc[ri][ci]=0.f;

    for (int k0=0;k0<K;k0+=32){
        for (int i=tid;i<64*32;i+=256){
            int rr=i>>5, kk=i&31; int gr=r0+rr, gk=k0+kk;
            As[i] = (gr<Nrows && gk<K)? A[(size_t)gr*K+gk] : 0.f;
        }
        for (int i=tid;i<32*128;i+=256){
            int kk=i>>7, jj=i&127; int gk=k0+kk;
            Bs[i] = (gk<K && jj<Ncols)? B[(size_t)gk*Ncols+jj] : 0.f;
        }
        __syncthreads();
        #pragma unroll 4
        for (int kk=0;kk<32;kk++){
            float a[8];
            #pragma unroll
            for (int ri=0;ri<8;ri++) a[ri]=As[(rowT+8*ri)*32+kk];
            #pragma unroll
            for (int ci=0;ci<4;ci++){
                float b=Bs[kk*128 + colT + 32*ci];
                #pragma unroll
                for (int ri=0;ri<8;ri++) acc[ri][ci] = fmaf(a[ri], b, acc[ri][ci]);
            }
        }
        __syncthreads();
    }
    #pragma unroll
    for (int ri=0;ri<8;ri++){
        int gr=r0+rowT+8*ri;
        if (gr >= Nrows) continue;
        #pragma unroll
        for (int ci=0;ci<4;ci++){
            int gj=colT+32*ci;
            if (gj < Ncols) g_NODE[(size_t)gr*Ncols+gj] = acc[ri][ci] + bias[gj];
        }
    }
}

// ---------------- UV GEMM (f32x2): g_UVh = fp16( g_NODE @ g_WP + g_BP ) ----------------
__global__ void __launch_bounds__(256) k_gemm_uv(int Ncols)
{
    __shared__ __align__(16) float As[16][128];
    __shared__ __align__(16) float Bs[16][128];
    int tid = threadIdx.x;
    int tx = tid & 15, ty = tid >> 4;
    int r0 = blockIdx.x*128, c0 = blockIdx.y*128;
    unsigned long long acc2[8][4];
    #pragma unroll
    for (int i=0;i<8;i++)
        #pragma unroll
        for (int p=0;p<4;p++) acc2[i][p]=0ull;

    for (int k0=0;k0<FDIM;k0+=16){
        #pragma unroll
        for (int h=0;h<2;h++){
            int arow = (tid>>2) + h*64;
            int acol = (tid&3)*4;
            float4 v = make_float4(0.f,0.f,0.f,0.f);
            int gr = r0 + arow;
            if (gr < N_ATOM) v = *(const float4*)&g_NODE[(size_t)gr*FDIM + k0 + acol];
            As[acol+0][arow]=v.x; As[acol+1][arow]=v.y; As[acol+2][arow]=v.z; As[acol+3][arow]=v.w;
        }
        #pragma unroll
        for (int h=0;h<2;h++){
            int brow = (tid>>5) + h*8;
            int bcol = (tid&31)*4;
            float4 v = make_float4(0.f,0.f,0.f,0.f);
            if (c0 + bcol < Ncols) v = *(const float4*)&g_WP[(size_t)(k0+brow)*Ncols + c0 + bcol];
            *(float4*)&Bs[brow][bcol] = v;
        }
        __syncthreads();
        #pragma unroll
        for (int kk=0;kk<16;kk++){
            float a[8];
            *(float4*)&a[0] = *(const float4*)&As[kk][ty*8];
            *(float4*)&a[4] = *(const float4*)&As[kk][ty*8+4];
            unsigned long long bp[4];
            #pragma unroll
            for (int p=0;p<4;p++) bp[p] = *(const unsigned long long*)&Bs[kk][tx*8 + 2*p];
            #pragma unroll
            for (int i=0;i<8;i++){
                unsigned long long ap = pack_dup(a[i]);
                #pragma unroll
                for (int p=0;p<4;p++) fma2(acc2[i][p], ap, bp[p]);
            }
        }
        __syncthreads();
    }
    #pragma unroll
    for (int ri=0;ri<8;ri++){
        int gr = r0 + ty*8 + ri;
        if (gr >= N_ATOM) continue;
        #pragma unroll
        for (int cj=0;cj<2;cj++){
            int gj = c0 + tx*8 + cj*4;
            if (gj < Ncols){
                float4 bv = *(const float4*)&g_BP[gj];
                float2 v0 = unpack2(acc2[ri][cj*2+0]);
                float2 v1 = unpack2(acc2[ri][cj*2+1]);
                __half2 h0 = __floats2half2_rn(v0.x + bv.x, v0.y + bv.y);
                __half2 h1 = __floats2half2_rn(v1.x + bv.z, v1.y + bv.w);
                uint2 st;
                st.x = *reinterpret_cast<unsigned int*>(&h0);
                st.y = *reinterpret_cast<unsigned int*>(&h1);
                *(uint2*)&g_UVh[(size_t)gr*Ncols + gj] = st;
            }
        }
    }
}

// ---------------- weight packing (+ stat zeroing) ----------------
__global__ void k_pack_layer(const float* __restrict__ Wn, const float* __restrict__ bn,
                             const float* __restrict__ We, const float* __restrict__ be)
{
    int stride = gridDim.x*blockDim.x;
    int t0 = blockIdx.x*blockDim.x + threadIdx.x;
    for (int idx=t0; idx<FDIM*UVS_L; idx+=stride){
        int k = idx / UVS_L, j = idx % UVS_L;
        float v;
        if (j<128)       v = Wn[k*128 + j];
        else if (j<256)  v = Wn[(64+k)*128 + (j-128)];
        else if (j<338)  v = We[k*82 + (j-256)];
        else             v = We[(64+k)*82 + (j-338)];
        g_WP[idx] = v;
    }
    for (int j=t0;j<UVS_L;j+=stride){
        float v = 0.f;
        if (j<128) v = bn[j];
        else if (j>=256 && j<338) v = be[j-256];
        g_BP[j]=v;
    }
    for (int idx=t0;idx<EDIMM*NC_L;idx+=stride){
        int k=idx/NC_L, j=idx%NC_L;
        g_EW[idx] = (j<128)? Wn[(128+k)*128 + j] : We[(128+k)*82 + (j-128)];
    }
    if (t0 < 2*NC_H)  g_S[t0]=0.0;
    if (t0 < 2*FDIM)  g_SA[t0]=0.0;
    if (t0 < 2*EDIMM) g_SG[t0]=0.0;
}

__global__ void k_pack_head(const float* __restrict__ Wd, const float* __restrict__ bd,
                            const float* __restrict__ Wc, const float* __restrict__ bc)
{
    int stride = gridDim.x*blockDim.x;
    int t0 = blockIdx.x*blockDim.x + threadIdx.x;
    for (int idx=t0; idx<FDIM*UVS_H; idx+=stride){
        int k = idx / UVS_H, j = idx % UVS_H;
        float v;
        if (j<128)       v = Wd[k*128 + j];
        else if (j<256)  v = Wd[(64+k)*128 + (j-128)];
        else if (j<384)  v = Wc[k*128 + (j-256)];
        else             v = Wc[(64+k)*128 + (j-384)];
        g_WP[idx] = v;
    }
    for (int j=t0;j<UVS_H;j+=stride){
        float v = 0.f;
        if (j<128) v = bd[j];
        else if (j>=256 && j<384) v = bc[j-256];
        g_BP[j]=v;
    }
    for (int idx=t0;idx<EDIMM*NC_H;idx+=stride){
        int k=idx/NC_H, j=idx%NC_H;
        g_EW[idx] = (j<128)? Wd[(128+k)*128 + j] : Wc[(128+k)*128 + (j-128)];
    }
    if (t0 < 2*NC_H) g_S[t0]=0.0;
}

// ---------------- pass1 v8: column-split (gridDim.y=2), 4 blocks/SM, TR=32, f32x2 pairs ----
// Each block handles 2 pair-groups: pair q = colT + 32*p + 64*by, p in {0,1}.
// smem: sWp [EDIMM][64] pairs (21KB) + dup-E double buffer TR=32 (21KB) = 42KB -> 4 blocks/SM.
#define P1_TR   32
#define P1_TE   (P1_TR*EDIMM)   // 1312
#define P1_DSMB ((EDIMM*64 + 2*P1_TE)*8)

template<int NC, int TAILN>
__global__ void __launch_bounds__(256,4) k_pass1(const float* __restrict__ Ein, int useG,
                                                 const int* __restrict__ eidx, int uvS)
{
    extern __shared__ unsigned long long dsm[];
    unsigned long long* sWp = dsm;                 // [EDIMM][64] this block's column-pairs
    unsigned long long* sE  = dsm + EDIMM*64;      // 2 x [P1_TR][EDIMM] duplicated e
    const int tid = threadIdx.x;
    const int colT = tid & 31, rowT = tid >> 5;
    const int by = blockIdx.y;                     // 0 or 1: column half
    const int gs = gridDim.x;
    const int nTiles = N_ROW / P1_TR;              // 18750

    // pack this half's weights as adjacent column pairs, zero-padded
    for (int idx = tid; idx < EDIMM*64; idx += 256){
        int k = idx >> 6, qq = idx & 63;
        int j0 = 2*(64*by + qq);
        float lo = 0.f, hi = 0.f;
        if (j0 < NC){ lo = g_EW[k*NC + j0]; hi = g_EW[k*NC + j0 + 1]; }
        sWp[idx] = pack2(lo, hi);
    }

    {
        int t0i = blockIdx.x;
        if (t0i < nTiles){
            size_t base = (size_t)t0i*P1_TE;
            for (int i=tid;i<P1_TE;i+=256){
                float e = useG ? __half2float(g_EDGEh[base + i]) : Ein[base + i];
                sE[i] = pack_dup(e);
            }
        }
    }
    __syncthreads();

    float s1[4], s2[4];
    #pragma unroll
    for (int ci=0;ci<4;ci++){ s1[ci]=0.f; s2[ci]=0.f; }

    int cur = 0;
    for (int t = blockIdx.x; t < nTiles; t += gs){
        float pf[6];
        int tn = t + gs;
        if (tn < nTiles){
            size_t nbase = (size_t)tn*P1_TE;
            #pragma unroll
            for (int i=0;i<6;i++){
                int idx = tid + i*256;
                if (idx < P1_TE)
                    pf[i] = useG ? __half2float(g_EDGEh[nbase + idx]) : Ein[nbase + idx];
            }
        }

        int r0 = t*P1_TR;
        unsigned long long acc2[4][2];
        #pragma unroll
        for (int ri=0;ri<4;ri++)
            #pragma unroll
            for (int p=0;p<2;p++) acc2[ri][p]=0ull;

        const unsigned long long* pE = sE + cur*P1_TE + rowT*4*EDIMM;
        const unsigned long long* pW = sWp + colT;
        #pragma unroll 2
        for (int k=0;k<EDIMM;k++){
            unsigned long long evp[4];
            #pragma unroll
            for (int ri=0;ri<4;ri++) evp[ri] = pE[ri*EDIMM + k];
            unsigned long long w0 = pW[k*64];
            unsigned long long w1 = pW[k*64 + 32];
            #pragma unroll
            for (int ri=0;ri<4;ri++) fma2(acc2[ri][0], evp[ri], w0);
            #pragma unroll
            for (int ri=0;ri<4;ri++) fma2(acc2[ri][1], evp[ri], w1);
        }
        #pragma unroll
        for (int ri=0;ri<4;ri++){
            int row = r0 + rowT*4 + ri;
            int n  = row / M_NBR;
            int gg = __ldg(&eidx[row]);
            const __half* Un = g_UVh + (size_t)n*uvS;
            const __half* Vg = g_UVh + (size_t)gg*uvS;
            __half* yp = g_Yh + (size_t)row*NC;
            #pragma unroll
            for (int p=0;p<2;p++){
                if (TAILN==0 || by==0 || p==0 || colT < TAILN){
                    int j0 = 2*(colT + 32*p + 64*by);
                    float2 y2 = unpack2(acc2[ri][p]);
                    int uc = (j0<128)? j0        : j0+128;
                    int vc = (j0<128)? (j0+128)  : j0+NC;
                    float2 uf = __half22float2(*(const __half2*)&Un[uc]);
                    float2 vf = __half22float2(*(const __half2*)&Vg[vc]);
                    float y0 = y2.x + uf.x + vf.x;
                    float y1 = y2.y + uf.y + vf.y;
                    *(__half2*)&yp[j0] = __floats2half2_rn(y0, y1);
                    s1[2*p]   += y0; s2[2*p]   += y0*y0;
                    s1[2*p+1] += y1; s2[2*p+1] += y1*y1;
                }
            }
        }

        if (tn < nTiles){
            unsigned long long* dst = sE + (cur^1)*P1_TE;
            #pragma unroll
            for (int i=0;i<6;i++){
                int idx = tid + i*256;
                if (idx < P1_TE) dst[idx] = pack_dup(pf[i]);
            }
        }
        __syncthreads();
        cur ^= 1;
    }

    float* red = (float*)sE;
    #pragma unroll 1
    for (int ci=0;ci<4;ci++){
        red[tid] = s1[ci];
        red[256+tid] = s2[ci];
        __syncthreads();
        if (tid < 32){
            float a=0.f, b=0.f;
            #pragma unroll
            for (int w=0;w<8;w++){ a += red[w*32+tid]; b += red[256+w*32+tid]; }
            int j = 2*(tid + 32*(ci>>1) + 64*by) + (ci&1);
            if (j < NC){
                atomicAdd(&g_S[j],    (double)a);
                atomicAdd(&g_S[NC+j], (double)b);
            }
        }
        __syncthreads();
    }
}

// ---------------- finalize stats ----------------
__global__ void k_finalize0(int C, double invCnt)
{
    int t = threadIdx.x + blockIdx.x*blockDim.x;
    if (t >= C) return;
    double m = g_S[t]*invCnt;
    double v = g_S[C+t]*invCnt - m*m;
    g_MEAN[t] = (float)m;
    g_ISTD[t] = rsqrtf((float)v + 1e-5f);
}

__global__ void k_finalize12()
{
    int t = threadIdx.x;
    if (t < FDIM){
        double m = g_SA[t] * (1.0/(double)N_ATOM);
        double v = g_SA[FDIM+t] * (1.0/(double)N_ATOM) - m*m;
        g_MEANA[t] = (float)m;
        g_ISTDA[t] = rsqrtf((float)v + 1e-5f);
    } else if (t >= 64 && t < 64+EDIMM){
        int c = t-64;
        double m = g_SG[c] * (1.0/(double)N_ROW);
        double v = g_SG[EDIMM+c] * (1.0/(double)N_ROW) - m*m;
        g_MEANG[c] = (float)m;
        g_ISTDG[c] = rsqrtf((float)v + 1e-5f);
    }
}

// ---------------- pass2 (layer) ----------------
__global__ void __launch_bounds__(128) k_pass2_layer()
{
    int t = threadIdx.x;
    bool isNode = t < 64;
    bool isEdge = (t >= 64 && t < 105);
    float m1=0.f,i1=0.f,m2=0.f,i2=0.f;
    int c = 0;
    if (isNode){ c=t;    m1=g_MEAN[c];     i1=g_ISTD[c];     m2=g_MEAN[64+c];  i2=g_ISTD[64+c]; }
    else if (isEdge){ c=t-64; m1=g_MEAN[128+c]; i1=g_ISTD[128+c]; m2=g_MEAN[169+c]; i2=g_ISTD[169+c]; }
    float st1=0.f, st2=0.f;
    for (int n = blockIdx.x; n < N_ATOM; n += gridDim.x){
        if (isNode){
            float a = 0.f;
            #pragma unroll
            for (int m=0;m<M_NBR;m++){
                size_t row = (size_t)(n*M_NBR+m);
                float y1 = (__half2float(g_Yh[row*NC_L + c])      - m1)*i1;
                float y2 = (__half2float(g_Yh[row*NC_L + 64 + c]) - m2)*i2;
                a += sigm(y1)*lrelu(y2);
            }
            g_AGGR[n*64 + c] = a;
            st1 += a; st2 += a*a;
        } else if (isEdge){
            #pragma unroll
            for (int m=0;m<M_NBR;m++){
                size_t row = (size_t)(n*M_NBR+m);
                float y1 = (__half2float(g_Yh[row*NC_L + 128 + c]) - m1)*i1;
                float y2 = (__half2float(g_Yh[row*NC_L + 169 + c]) - m2)*i2;
                float gv = sigm(y1)*lrelu(y2);
                g_Gh[row*EDIMM + c] = __float2half_rn(gv);
                st1 += gv; st2 += gv*gv;
            }
        }
    }
    if (isNode){ atomicAdd(&g_SA[c], (double)st1); atomicAdd(&g_SA[64+c], (double)st2); }
    else if (isEdge){ atomicAdd(&g_SG[c], (double)st1); atomicAdd(&g_SG[41+c], (double)st2); }
}

__global__ void k_node_update()
{
    int idx = blockIdx.x*blockDim.x + threadIdx.x;
    if (idx >= N_ATOM*FDIM) return;
    int c = idx & 63;
    float v = g_NODE[idx] + (g_AGGR[idx] - g_MEANA[c]) * g_ISTDA[c];
    g_NODE[idx] = lrelu(v);
}

// ---------------- edge update: half2-vectorized, 2 elems/thread ----------------
__global__ void k_edge_update(const float* __restrict__ Ein, int useG)
{
    size_t i2 = (size_t)blockIdx.x*blockDim.x + threadIdx.x;
    size_t idx = i2 * 2;
    if (idx >= (size_t)N_ROW*EDIMM) return;
    int c0 = (int)(idx % EDIMM);
    int c1 = c0 + 1 >= EDIMM ? 0 : c0 + 1;
    float2 g = __half22float2(*(const __half2*)&g_Gh[idx]);
    float e0, e1;
    if (useG){
        float2 e = __half22float2(*(const __half2*)&g_EDGEh[idx]);
        e0 = e.x; e1 = e.y;
    } else {
        float2 e = *(const float2*)&Ein[idx];
        e0 = e.x; e1 = e.y;
    }
    float v0 = lrelu(e0 + (g.x - g_MEANG[c0]) * g_ISTDG[c0]);
    float v1 = lrelu(e1 + (g.y - g_MEANG[c1]) * g_ISTDG[c1]);
    *(__half2*)&g_EDGEh[idx] = __floats2half2_rn(v0, v1);
}

// ---------------- pass2 (head): half2 loads, fast softplus ----------------
__global__ void __launch_bounds__(256) k_pass2_head(float* __restrict__ out)
{
    int warp = threadIdx.x >> 5, lane = threadIdx.x & 31;
    size_t r = (size_t)blockIdx.x*8 + warp;
    if (r >= N_ROW) return;
    float dist = g_DIST[r];
    float bd = 0.f, bc = 0.f;
    const __half* y = g_Yh + r*NC_H;
    #pragma unroll
    for (int i=0;i<4;i++){
        int c2 = 2*lane + 64*i;
        float2 f = __half22float2(*(const __half2*)&y[c2]);
        float v0 = (f.x - g_MEAN[c2])   * g_ISTD[c2];
        float v1 = (f.y - g_MEAN[c2+1]) * g_ISTD[c2+1];
        if (i < 2){ bd += softplus(v0 + dist) + softplus(v1 + dist); }
        else      { bc += softplus(v0) + softplus(v1); }
    }
    #pragma unroll
    for (int o=16;o>0;o>>=1){
        bd += __shfl_down_sync(0xffffffffu, bd, o);
        bc += __shfl_down_sync(0xffffffffu, bc, o);
    }
    if (lane==0){
        out[r*2]   = bd * (1.f/128.f);
        out[r*2+1] = bc * (1.f/128.f) * (1.f/(float)N_ATOM);
    }
}

// ---------------- host orchestration ----------------
extern "C" void kernel_launch(void* const* d_in, const int* in_sizes, int n_in,
                              void* d_out, int out_size)
{
    const float* node_fea = (const float*)d_in[0];
    const float* edge_fea = (const float*)d_in[1];
    const float* nbr_off  = (const float*)d_in[2];
    const float* atom_pos = (const float*)d_in[3];
    const float* cells    = (const float*)d_in[4];
    const int*   eidx     = (const int*)  d_in[5];
    const float* W_emb = (const float*)d_in[6];
    const float* b_emb = (const float*)d_in[7];
    const float* W_pn  = (const float*)d_in[8];
    const float* b_pn  = (const float*)d_in[9];
    const float* W_pe  = (const float*)d_in[10];
    const float* b_pe  = (const float*)d_in[11];
    const float* W_d   = (const float*)d_in[12];
    const float* b_d   = (const float*)d_in[13];
    const float* W_c   = (const float*)d_in[14];
    const float* b_c   = (const float*)d_in[15];
    float* out = (float*)d_out;

    cudaFuncSetAttribute(k_pass1<NC_L,9>, cudaFuncAttributeMaxDynamicSharedMemorySize, P1_DSMB);
    cudaFuncSetAttribute(k_pass1<NC_H,0>, cudaFuncAttributeMaxDynamicSharedMemorySize, P1_DSMB);

    // NOTE: k_dist moved late (only needed by k_pass2_head) so the ncu capture
    // slot lands on pass1 layer 0 instead of a 4th identical gemm_uv profile.
    k_gemm_emb<<<(N_ATOM+63)/64, 256>>>(node_fea, W_emb, b_emb, N_ATOM, OFD, FDIM);

    const size_t nEl2 = ((size_t)N_ROW*EDIMM)/2;
    for (int l=0;l<3;l++){
        int useG = (l>0) ? 1 : 0;
        k_pack_layer<<<64,256>>>(W_pn + (size_t)l*169*128, b_pn + l*128,
                                 W_pe + (size_t)l*169*82,  b_pe + l*82);
        k_gemm_uv<<<dim3((N_ATOM+127)/128, (UVS_L+127)/128), 256>>>(UVS_L);
        k_pass1<NC_L,9><<<dim3(1184,2),256,P1_DSMB>>>(edge_fea, useG, eidx, UVS_L);
        k_finalize0<<<1,256>>>(NC_L, 1.0/(double)N_ROW);
        k_pass2_layer<<<2368,128>>>();
        k_finalize12<<<1,128>>>();
        k_node_update<<<(N_ATOM*FDIM+255)/256,256>>>();
        k_edge_update<<<(int)((nEl2+255)/256),256>>>(edge_fea, useG);
    }

    k_pack_head<<<64,256>>>(W_d, b_d, W_c, b_c);
    k_gemm_uv<<<dim3((N_ATOM+127)/128, (UVS_H+127)/128), 256>>>(UVS_H);
    k_pass1<NC_H,0><<<dim3(1184,2),256,P1_DSMB>>>(edge_fea, 1, eidx, UVS_H);
    k_finalize0<<<1,256>>>(NC_H, 1.0/(double)N_ROW);
    k_dist<<<(N_ROW+255)/256, 256>>>(nbr_off, atom_pos, cells, eidx);
    k_pass2_head<<<(int)((N_ROW+7)/8), 256>>>(out);
}

// round 16
// speedup vs baseline: 1.5173x; 1.0027x over previous
#include <cuda_runtime.h>
#include <cuda_fp16.h>
#include <math.h>

#define N_ATOM  50000
#define M_NBR   12
#define N_ROW   600000
#define OFD     92
#define FDIM    64
#define EDIMM   41
#define NC_L    210
#define NC_H    256
#define UVS_L   420
#define UVS_H   512

// ---------------- scratch (device globals; no runtime allocation) ----------------
__device__ __align__(16) __half g_Yh[(size_t)N_ROW * NC_H];    // fp16 pre-activations
__device__ __align__(16) __half g_Gh[(size_t)N_ROW * EDIMM];   // fp16 edge gate values
__device__ __align__(16) __half g_EDGEh[(size_t)N_ROW * EDIMM];// fp16 current edge features
__device__ __align__(16) float  g_NODE[N_ATOM * FDIM];
__device__ __align__(16) float  g_AGGR[N_ATOM * FDIM];
__device__ __align__(16) __half g_UVh[(size_t)N_ATOM * UVS_H]; // fp16 UV table
__device__ __align__(16) float  g_WP[FDIM * UVS_H];
__device__ __align__(16) float  g_BP[UVS_H];
__device__ __align__(16) float  g_EW[EDIMM * NC_H];
__device__ __align__(16) float  g_DIST[N_ROW];
__device__ double g_S[2 * NC_H];
__device__ double g_SA[2 * FDIM];
__device__ double g_SG[2 * EDIMM];
__device__ float  g_MEAN[NC_H], g_ISTD[NC_H];
__device__ float  g_MEANA[FDIM], g_ISTDA[FDIM];
__device__ float  g_MEANG[EDIMM], g_ISTDG[EDIMM];

__device__ __forceinline__ float lrelu(float x){ return x > 0.f ? x : 0.01f*x; }
__device__ __forceinline__ float sigm(float x){ return __fdividef(1.f, 1.f + __expf(-x)); }
__device__ __forceinline__ float softplus(float x){
    return fmaxf(x,0.f) + __logf(1.f + __expf(-fabsf(x)));
}

// ---------------- packed f32x2 helpers (sm_103a FFMA2 via PTX) ----------------
__device__ __forceinline__ unsigned long long pack_dup(float x){
    unsigned long long r; unsigned int xi = __float_as_uint(x);
    asm("mov.b64 %0, {%1, %1};" : "=l"(r) : "r"(xi));
    return r;
}
__device__ __forceinline__ unsigned long long pack2(float lo, float hi){
    unsigned long long r;
    asm("mov.b64 %0, {%1, %2};" : "=l"(r) : "r"(__float_as_uint(lo)), "r"(__float_as_uint(hi)));
    return r;
}
__device__ __forceinline__ void fma2(unsigned long long &d, unsigned long long a, unsigned long long b){
    asm("fma.rn.f32x2 %0, %1, %2, %0;" : "+l"(d) : "l"(a), "l"(b));
}
__device__ __forceinline__ float2 unpack2(unsigned long long v){
    unsigned int lo, hi;
    asm("mov.b64 {%0, %1}, %2;" : "=r"(lo), "=r"(hi) : "l"(v));
    float2 f; f.x = __uint_as_float(lo); f.y = __uint_as_float(hi); return f;
}

// ---------------- distance ----------------
__global__ void k_dist(const float* __restrict__ nbr, const float* __restrict__ pos,
                       const float* __restrict__ cells, const int* __restrict__ eidx)
{
    int r = blockIdx.x*blockDim.x + threadIdx.x;
    if (r >= N_ROW) return;
    int n = r / M_NBR;
    float o0=nbr[r*3], o1=nbr[r*3+1], o2=nbr[r*3+2];
    const float* c = cells + (size_t)n*9;
    int g = eidx[r];
    float dd = 1e-12f;
    #pragma unroll
    for (int j=0;j<3;j++){
        float off = o0*c[j] + o1*c[3+j] + o2*c[6+j];
        float d = pos[g*3+j] + off - pos[n*3+j];
        dd += d*d;
    }
    g_DIST[r] = sqrtf(dd);
}

// ---------------- embedding GEMM: g_NODE = node_fea @ W_emb + b_emb ----------------
__global__ void __launch_bounds__(256) k_gemm_emb(const float* __restrict__ A,
                                                  const float* __restrict__ B,
                                                  const float* __restrict__ bias,
                                                  int Nrows, int K, int Ncols)
{
    __shared__ float As[64*32];
    __shared__ float Bs[32*128];
    int tid = threadIdx.x;
    int colT = tid & 31, rowT = tid >> 5;
    int r0 = blockIdx.x*64;
    float acc[8][4];
    #pragma unroll
    for (int ri=0;ri<8;ri++)
        #pragma unroll
        for (int ci=0;ci<4;ci++) acc[ri][ci]=0.f;

    for (int k0=0;k0<K;k0+=32){
        for (int i=tid;i<64*32;i+=256){
            int rr=i>>5, kk=i&31; int gr=r0+rr, gk=k0+kk;
            As[i] = (gr<Nrows && gk<K)? A[(size_t)gr*K+gk] : 0.f;
        }
        for (int i=tid;i<32*128;i+=256){
            int kk=i>>7, jj=i&127; int gk=k0+kk;
            Bs[i] = (gk<K && jj<Ncols)? B[(size_t)gk*Ncols+jj] : 0.f;
        }
        __syncthreads();
        #pragma unroll 4
        for (int kk=0;kk<32;kk++){
            float a[8];
            #pragma unroll
            for (int ri=0;ri<8;ri++) a[ri]=As[(rowT+8*ri)*32+kk];
            #pragma unroll
            for (int ci=0;ci<4;ci++){
                float b=Bs[kk*128 + colT + 32*ci];
                #pragma unroll
                for (int ri=0;ri<8;ri++) acc[ri][ci] = fmaf(a[ri], b, acc[ri][ci]);
            }
        }
        __syncthreads();
    }
    #pragma unroll
    for (int ri=0;ri<8;ri++){
        int gr=r0+rowT+8*ri;
        if (gr >= Nrows) continue;
        #pragma unroll
        for (int ci=0;ci<4;ci++){
            int gj=colT+32*ci;
            if (gj < Ncols) g_NODE[(size_t)gr*Ncols+gj] = acc[ri][ci] + bias[gj];
        }
    }
}

// ---------------- UV GEMM (f32x2): g_UVh = fp16( g_NODE @ g_WP + g_BP ) ----------------
__global__ void __launch_bounds__(256) k_gemm_uv(int Ncols)
{
    __shared__ __align__(16) float As[16][128];
    __shared__ __align__(16) float Bs[16][128];
    int tid = threadIdx.x;
    int tx = tid & 15, ty = tid >> 4;
    int r0 = blockIdx.x*128, c0 = blockIdx.y*128;
    unsigned long long acc2[8][4];
    #pragma unroll
    for (int i=0;i<8;i++)
        #pragma unroll
        for (int p=0;p<4;p++) acc2[i][p]=0ull;

    for (int k0=0;k0<FDIM;k0+=16){
        #pragma unroll
        for (int h=0;h<2;h++){
            int arow = (tid>>2) + h*64;
            int acol = (tid&3)*4;
            float4 v = make_float4(0.f,0.f,0.f,0.f);
            int gr = r0 + arow;
            if (gr < N_ATOM) v = *(const float4*)&g_NODE[(size_t)gr*FDIM + k0 + acol];
            As[acol+0][arow]=v.x; As[acol+1][arow]=v.y; As[acol+2][arow]=v.z; As[acol+3][arow]=v.w;
        }
        #pragma unroll
        for (int h=0;h<2;h++){
            int brow = (tid>>5) + h*8;
            int bcol = (tid&31)*4;
            float4 v = make_float4(0.f,0.f,0.f,0.f);
            if (c0 + bcol < Ncols) v = *(const float4*)&g_WP[(size_t)(k0+brow)*Ncols + c0 + bcol];
            *(float4*)&Bs[brow][bcol] = v;
        }
        __syncthreads();
        #pragma unroll
        for (int kk=0;kk<16;kk++){
            float a[8];
            *(float4*)&a[0] = *(const float4*)&As[kk][ty*8];
            *(float4*)&a[4] = *(const float4*)&As[kk][ty*8+4];
            unsigned long long bp[4];
            #pragma unroll
            for (int p=0;p<4;p++) bp[p] = *(const unsigned long long*)&Bs[kk][tx*8 + 2*p];
            #pragma unroll
            for (int i=0;i<8;i++){
                unsigned long long ap = pack_dup(a[i]);
                #pragma unroll
                for (int p=0;p<4;p++) fma2(acc2[i][p], ap, bp[p]);
            }
        }
        __syncthreads();
    }
    #pragma unroll
    for (int ri=0;ri<8;ri++){
        int gr = r0 + ty*8 + ri;
        if (gr >= N_ATOM) continue;
        #pragma unroll
        for (int cj=0;cj<2;cj++){
            int gj = c0 + tx*8 + cj*4;
            if (gj < Ncols){
                float4 bv = *(const float4*)&g_BP[gj];
                float2 v0 = unpack2(acc2[ri][cj*2+0]);
                float2 v1 = unpack2(acc2[ri][cj*2+1]);
                __half2 h0 = __floats2half2_rn(v0.x + bv.x, v0.y + bv.y);
                __half2 h1 = __floats2half2_rn(v1.x + bv.z, v1.y + bv.w);
                uint2 st;
                st.x = *reinterpret_cast<unsigned int*>(&h0);
                st.y = *reinterpret_cast<unsigned int*>(&h1);
                *(uint2*)&g_UVh[(size_t)gr*Ncols + gj] = st;
            }
        }
    }
}

// ---------------- weight packing (+ stat zeroing) ----------------
__global__ void k_pack_layer(const float* __restrict__ Wn, const float* __restrict__ bn,
                             const float* __restrict__ We, const float* __restrict__ be)
{
    int stride = gridDim.x*blockDim.x;
    int t0 = blockIdx.x*blockDim.x + threadIdx.x;
    for (int idx=t0; idx<FDIM*UVS_L; idx+=stride){
        int k = idx / UVS_L, j = idx % UVS_L;
        float v;
        if (j<128)       v = Wn[k*128 + j];
        else if (j<256)  v = Wn[(64+k)*128 + (j-128)];
        else if (j<338)  v = We[k*82 + (j-256)];
        else             v = We[(64+k)*82 + (j-338)];
        g_WP[idx] = v;
    }
    for (int j=t0;j<UVS_L;j+=stride){
        float v = 0.f;
        if (j<128) v = bn[j];
        else if (j>=256 && j<338) v = be[j-256];
        g_BP[j]=v;
    }
    for (int idx=t0;idx<EDIMM*NC_L;idx+=stride){
        int k=idx/NC_L, j=idx%NC_L;
        g_EW[idx] = (j<128)? Wn[(128+k)*128 + j] : We[(128+k)*82 + (j-128)];
    }
    if (t0 < 2*NC_H)  g_S[t0]=0.0;
    if (t0 < 2*FDIM)  g_SA[t0]=0.0;
    if (t0 < 2*EDIMM) g_SG[t0]=0.0;
}

__global__ void k_pack_head(const float* __restrict__ Wd, const float* __restrict__ bd,
                            const float* __restrict__ Wc, const float* __restrict__ bc)
{
    int stride = gridDim.x*blockDim.x;
    int t0 = blockIdx.x*blockDim.x + threadIdx.x;
    for (int idx=t0; idx<FDIM*UVS_H; idx+=stride){
        int k = idx / UVS_H, j = idx % UVS_H;
        float v;
        if (j<128)       v = Wd[k*128 + j];
        else if (j<256)  v = Wd[(64+k)*128 + (j-128)];
        else if (j<384)  v = Wc[k*128 + (j-256)];
        else             v = Wc[(64+k)*128 + (j-384)];
        g_WP[idx] = v;
    }
    for (int j=t0;j<UVS_H;j+=stride){
        float v = 0.f;
        if (j<128) v = bd[j];
        else if (j>=256 && j<384) v = bc[j-256];
        g_BP[j]=v;
    }
    for (int idx=t0;idx<EDIMM*NC_H;idx+=stride){
        int k=idx/NC_H, j=idx%NC_H;
        g_EW[idx] = (j<128)? Wd[(128+k)*128 + j] : Wc[(128+k)*128 + (j-128)];
    }
    if (t0 < 2*NC_H) g_S[t0]=0.0;
}

// ---------------- pass1 v9: col-split, 4 blocks/SM, vectorized loads, fused edge-update ----
// ESRC: 0 = E from float Ein, 1 = E from g_EDGEh (fp16).
// FUSE: e' = lrelu(e + (g_Gh - meanG)*istdG) computed at tile load.
// WRITE: by==0 block writes e' back to g_EDGEh.
#define P1_TR   32
#define P1_TE   (P1_TR*EDIMM)   // 1312
#define P1_DSMB ((EDIMM*64 + 2*P1_TE + 48)*8)

template<int ESRC, int FUSE>
struct TileRegs {
    uint4  eH, gH;      // ESRC=1: 8 halves each
    float4 eF0, eF1;    // ESRC=0: 2x4 floats
    uint2  gF0, gF1;    // ESRC=0 + FUSE: 2x4 halves
};

template<int ESRC, int FUSE>
__device__ __forceinline__ void tile_load(TileRegs<ESRC,FUSE>& r, const float* __restrict__ Ein,
                                          size_t base, int tid)
{
    if (ESRC==1){
        if (tid < P1_TE/8){
            r.eH = *(const uint4*)(g_EDGEh + base + (size_t)tid*8);
            if (FUSE) r.gH = *(const uint4*)(g_Gh + base + (size_t)tid*8);
        }
    } else {
        r.eF0 = *(const float4*)(Ein + base + (size_t)tid*4);
        if (FUSE) r.gF0 = *(const uint2*)(g_Gh + base + (size_t)tid*4);
        if (tid < P1_TE/4 - 256){
            r.eF1 = *(const float4*)(Ein + base + (size_t)(tid+256)*4);
            if (FUSE) r.gF1 = *(const uint2*)(g_Gh + base + (size_t)(tid+256)*4);
        }
    }
}

template<int ESRC, int FUSE, int WRITE>
__device__ __forceinline__ void tile_store(TileRegs<ESRC,FUSE>& r, unsigned long long* dst,
                                           size_t base, int tid, int by,
                                           const float* sMg, const float* sIg)
{
    if (ESRC==1){
        if (tid < P1_TE/8){
            int i0 = tid*8;
            float e[8];
            const __half2* eh2 = (const __half2*)&r.eH;
            #pragma unroll
            for (int q=0;q<4;q++){
                float2 f = __half22float2(eh2[q]);
                e[2*q]=f.x; e[2*q+1]=f.y;
            }
            if (FUSE){
                float g[8];
                const __half2* gh2 = (const __half2*)&r.gH;
                #pragma unroll
                for (int q=0;q<4;q++){
                    float2 f = __half22float2(gh2[q]);
                    g[2*q]=f.x; g[2*q+1]=f.y;
                }
                int c = i0 % EDIMM;
                #pragma unroll
                for (int j=0;j<8;j++){
                    e[j] = lrelu(e[j] + (g[j]-sMg[c])*sIg[c]);
                    c++; c = (c==EDIMM)? 0 : c;
                }
            }
            #pragma unroll
            for (int j=0;j<8;j++) dst[i0+j] = pack_dup(e[j]);
            if (WRITE){
                if (by==0){
                    __half2 o[4];
                    #pragma unroll
                    for (int q=0;q<4;q++) o[q] = __floats2half2_rn(e[2*q], e[2*q+1]);
                    *(uint4*)(g_EDGEh + base + i0) = *(const uint4*)o;
                }
            }
        }
    } else {
        {
            int i0 = tid*4;
            float e[4] = {r.eF0.x, r.eF0.y, r.eF0.z, r.eF0.w};
            if (FUSE){
                const __half2* gh2 = (const __half2*)&r.gF0;
                float2 f0 = __half22float2(gh2[0]);
                float2 f1 = __half22float2(gh2[1]);
                float g[4] = {f0.x, f0.y, f1.x, f1.y};
                int c = i0 % EDIMM;
                #pragma unroll
                for (int j=0;j<4;j++){
                    e[j] = lrelu(e[j] + (g[j]-sMg[c])*sIg[c]);
                    c++; c = (c==EDIMM)? 0 : c;
                }
            }
            #pragma unroll
            for (int j=0;j<4;j++) dst[i0+j] = pack_dup(e[j]);
            if (WRITE){
                if (by==0){
                    __half2 o[2];
                    o[0]=__floats2half2_rn(e[0],e[1]);
                    o[1]=__floats2half2_rn(e[2],e[3]);
                    *(uint2*)(g_EDGEh + base + i0) = *(const uint2*)o;
                }
            }
        }
        if (tid < P1_TE/4 - 256){
            int i0 = (tid+256)*4;
            float e[4] = {r.eF1.x, r.eF1.y, r.eF1.z, r.eF1.w};
            if (FUSE){
                const __half2* gh2 = (const __half2*)&r.gF1;
                float2 f0 = __half22float2(gh2[0]);
                float2 f1 = __half22float2(gh2[1]);
                float g[4] = {f0.x, f0.y, f1.x, f1.y};
                int c = i0 % EDIMM;
                #pragma unroll
                for (int j=0;j<4;j++){
                    e[j] = lrelu(e[j] + (g[j]-sMg[c])*sIg[c]);
                    c++; c = (c==EDIMM)? 0 : c;
                }
            }
            #pragma unroll
            for (int j=0;j<4;j++) dst[i0+j] = pack_dup(e[j]);
            if (WRITE){
                if (by==0){
                    __half2 o[2];
                    o[0]=__floats2half2_rn(e[0],e[1]);
                    o[1]=__floats2half2_rn(e[2],e[3]);
                    *(uint2*)(g_EDGEh + base + i0) = *(const uint2*)o;
                }
            }
        }
    }
}

template<int NC, int TAILN, int ESRC, int FUSE, int WRITE>
__global__ void __launch_bounds__(256,4) k_pass1(const float* __restrict__ Ein,
                                                 const int* __restrict__ eidx, int uvS)
{
    extern __shared__ unsigned long long dsm[];
    unsigned long long* sWp = dsm;                    // [EDIMM][64] column-pairs
    unsigned long long* sE  = dsm + EDIMM*64;         // 2 x [P1_TR][EDIMM] dup'd e
    float* sMg = (float*)(dsm + EDIMM*64 + 2*P1_TE);  // [EDIMM]
    float* sIg = sMg + EDIMM;
    const int tid = threadIdx.x;
    const int colT = tid & 31, rowT = tid >> 5;
    const int by = blockIdx.y;
    const int gs = gridDim.x;
    const int nTiles = N_ROW / P1_TR;

    for (int idx = tid; idx < EDIMM*64; idx += 256){
        int k = idx >> 6, qq = idx & 63;
        int j0 = 2*(64*by + qq);
        float lo = 0.f, hi = 0.f;
        if (j0 < NC){ lo = g_EW[k*NC + j0]; hi = g_EW[k*NC + j0 + 1]; }
        sWp[idx] = pack2(lo, hi);
    }
    if (FUSE && tid < EDIMM){ sMg[tid] = g_MEANG[tid]; sIg[tid] = g_ISTDG[tid]; }
    __syncthreads();   // sMg/sIg ready for prologue fuse

    // prologue: first tile into buffer 0
    {
        size_t base = (size_t)blockIdx.x*P1_TE;
        TileRegs<ESRC,FUSE> tr;
        tile_load<ESRC,FUSE>(tr, Ein, base, tid);
        tile_store<ESRC,FUSE,WRITE>(tr, sE, base, tid, by, sMg, sIg);
    }
    __syncthreads();

    float s1[4], s2[4];
    #pragma unroll
    for (int ci=0;ci<4;ci++){ s1[ci]=0.f; s2[ci]=0.f; }

    int cur = 0;
    for (int t = blockIdx.x; t < nTiles; t += gs){
        TileRegs<ESRC,FUSE> tr;
        int tn = t + gs;
        if (tn < nTiles)
            tile_load<ESRC,FUSE>(tr, Ein, (size_t)tn*P1_TE, tid);

        int r0 = t*P1_TR;
        unsigned long long acc2[4][2];
        #pragma unroll
        for (int ri=0;ri<4;ri++)
            #pragma unroll
            for (int p=0;p<2;p++) acc2[ri][p]=0ull;

        const unsigned long long* pE = sE + cur*P1_TE + rowT*4*EDIMM;
        const unsigned long long* pW = sWp + colT;
        #pragma unroll 2
        for (int k=0;k<EDIMM;k++){
            unsigned long long evp[4];
            #pragma unroll
            for (int ri=0;ri<4;ri++) evp[ri] = pE[ri*EDIMM + k];
            unsigned long long w0 = pW[k*64];
            unsigned long long w1 = pW[k*64 + 32];
            #pragma unroll
            for (int ri=0;ri<4;ri++) fma2(acc2[ri][0], evp[ri], w0);
            #pragma unroll
            for (int ri=0;ri<4;ri++) fma2(acc2[ri][1], evp[ri], w1);
        }
        #pragma unroll
        for (int ri=0;ri<4;ri++){
            int row = r0 + rowT*4 + ri;
            int n  = row / M_NBR;
            int gg = __ldg(&eidx[row]);
            const __half* Un = g_UVh + (size_t)n*uvS;
            const __half* Vg = g_UVh + (size_t)gg*uvS;
            __half* yp = g_Yh + (size_t)row*NC;
            #pragma unroll
            for (int p=0;p<2;p++){
                if (TAILN==0 || by==0 || p==0 || colT < TAILN){
                    int j0 = 2*(colT + 32*p + 64*by);
                    float2 y2 = unpack2(acc2[ri][p]);
                    int uc = (j0<128)? j0        : j0+128;
                    int vc = (j0<128)? (j0+128)  : j0+NC;
                    float2 uf = __half22float2(*(const __half2*)&Un[uc]);
                    float2 vf = __half22float2(*(const __half2*)&Vg[vc]);
                    float y0 = y2.x + uf.x + vf.x;
                    float y1 = y2.y + uf.y + vf.y;
                    *(__half2*)&yp[j0] = __floats2half2_rn(y0, y1);
                    s1[2*p]   += y0; s2[2*p]   += y0*y0;
                    s1[2*p+1] += y1; s2[2*p+1] += y1*y1;
                }
            }
        }

        if (tn < nTiles)
            tile_store<ESRC,FUSE,WRITE>(tr, sE + (cur^1)*P1_TE, (size_t)tn*P1_TE, tid, by, sMg, sIg);
        __syncthreads();
        cur ^= 1;
    }

    float* red = (float*)sE;
    #pragma unroll 1
    for (int ci=0;ci<4;ci++){
        red[tid] = s1[ci];
        red[256+tid] = s2[ci];
        __syncthreads();
        if (tid < 32){
            float a=0.f, b=0.f;
            #pragma unroll
            for (int w=0;w<8;w++){ a += red[w*32+tid]; b += red[256+w*32+tid]; }
            int j = 2*(tid + 32*(ci>>1) + 64*by) + (ci&1);
            if (j < NC){
                atomicAdd(&g_S[j],    (double)a);
                atomicAdd(&g_S[NC+j], (double)b);
            }
        }
        __syncthreads();
    }
}

// ---------------- finalize stats ----------------
__global__ void k_finalize0(int C, double invCnt)
{
    int t = threadIdx.x + blockIdx.x*blockDim.x;
    if (t >= C) return;
    double m = g_S[t]*invCnt;
    double v = g_S[C+t]*invCnt - m*m;
    g_MEAN[t] = (float)m;
    g_ISTD[t] = rsqrtf((float)v + 1e-5f);
}

__global__ void k_finalize12()
{
    int t = threadIdx.x;
    if (t < FDIM){
        double m = g_SA[t] * (1.0/(double)N_ATOM);
        double v = g_SA[FDIM+t] * (1.0/(double)N_ATOM) - m*m;
        g_MEANA[t] = (float)m;
        g_ISTDA[t] = rsqrtf((float)v + 1e-5f);
    } else if (t >= 64 && t < 64+EDIMM){
        int c = t-64;
        double m = g_SG[c] * (1.0/(double)N_ROW);
        double v = g_SG[EDIMM+c] * (1.0/(double)N_ROW) - m*m;
        g_MEANG[c] = (float)m;
        g_ISTDG[c] = rsqrtf((float)v + 1e-5f);
    }
}

// ---------------- pass2 (layer) ----------------
__global__ void __launch_bounds__(128) k_pass2_layer()
{
    int t = threadIdx.x;
    bool isNode = t < 64;
    bool isEdge = (t >= 64 && t < 105);
    float m1=0.f,i1=0.f,m2=0.f,i2=0.f;
    int c = 0;
    if (isNode){ c=t;    m1=g_MEAN[c];     i1=g_ISTD[c];     m2=g_MEAN[64+c];  i2=g_ISTD[64+c]; }
    else if (isEdge){ c=t-64; m1=g_MEAN[128+c]; i1=g_ISTD[128+c]; m2=g_MEAN[169+c]; i2=g_ISTD[169+c]; }
    float st1=0.f, st2=0.f;
    for (int n = blockIdx.x; n < N_ATOM; n += gridDim.x){
        if (isNode){
            float a = 0.f;
            #pragma unroll
            for (int m=0;m<M_NBR;m++){
                size_t row = (size_t)(n*M_NBR+m);
                float y1 = (__half2float(g_Yh[row*NC_L + c])      - m1)*i1;
                float y2 = (__half2float(g_Yh[row*NC_L + 64 + c]) - m2)*i2;
                a += sigm(y1)*lrelu(y2);
            }
            g_AGGR[n*64 + c] = a;
            st1 += a; st2 += a*a;
        } else if (isEdge){
            #pragma unroll
            for (int m=0;m<M_NBR;m++){
                size_t row = (size_t)(n*M_NBR+m);
                float y1 = (__half2float(g_Yh[row*NC_L + 128 + c]) - m1)*i1;
                float y2 = (__half2float(g_Yh[row*NC_L + 169 + c]) - m2)*i2;
                float gv = sigm(y1)*lrelu(y2);
                g_Gh[row*EDIMM + c] = __float2half_rn(gv);
                st1 += gv; st2 += gv*gv;
            }
        }
    }
    if (isNode){ atomicAdd(&g_SA[c], (double)st1); atomicAdd(&g_SA[64+c], (double)st2); }
    else if (isEdge){ atomicAdd(&g_SG[c], (double)st1); atomicAdd(&g_SG[41+c], (double)st2); }
}

__global__ void k_node_update()
{
    int idx = blockIdx.x*blockDim.x + threadIdx.x;
    if (idx >= N_ATOM*FDIM) return;
    int c = idx & 63;
    float v = g_NODE[idx] + (g_AGGR[idx] - g_MEANA[c]) * g_ISTDA[c];
    g_NODE[idx] = lrelu(v);
}

// ---------------- pass2 (head): half2 loads, fast softplus ----------------
__global__ void __launch_bounds__(256) k_pass2_head(float* __restrict__ out)
{
    int warp = threadIdx.x >> 5, lane = threadIdx.x & 31;
    size_t r = (size_t)blockIdx.x*8 + warp;
    if (r >= N_ROW) return;
    float dist = g_DIST[r];
    float bd = 0.f, bc = 0.f;
    const __half* y = g_Yh + r*NC_H;
    #pragma unroll
    for (int i=0;i<4;i++){
        int c2 = 2*lane + 64*i;
        float2 f = __half22float2(*(const __half2*)&y[c2]);
        float v0 = (f.x - g_MEAN[c2])   * g_ISTD[c2];
        float v1 = (f.y - g_MEAN[c2+1]) * g_ISTD[c2+1];
        if (i < 2){ bd += softplus(v0 + dist) + softplus(v1 + dist); }
        else      { bc += softplus(v0) + softplus(v1); }
    }
    #pragma unroll
    for (int o=16;o>0;o>>=1){
        bd += __shfl_down_sync(0xffffffffu, bd, o);
        bc += __shfl_down_sync(0xffffffffu, bc, o);
    }
    if (lane==0){
        out[r*2]   = bd * (1.f/128.f);
        out[r*2+1] = bc * (1.f/128.f) * (1.f/(float)N_ATOM);
    }
}

// ---------------- host orchestration ----------------
extern "C" void kernel_launch(void* const* d_in, const int* in_sizes, int n_in,
                              void* d_out, int out_size)
{
    const float* node_fea = (const float*)d_in[0];
    const float* edge_fea = (const float*)d_in[1];
    const float* nbr_off  = (const float*)d_in[2];
    const float* atom_pos = (const float*)d_in[3];
    const float* cells    = (const float*)d_in[4];
    const int*   eidx     = (const int*)  d_in[5];
    const float* W_emb = (const float*)d_in[6];
    const float* b_emb = (const float*)d_in[7];
    const float* W_pn  = (const float*)d_in[8];
    const float* b_pn  = (const float*)d_in[9];
    const float* W_pe  = (const float*)d_in[10];
    const float* b_pe  = (const float*)d_in[11];
    const float* W_d   = (const float*)d_in[12];
    const float* b_d   = (const float*)d_in[13];
    const float* W_c   = (const float*)d_in[14];
    const float* b_c   = (const float*)d_in[15];
    float* out = (float*)d_out;

    cudaFuncSetAttribute(k_pass1<NC_L,9,0,0,0>, cudaFuncAttributeMaxDynamicSharedMemorySize, P1_DSMB);
    cudaFuncSetAttribute(k_pass1<NC_L,9,0,1,1>, cudaFuncAttributeMaxDynamicSharedMemorySize, P1_DSMB);
    cudaFuncSetAttribute(k_pass1<NC_L,9,1,1,1>, cudaFuncAttributeMaxDynamicSharedMemorySize, P1_DSMB);
    cudaFuncSetAttribute(k_pass1<NC_H,0,1,1,0>, cudaFuncAttributeMaxDynamicSharedMemorySize, P1_DSMB);

    k_gemm_emb<<<(N_ATOM+63)/64, 256>>>(node_fea, W_emb, b_emb, N_ATOM, OFD, FDIM);

    for (int l=0;l<3;l++){
        k_pack_layer<<<64,256>>>(W_pn + (size_t)l*169*128, b_pn + l*128,
                                 W_pe + (size_t)l*169*82,  b_pe + l*82);
        k_gemm_uv<<<dim3((N_ATOM+127)/128, (UVS_L+127)/128), 256>>>(UVS_L);
        if (l == 0)
            k_pass1<NC_L,9,0,0,0><<<dim3(1184,2),256,P1_DSMB>>>(edge_fea, eidx, UVS_L);
        else if (l == 1)
            k_pass1<NC_L,9,0,1,1><<<dim3(1184,2),256,P1_DSMB>>>(edge_fea, eidx, UVS_L);
        else
            k_pass1<NC_L,9,1,1,1><<<dim3(1184,2),256,P1_DSMB>>>(edge_fea, eidx, UVS_L);
        k_finalize0<<<1,256>>>(NC_L, 1.0/(double)N_ROW);
        k_pass2_layer<<<2368,128>>>();
        k_finalize12<<<1,128>>>();
        k_node_update<<<(N_ATOM*FDIM+255)/256,256>>>();
    }

    k_pack_head<<<64,256>>>(W_d, b_d, W_c, b_c);
    k_gemm_uv<<<dim3((N_ATOM+127)/128, (UVS_H+127)/128), 256>>>(UVS_H);
    k_pass1<NC_H,0,1,1,0><<<dim3(1184,2),256,P1_DSMB>>>(edge_fea, eidx, UVS_H);
    k_finalize0<<<1,256>>>(NC_H, 1.0/(double)N_ROW);
    k_dist<<<(N_ROW+255)/256, 256>>>(nbr_off, atom_pos, cells, eidx);
    k_pass2_head<<<(int)((N_ROW+7)/8), 256>>>(out);
}

// round 17
// speedup vs baseline: 1.5216x; 1.0029x over previous
#include <cuda_runtime.h>
#include <cuda_fp16.h>
#include <math.h>

#define N_ATOM  50000
#define M_NBR   12
#define N_ROW   600000
#define OFD     92
#define FDIM    64
#define EDIMM   41
#define NC_L    210
#define NC_H    256
#define UVS_L   420
#define UVS_H   512

// ---------------- scratch (device globals; no runtime allocation) ----------------
__device__ __align__(16) __half g_Yh[(size_t)N_ROW * NC_H];     // fp16 pre-activations
__device__ __align__(16) __half g_Gh[(size_t)N_ROW * EDIMM];    // fp16 edge gate values
__device__ __align__(16) __half g_EDGEh[(size_t)N_ROW * EDIMM]; // edge features (buffer A)
__device__ __align__(16) __half g_EDGE2h[(size_t)N_ROW * EDIMM];// edge features (buffer B)
__device__ __align__(16) float  g_NODE[N_ATOM * FDIM];
__device__ __align__(16) float  g_AGGR[N_ATOM * FDIM];
__device__ __align__(16) __half g_UVh[(size_t)N_ATOM * UVS_H];  // fp16 UV table
__device__ __align__(16) float  g_WP[FDIM * UVS_H];
__device__ __align__(16) float  g_BP[UVS_H];
__device__ __align__(16) float  g_EW[EDIMM * NC_H];
__device__ __align__(16) float  g_DIST[N_ROW];
__device__ double g_S[2 * NC_H];
__device__ double g_SA[2 * FDIM];
__device__ double g_SG[2 * EDIMM];
__device__ float  g_MEAN[NC_H], g_ISTD[NC_H];
__device__ float  g_MEANA[FDIM], g_ISTDA[FDIM];
__device__ float  g_MEANG[EDIMM], g_ISTDG[EDIMM];

__device__ __forceinline__ float lrelu(float x){ return x > 0.f ? x : 0.01f*x; }
__device__ __forceinline__ float sigm(float x){ return __fdividef(1.f, 1.f + __expf(-x)); }
__device__ __forceinline__ float softplus(float x){
    return fmaxf(x,0.f) + __logf(1.f + __expf(-fabsf(x)));
}

// ---------------- packed f32x2 helpers (sm_103a FFMA2 via PTX) ----------------
__device__ __forceinline__ unsigned long long pack_dup(float x){
    unsigned long long r; unsigned int xi = __float_as_uint(x);
    asm("mov.b64 %0, {%1, %1};" : "=l"(r) : "r"(xi));
    return r;
}
__device__ __forceinline__ unsigned long long pack2(float lo, float hi){
    unsigned long long r;
    asm("mov.b64 %0, {%1, %2};" : "=l"(r) : "r"(__float_as_uint(lo)), "r"(__float_as_uint(hi)));
    return r;
}
__device__ __forceinline__ void fma2(unsigned long long &d, unsigned long long a, unsigned long long b){
    asm("fma.rn.f32x2 %0, %1, %2, %0;" : "+l"(d) : "l"(a), "l"(b));
}
__device__ __forceinline__ float2 unpack2(unsigned long long v){
    unsigned int lo, hi;
    asm("mov.b64 {%0, %1}, %2;" : "=r"(lo), "=r"(hi) : "l"(v));
    float2 f; f.x = __uint_as_float(lo); f.y = __uint_as_float(hi); return f;
}

// ---------------- distance ----------------
__global__ void k_dist(const float* __restrict__ nbr, const float* __restrict__ pos,
                       const float* __restrict__ cells, const int* __restrict__ eidx)
{
    int r = blockIdx.x*blockDim.x + threadIdx.x;
    if (r >= N_ROW) return;
    int n = r / M_NBR;
    float o0=nbr[r*3], o1=nbr[r*3+1], o2=nbr[r*3+2];
    const float* c = cells + (size_t)n*9;
    int g = eidx[r];
    float dd = 1e-12f;
    #pragma unroll
    for (int j=0;j<3;j++){
        float off = o0*c[j] + o1*c[3+j] + o2*c[6+j];
        float d = pos[g*3+j] + off - pos[n*3+j];
        dd += d*d;
    }
    g_DIST[r] = sqrtf(dd);
}

// ---------------- embedding GEMM: g_NODE = node_fea @ W_emb + b_emb ----------------
__global__ void __launch_bounds__(256) k_gemm_emb(const float* __restrict__ A,
                                                  const float* __restrict__ B,
                                                  const float* __restrict__ bias,
                                                  int Nrows, int K, int Ncols)
{
    __shared__ float As[64*32];
    __shared__ float Bs[32*128];
    int tid = threadIdx.x;
    int colT = tid & 31, rowT = tid >> 5;
    int r0 = blockIdx.x*64;
    float acc[8][4];
    #pragma unroll
    for (int ri=0;ri<8;ri++)
        #pragma unroll
        for (int ci=0;ci<4;ci++) acc[ri][ci]=0.f;

    for (int k0=0;k0<K;k0+=32){
        for (int i=tid;i<64*32;i+=256){
            int rr=i>>5, kk=i&31; int gr=r0+rr, gk=k0+kk;
            As[i] = (gr<Nrows && gk<K)? A[(size_t)gr*K+gk] : 0.f;
        }
        for (int i=tid;i<32*128;i+=256){
            int kk=i>>7, jj=i&127; int gk=k0+kk;
            Bs[i] = (gk<K && jj<Ncols)? B[(size_t)gk*Ncols+jj] : 0.f;
        }
        __syncthreads();
        #pragma unroll 4
        for (int kk=0;kk<32;kk++){
            float a[8];
            #pragma unroll
            for (int ri=0;ri<8;ri++) a[ri]=As[(rowT+8*ri)*32+kk];
            #pragma unroll
            for (int ci=0;ci<4;ci++){
                float b=Bs[kk*128 + colT + 32*ci];
                #pragma unroll
                for (int ri=0;ri<8;ri++) acc[ri][ci] = fmaf(a[ri], b, acc[ri][ci]);
            }
        }
        __syncthreads();
    }
    #pragma unroll
    for (int ri=0;ri<8;ri++){
        int gr=r0+rowT+8*ri;
        if (gr >= Nrows) continue;
        #pragma unroll
        for (int ci=0;ci<4;ci++){
            int gj=colT+32*ci;
            if (gj < Ncols) g_NODE[(size_t)gr*Ncols+gj] = acc[ri][ci] + bias[gj];
        }
    }
}

// ---------------- UV GEMM (f32x2): g_UVh = fp16( g_NODE @ g_WP + g_BP ) ----------------
__global__ void __launch_bounds__(256) k_gemm_uv(int Ncols)
{
    __shared__ __align__(16) float As[16][128];
    __shared__ __align__(16) float Bs[16][128];
    int tid = threadIdx.x;
    int tx = tid & 15, ty = tid >> 4;
    int r0 = blockIdx.x*128, c0 = blockIdx.y*128;
    unsigned long long acc2[8][4];
    #pragma unroll
    for (int i=0;i<8;i++)
        #pragma unroll
        for (int p=0;p<4;p++) acc2[i][p]=0ull;

    for (int k0=0;k0<FDIM;k0+=16){
        #pragma unroll
        for (int h=0;h<2;h++){
            int arow = (tid>>2) + h*64;
            int acol = (tid&3)*4;
            float4 v = make_float4(0.f,0.f,0.f,0.f);
            int gr = r0 + arow;
            if (gr < N_ATOM) v = *(const float4*)&g_NODE[(size_t)gr*FDIM + k0 + acol];
            As[acol+0][arow]=v.x; As[acol+1][arow]=v.y; As[acol+2][arow]=v.z; As[acol+3][arow]=v.w;
        }
        #pragma unroll
        for (int h=0;h<2;h++){
            int brow = (tid>>5) + h*8;
            int bcol = (tid&31)*4;
            float4 v = make_float4(0.f,0.f,0.f,0.f);
            if (c0 + bcol < Ncols) v = *(const float4*)&g_WP[(size_t)(k0+brow)*Ncols + c0 + bcol];
            *(float4*)&Bs[brow][bcol] = v;
        }
        __syncthreads();
        #pragma unroll
        for (int kk=0;kk<16;kk++){
            float a[8];
            *(float4*)&a[0] = *(const float4*)&As[kk][ty*8];
            *(float4*)&a[4] = *(const float4*)&As[kk][ty*8+4];
            unsigned long long bp[4];
            #pragma unroll
            for (int p=0;p<4;p++) bp[p] = *(const unsigned long long*)&Bs[kk][tx*8 + 2*p];
            #pragma unroll
            for (int i=0;i<8;i++){
                unsigned long long ap = pack_dup(a[i]);
                #pragma unroll
                for (int p=0;p<4;p++) fma2(acc2[i][p], ap, bp[p]);
            }
        }
        __syncthreads();
    }
    #pragma unroll
    for (int ri=0;ri<8;ri++){
        int gr = r0 + ty*8 + ri;
        if (gr >= N_ATOM) continue;
        #pragma unroll
        for (int cj=0;cj<2;cj++){
            int gj = c0 + tx*8 + cj*4;
            if (gj < Ncols){
                float4 bv = *(const float4*)&g_BP[gj];
                float2 v0 = unpack2(acc2[ri][cj*2+0]);
                float2 v1 = unpack2(acc2[ri][cj*2+1]);
                __half2 h0 = __floats2half2_rn(v0.x + bv.x, v0.y + bv.y);
                __half2 h1 = __floats2half2_rn(v1.x + bv.z, v1.y + bv.w);
                uint2 st;
                st.x = *reinterpret_cast<unsigned int*>(&h0);
                st.y = *reinterpret_cast<unsigned int*>(&h1);
                *(uint2*)&g_UVh[(size_t)gr*Ncols + gj] = st;
            }
        }
    }
}

// ---------------- weight packing (+ stat zeroing) ----------------
__global__ void k_pack_layer(const float* __restrict__ Wn, const float* __restrict__ bn,
                             const float* __restrict__ We, const float* __restrict__ be)
{
    int stride = gridDim.x*blockDim.x;
    int t0 = blockIdx.x*blockDim.x + threadIdx.x;
    for (int idx=t0; idx<FDIM*UVS_L; idx+=stride){
        int k = idx / UVS_L, j = idx % UVS_L;
        float v;
        if (j<128)       v = Wn[k*128 + j];
        else if (j<256)  v = Wn[(64+k)*128 + (j-128)];
        else if (j<338)  v = We[k*82 + (j-256)];
        else             v = We[(64+k)*82 + (j-338)];
        g_WP[idx] = v;
    }
    for (int j=t0;j<UVS_L;j+=stride){
        float v = 0.f;
        if (j<128) v = bn[j];
        else if (j>=256 && j<338) v = be[j-256];
        g_BP[j]=v;
    }
    for (int idx=t0;idx<EDIMM*NC_L;idx+=stride){
        int k=idx/NC_L, j=idx%NC_L;
        g_EW[idx] = (j<128)? Wn[(128+k)*128 + j] : We[(128+k)*82 + (j-128)];
    }
    if (t0 < 2*NC_H)  g_S[t0]=0.0;
    if (t0 < 2*FDIM)  g_SA[t0]=0.0;
    if (t0 < 2*EDIMM) g_SG[t0]=0.0;
}

__global__ void k_pack_head(const float* __restrict__ Wd, const float* __restrict__ bd,
                            const float* __restrict__ Wc, const float* __restrict__ bc)
{
    int stride = gridDim.x*blockDim.x;
    int t0 = blockIdx.x*blockDim.x + threadIdx.x;
    for (int idx=t0; idx<FDIM*UVS_H; idx+=stride){
        int k = idx / UVS_H, j = idx % UVS_H;
        float v;
        if (j<128)       v = Wd[k*128 + j];
        else if (j<256)  v = Wd[(64+k)*128 + (j-128)];
        else if (j<384)  v = Wc[k*128 + (j-256)];
        else             v = Wc[(64+k)*128 + (j-384)];
        g_WP[idx] = v;
    }
    for (int j=t0;j<UVS_H;j+=stride){
        float v = 0.f;
        if (j<128) v = bd[j];
        else if (j>=256 && j<384) v = bc[j-256];
        g_BP[j]=v;
    }
    for (int idx=t0;idx<EDIMM*NC_H;idx+=stride){
        int k=idx/NC_H, j=idx%NC_H;
        g_EW[idx] = (j<128)? Wd[(128+k)*128 + j] : Wc[(128+k)*128 + (j-128)];
    }
    if (t0 < 2*NC_H) g_S[t0]=0.0;
}

// ---------------- pass1 v10: col-split, 4 blocks/SM, fused edge-update, PING-PONG buffers ----
// ESRC: 0 = E from float Ein, 1 = E from fp16 buffer (RB selects which).
// RB:   0 = read g_EDGEh / write g_EDGE2h;  1 = read g_EDGE2h / write g_EDGEh.
//       (writers and readers always touch DIFFERENT buffers -> no cross-block race)
// For ESRC=0 (l=1), write goes to g_EDGEh.
// FUSE: e' = lrelu(e + (g_Gh - meanG)*istdG) at tile load. WRITE: by==0 writes e'.
#define P1_TR   32
#define P1_TE   (P1_TR*EDIMM)   // 1312
#define P1_DSMB ((EDIMM*64 + 2*P1_TE + 48)*8)

template<int ESRC, int FUSE>
struct TileRegs {
    uint4  eH, gH;      // ESRC=1: 8 halves each
    float4 eF0, eF1;    // ESRC=0: 2x4 floats
    uint2  gF0, gF1;    // ESRC=0 + FUSE: 2x4 halves
};

template<int ESRC, int FUSE>
__device__ __forceinline__ void tile_load(TileRegs<ESRC,FUSE>& r, const float* __restrict__ Ein,
                                          const __half* __restrict__ Eh, size_t base, int tid)
{
    if (ESRC==1){
        if (tid < P1_TE/8){
            r.eH = *(const uint4*)(Eh + base + (size_t)tid*8);
            if (FUSE) r.gH = *(const uint4*)(g_Gh + base + (size_t)tid*8);
        }
    } else {
        r.eF0 = *(const float4*)(Ein + base + (size_t)tid*4);
        if (FUSE) r.gF0 = *(const uint2*)(g_Gh + base + (size_t)tid*4);
        if (tid < P1_TE/4 - 256){
            r.eF1 = *(const float4*)(Ein + base + (size_t)(tid+256)*4);
            if (FUSE) r.gF1 = *(const uint2*)(g_Gh + base + (size_t)(tid+256)*4);
        }
    }
}

template<int ESRC, int FUSE, int WRITE>
__device__ __forceinline__ void tile_store(TileRegs<ESRC,FUSE>& r, unsigned long long* dst,
                                           __half* __restrict__ Ewr, size_t base, int tid, int by,
                                           const float* sMg, const float* sIg)
{
    if (ESRC==1){
        if (tid < P1_TE/8){
            int i0 = tid*8;
            float e[8];
            const __half2* eh2 = (const __half2*)&r.eH;
            #pragma unroll
            for (int q=0;q<4;q++){
                float2 f = __half22float2(eh2[q]);
                e[2*q]=f.x; e[2*q+1]=f.y;
            }
            if (FUSE){
                float g[8];
                const __half2* gh2 = (const __half2*)&r.gH;
                #pragma unroll
                for (int q=0;q<4;q++){
                    float2 f = __half22float2(gh2[q]);
                    g[2*q]=f.x; g[2*q+1]=f.y;
                }
                int c = i0 % EDIMM;
                #pragma unroll
                for (int j=0;j<8;j++){
                    e[j] = lrelu(e[j] + (g[j]-sMg[c])*sIg[c]);
                    c++; c = (c==EDIMM)? 0 : c;
                }
            }
            #pragma unroll
            for (int j=0;j<8;j++) dst[i0+j] = pack_dup(e[j]);
            if (WRITE){
                if (by==0){
                    __half2 o[4];
                    #pragma unroll
                    for (int q=0;q<4;q++) o[q] = __floats2half2_rn(e[2*q], e[2*q+1]);
                    *(uint4*)(Ewr + base + i0) = *(const uint4*)o;
                }
            }
        }
    } else {
        {
            int i0 = tid*4;
            float e[4] = {r.eF0.x, r.eF0.y, r.eF0.z, r.eF0.w};
            if (FUSE){
                const __half2* gh2 = (const __half2*)&r.gF0;
                float2 f0 = __half22float2(gh2[0]);
                float2 f1 = __half22float2(gh2[1]);
                float g[4] = {f0.x, f0.y, f1.x, f1.y};
                int c = i0 % EDIMM;
                #pragma unroll
                for (int j=0;j<4;j++){
                    e[j] = lrelu(e[j] + (g[j]-sMg[c])*sIg[c]);
                    c++; c = (c==EDIMM)? 0 : c;
                }
            }
            #pragma unroll
            for (int j=0;j<4;j++) dst[i0+j] = pack_dup(e[j]);
            if (WRITE){
                if (by==0){
                    __half2 o[2];
                    o[0]=__floats2half2_rn(e[0],e[1]);
                    o[1]=__floats2half2_rn(e[2],e[3]);
                    *(uint2*)(Ewr + base + i0) = *(const uint2*)o;
                }
            }
        }
        if (tid < P1_TE/4 - 256){
            int i0 = (tid+256)*4;
            float e[4] = {r.eF1.x, r.eF1.y, r.eF1.z, r.eF1.w};
            if (FUSE){
                const __half2* gh2 = (const __half2*)&r.gF1;
                float2 f0 = __half22float2(gh2[0]);
                float2 f1 = __half22float2(gh2[1]);
                float g[4] = {f0.x, f0.y, f1.x, f1.y};
                int c = i0 % EDIMM;
                #pragma unroll
                for (int j=0;j<4;j++){
                    e[j] = lrelu(e[j] + (g[j]-sMg[c])*sIg[c]);
                    c++; c = (c==EDIMM)? 0 : c;
                }
            }
            #pragma unroll
            for (int j=0;j<4;j++) dst[i0+j] = pack_dup(e[j]);
            if (WRITE){
                if (by==0){
                    __half2 o[2];
                    o[0]=__floats2half2_rn(e[0],e[1]);
                    o[1]=__floats2half2_rn(e[2],e[3]);
                    *(uint2*)(Ewr + base + i0) = *(const uint2*)o;
                }
            }
        }
    }
}

template<int NC, int TAILN, int ESRC, int FUSE, int WRITE, int RB>
__global__ void __launch_bounds__(256,4) k_pass1(const float* __restrict__ Ein,
                                                 const int* __restrict__ eidx, int uvS)
{
    extern __shared__ unsigned long long dsm[];
    unsigned long long* sWp = dsm;                    // [EDIMM][64] column-pairs
    unsigned long long* sE  = dsm + EDIMM*64;         // 2 x [P1_TR][EDIMM] dup'd e
    float* sMg = (float*)(dsm + EDIMM*64 + 2*P1_TE);  // [EDIMM]
    float* sIg = sMg + EDIMM;
    const __half* Eh  = (RB==0) ? g_EDGEh  : g_EDGE2h;   // read buffer (ESRC=1)
    __half*       Ewr = (ESRC==0) ? g_EDGEh : ((RB==0) ? g_EDGE2h : g_EDGEh); // write buffer
    const int tid = threadIdx.x;
    const int colT = tid & 31, rowT = tid >> 5;
    const int by = blockIdx.y;
    const int gs = gridDim.x;
    const int nTiles = N_ROW / P1_TR;

    for (int idx = tid; idx < EDIMM*64; idx += 256){
        int k = idx >> 6, qq = idx & 63;
        int j0 = 2*(64*by + qq);
        float lo = 0.f, hi = 0.f;
        if (j0 < NC){ lo = g_EW[k*NC + j0]; hi = g_EW[k*NC + j0 + 1]; }
        sWp[idx] = pack2(lo, hi);
    }
    if (FUSE && tid < EDIMM){ sMg[tid] = g_MEANG[tid]; sIg[tid] = g_ISTDG[tid]; }
    __syncthreads();   // sMg/sIg ready for prologue fuse

    // prologue: first tile into buffer 0
    {
        size_t base = (size_t)blockIdx.x*P1_TE;
        TileRegs<ESRC,FUSE> tr;
        tile_load<ESRC,FUSE>(tr, Ein, Eh, base, tid);
        tile_store<ESRC,FUSE,WRITE>(tr, sE, Ewr, base, tid, by, sMg, sIg);
    }
    __syncthreads();

    float s1[4], s2[4];
    #pragma unroll
    for (int ci=0;ci<4;ci++){ s1[ci]=0.f; s2[ci]=0.f; }

    int cur = 0;
    for (int t = blockIdx.x; t < nTiles; t += gs){
        TileRegs<ESRC,FUSE> tr;
        int tn = t + gs;
        if (tn < nTiles)
            tile_load<ESRC,FUSE>(tr, Ein, Eh, (size_t)tn*P1_TE, tid);

        int r0 = t*P1_TR;
        unsigned long long acc2[4][2];
        #pragma unroll
        for (int ri=0;ri<4;ri++)
            #pragma unroll
            for (int p=0;p<2;p++) acc2[ri][p]=0ull;

        const unsigned long long* pE = sE + cur*P1_TE + rowT*4*EDIMM;
        const unsigned long long* pW = sWp + colT;
        #pragma unroll 2
        for (int k=0;k<EDIMM;k++){
            unsigned long long evp[4];
            #pragma unroll
            for (int ri=0;ri<4;ri++) evp[ri] = pE[ri*EDIMM + k];
            unsigned long long w0 = pW[k*64];
            unsigned long long w1 = pW[k*64 + 32];
            #pragma unroll
            for (int ri=0;ri<4;ri++) fma2(acc2[ri][0], evp[ri], w0);
            #pragma unroll
            for (int ri=0;ri<4;ri++) fma2(acc2[ri][1], evp[ri], w1);
        }
        #pragma unroll
        for (int ri=0;ri<4;ri++){
            int row = r0 + rowT*4 + ri;
            int n  = row / M_NBR;
            int gg = __ldg(&eidx[row]);
            const __half* Un = g_UVh + (size_t)n*uvS;
            const __half* Vg = g_UVh + (size_t)gg*uvS;
            __half* yp = g_Yh + (size_t)row*NC;
            #pragma unroll
            for (int p=0;p<2;p++){
                if (TAILN==0 || by==0 || p==0 || colT < TAILN){
                    int j0 = 2*(colT + 32*p + 64*by);
                    float2 y2 = unpack2(acc2[ri][p]);
                    int uc = (j0<128)? j0        : j0+128;
                    int vc = (j0<128)? (j0+128)  : j0+NC;
                    float2 uf = __half22float2(*(const __half2*)&Un[uc]);
                    float2 vf = __half22float2(*(const __half2*)&Vg[vc]);
                    float y0 = y2.x + uf.x + vf.x;
                    float y1 = y2.y + uf.y + vf.y;
                    *(__half2*)&yp[j0] = __floats2half2_rn(y0, y1);
                    s1[2*p]   += y0; s2[2*p]   += y0*y0;
                    s1[2*p+1] += y1; s2[2*p+1] += y1*y1;
                }
            }
        }

        if (tn < nTiles)
            tile_store<ESRC,FUSE,WRITE>(tr, sE + (cur^1)*P1_TE, Ewr, (size_t)tn*P1_TE, tid, by, sMg, sIg);
        __syncthreads();
        cur ^= 1;
    }

    float* red = (float*)sE;
    #pragma unroll 1
    for (int ci=0;ci<4;ci++){
        red[tid] = s1[ci];
        red[256+tid] = s2[ci];
        __syncthreads();
        if (tid < 32){
            float a=0.f, b=0.f;
            #pragma unroll
            for (int w=0;w<8;w++){ a += red[w*32+tid]; b += red[256+w*32+tid]; }
            int j = 2*(tid + 32*(ci>>1) + 64*by) + (ci&1);
            if (j < NC){
                atomicAdd(&g_S[j],    (double)a);
                atomicAdd(&g_S[NC+j], (double)b);
            }
        }
        __syncthreads();
    }
}

// ---------------- finalize stats ----------------
__global__ void k_finalize0(int C, double invCnt)
{
    int t = threadIdx.x + blockIdx.x*blockDim.x;
    if (t >= C) return;
    double m = g_S[t]*invCnt;
    double v = g_S[C+t]*invCnt - m*m;
    g_MEAN[t] = (float)m;
    g_ISTD[t] = rsqrtf((float)v + 1e-5f);
}

__global__ void k_finalize12()
{
    int t = threadIdx.x;
    if (t < FDIM){
        double m = g_SA[t] * (1.0/(double)N_ATOM);
        double v = g_SA[FDIM+t] * (1.0/(double)N_ATOM) - m*m;
        g_MEANA[t] = (float)m;
        g_ISTDA[t] = rsqrtf((float)v + 1e-5f);
    } else if (t >= 64 && t < 64+EDIMM){
        int c = t-64;
        double m = g_SG[c] * (1.0/(double)N_ROW);
        double v = g_SG[EDIMM+c] * (1.0/(double)N_ROW) - m*m;
        g_MEANG[c] = (float)m;
        g_ISTDG[c] = rsqrtf((float)v + 1e-5f);
    }
}

// ---------------- pass2 (layer) ----------------
__global__ void __launch_bounds__(128) k_pass2_layer()
{
    int t = threadIdx.x;
    bool isNode = t < 64;
    bool isEdge = (t >= 64 && t < 105);
    float m1=0.f,i1=0.f,m2=0.f,i2=0.f;
    int c = 0;
    if (isNode){ c=t;    m1=g_MEAN[c];     i1=g_ISTD[c];     m2=g_MEAN[64+c];  i2=g_ISTD[64+c]; }
    else if (isEdge){ c=t-64; m1=g_MEAN[128+c]; i1=g_ISTD[128+c]; m2=g_MEAN[169+c]; i2=g_ISTD[169+c]; }
    float st1=0.f, st2=0.f;
    for (int n = blockIdx.x; n < N_ATOM; n += gridDim.x){
        if (isNode){
            float a = 0.f;
            #pragma unroll
            for (int m=0;m<M_NBR;m++){
                size_t row = (size_t)(n*M_NBR+m);
                float y1 = (__half2float(g_Yh[row*NC_L + c])      - m1)*i1;
                float y2 = (__half2float(g_Yh[row*NC_L + 64 + c]) - m2)*i2;
                a += sigm(y1)*lrelu(y2);
            }
            g_AGGR[n*64 + c] = a;
            st1 += a; st2 += a*a;
        } else if (isEdge){
            #pragma unroll
            for (int m=0;m<M_NBR;m++){
                size_t row = (size_t)(n*M_NBR+m);
                float y1 = (__half2float(g_Yh[row*NC_L + 128 + c]) - m1)*i1;
                float y2 = (__half2float(g_Yh[row*NC_L + 169 + c]) - m2)*i2;
                float gv = sigm(y1)*lrelu(y2);
                g_Gh[row*EDIMM + c] = __float2half_rn(gv);
                st1 += gv; st2 += gv*gv;
            }
        }
    }
    if (isNode){ atomicAdd(&g_SA[c], (double)st1); atomicAdd(&g_SA[64+c], (double)st2); }
    else if (isEdge){ atomicAdd(&g_SG[c], (double)st1); atomicAdd(&g_SG[41+c], (double)st2); }
}

__global__ void k_node_update()
{
    int idx = blockIdx.x*blockDim.x + threadIdx.x;
    if (idx >= N_ATOM*FDIM) return;
    int c = idx & 63;
    float v = g_NODE[idx] + (g_AGGR[idx] - g_MEANA[c]) * g_ISTDA[c];
    g_NODE[idx] = lrelu(v);
}

// ---------------- pass2 (head): half2 loads, fast softplus ----------------
__global__ void __launch_bounds__(256) k_pass2_head(float* __restrict__ out)
{
    int warp = threadIdx.x >> 5, lane = threadIdx.x & 31;
    size_t r = (size_t)blockIdx.x*8 + warp;
    if (r >= N_ROW) return;
    float dist = g_DIST[r];
    float bd = 0.f, bc = 0.f;
    const __half* y = g_Yh + r*NC_H;
    #pragma unroll
    for (int i=0;i<4;i++){
        int c2 = 2*lane + 64*i;
        float2 f = __half22float2(*(const __half2*)&y[c2]);
        float v0 = (f.x - g_MEAN[c2])   * g_ISTD[c2];
        float v1 = (f.y - g_MEAN[c2+1]) * g_ISTD[c2+1];
        if (i < 2){ bd += softplus(v0 + dist) + softplus(v1 + dist); }
        else      { bc += softplus(v0) + softplus(v1); }
    }
    #pragma unroll
    for (int o=16;o>0;o>>=1){
        bd += __shfl_down_sync(0xffffffffu, bd, o);
        bc += __shfl_down_sync(0xffffffffu, bc, o);
    }
    if (lane==0){
        out[r*2]   = bd * (1.f/128.f);
        out[r*2+1] = bc * (1.f/128.f) * (1.f/(float)N_ATOM);
    }
}

// ---------------- host orchestration ----------------
extern "C" void kernel_launch(void* const* d_in, const int* in_sizes, int n_in,
                              void* d_out, int out_size)
{
    const float* node_fea = (const float*)d_in[0];
    const float* edge_fea = (const float*)d_in[1];
    const float* nbr_off  = (const float*)d_in[2];
    const float* atom_pos = (const float*)d_in[3];
    const float* cells    = (const float*)d_in[4];
    const int*   eidx     = (const int*)  d_in[5];
    const float* W_emb = (const float*)d_in[6];
    const float* b_emb = (const float*)d_in[7];
    const float* W_pn  = (const float*)d_in[8];
    const float* b_pn  = (const float*)d_in[9];
    const float* W_pe  = (const float*)d_in[10];
    const float* b_pe  = (const float*)d_in[11];
    const float* W_d   = (const float*)d_in[12];
    const float* b_d   = (const float*)d_in[13];
    const float* W_c   = (const float*)d_in[14];
    const float* b_c   = (const float*)d_in[15];
    float* out = (float*)d_out;

    cudaFuncSetAttribute(k_pass1<NC_L,9,0,0,0,0>, cudaFuncAttributeMaxDynamicSharedMemorySize, P1_DSMB);
    cudaFuncSetAttribute(k_pass1<NC_L,9,0,1,1,0>, cudaFuncAttributeMaxDynamicSharedMemorySize, P1_DSMB);
    cudaFuncSetAttribute(k_pass1<NC_L,9,1,1,1,0>, cudaFuncAttributeMaxDynamicSharedMemorySize, P1_DSMB);
    cudaFuncSetAttribute(k_pass1<NC_H,0,1,1,0,1>, cudaFuncAttributeMaxDynamicSharedMemorySize, P1_DSMB);

    k_gemm_emb<<<(N_ATOM+63)/64, 256>>>(node_fea, W_emb, b_emb, N_ATOM, OFD, FDIM);

    for (int l=0;l<3;l++){
        k_pack_layer<<<64,256>>>(W_pn + (size_t)l*169*128, b_pn + l*128,
                                 W_pe + (size_t)l*169*82,  b_pe + l*82);
        k_gemm_uv<<<dim3((N_ATOM+127)/128, (UVS_L+127)/128), 256>>>(UVS_L);
        if (l == 0)
            k_pass1<NC_L,9,0,0,0,0><<<dim3(1184,2),256,P1_DSMB>>>(edge_fea, eidx, UVS_L);   // raw
        else if (l == 1)
            k_pass1<NC_L,9,0,1,1,0><<<dim3(1184,2),256,P1_DSMB>>>(edge_fea, eidx, UVS_L);   // fuse(edge_fea,G0) -> write g_EDGEh
        else
            k_pass1<NC_L,9,1,1,1,0><<<dim3(1184,2),256,P1_DSMB>>>(edge_fea, eidx, UVS_L);   // read g_EDGEh, fuse(G1) -> write g_EDGE2h
        k_finalize0<<<1,256>>>(NC_L, 1.0/(double)N_ROW);
        k_pass2_layer<<<2368,128>>>();
        k_finalize12<<<1,128>>>();
        k_node_update<<<(N_ATOM*FDIM+255)/256,256>>>();
    }

    k_pack_head<<<64,256>>>(W_d, b_d, W_c, b_c);
    k_gemm_uv<<<dim3((N_ATOM+127)/128, (UVS_H+127)/128), 256>>>(UVS_H);
    k_pass1<NC_H,0,1,1,0,1><<<dim3(1184,2),256,P1_DSMB>>>(edge_fea, eidx, UVS_H);           // read g_EDGE2h, fuse(G2), no write
    k_finalize0<<<1,256>>>(NC_H, 1.0/(double)N_ROW);
    k_dist<<<(N_ROW+255)/256, 256>>>(nbr_off, atom_pos, cells, eidx);
    k_pass2_head<<<(int)((N_ROW+7)/8), 256>>>(out);
}